// round 9
// baseline (speedup 1.0000x reference)
#include <cuda_runtime.h>
#include <cuda_bf16.h>
#include <math.h>
#include <stdint.h>

#define N_NODES 100000
#define N_EDGES 1600000
#define N_QUERY 500000
#define F_IN 7
#define HID 128
#define EMB 64

// ---------------- scratch (device globals) ----------------
__device__ float g_dinv[N_NODES];
__device__ int   g_cnt[N_NODES];
__device__ int   g_off[N_NODES + 1];
__device__ int   g_cur[N_NODES];
__device__ int   g_srcn[N_EDGES];
__device__ __nv_bfloat16 g_hsb[(size_t)N_NODES * HID];   // bf16 message buffer
__device__ __nv_bfloat16 g_hb2[(size_t)N_NODES * HID];   // bf16 aggregated activations
__device__ __nv_bfloat16 g_uvb[(size_t)N_NODES * 256];   // bf16 [U(128)+b1' | V(128)]
__device__ float g_wd1p[64 * 256];                       // packed [Wd1_top | Wd1_bot]
__device__ float g_bc[256];                              // [bd1 | 0]
__device__ float g_w2t[64 * 128];                        // Wd2^T [n][k], tf32-rounded
__device__ float g_wcomb[128 * 256];                     // Wfc @ Wd1p
__device__ float g_bcomb[256];                           // bfc @ Wd1p + bc

__device__ __forceinline__ float to_tf32(float x) {
    uint32_t u;
    asm("cvt.rna.tf32.f32 %0, %1;" : "=r"(u) : "f"(x));
    return __uint_as_float(u);
}

// ---------------- CSR build ----------------
__global__ void k_cnt(const int* __restrict__ ei) {
    int e = blockIdx.x * blockDim.x + threadIdx.x;
    if (e < N_EDGES) atomicAdd(&g_cnt[ei[N_EDGES + e]], 1);
}

__global__ __launch_bounds__(1024) void k_scan() {
    __shared__ int ssum[1024];
    const int tid = threadIdx.x;
    const int CHUNK = (N_NODES + 1023) / 1024;
    int lo = tid * CHUNK;
    int hi = min(lo + CHUNK, N_NODES);
    int sum = 0;
    for (int i = lo; i < hi; i++) sum += g_cnt[i];
    ssum[tid] = sum;
    __syncthreads();
    for (int off = 1; off < 1024; off <<= 1) {
        int t = (tid >= off) ? ssum[tid - off] : 0;
        __syncthreads();
        if (tid >= off) ssum[tid] += t;
        __syncthreads();
    }
    int run = ssum[tid] - sum;
    for (int i = lo; i < hi; i++) {
        g_off[i] = run;
        g_cur[i] = run;
        run += g_cnt[i];
    }
    if (lo < N_NODES && hi == N_NODES) g_off[N_NODES] = run;
}

__global__ void k_dinv() {
    int i = blockIdx.x * blockDim.x + threadIdx.x;
    if (i < N_NODES) g_dinv[i] = rsqrtf((float)g_cnt[i] + 1.0f);
}

__global__ void k_fill(const int* __restrict__ ei) {
    int e = blockIdx.x * blockDim.x + threadIdx.x;
    if (e >= N_EDGES) return;
    int s = ei[e];
    int d = ei[N_EDGES + e];
    int pos = atomicAdd(&g_cur[d], 1);
    g_srcn[pos] = s;
}

// ---------------- pack decoder weights ----------------
__global__ void k_pack(const float* __restrict__ Wd1, const float* __restrict__ bd1,
                       const float* __restrict__ Wd2) {
    int idx = blockIdx.x * blockDim.x + threadIdx.x;
    if (idx < 64 * 256) {
        int k = idx >> 8, j = idx & 255;
        g_wd1p[idx] = (j < 128) ? Wd1[k * 128 + j] : Wd1[(64 + k) * 128 + (j - 128)];
    }
    if (idx < 256) g_bc[idx] = (idx < 128) ? bd1[idx] : 0.f;
    if (idx < 64 * 128) {
        int n = idx >> 7, k = idx & 127;
        g_w2t[idx] = to_tf32(Wd2[k * 64 + n]);
    }
}

// ---------------- combine fc into UV: Wcomb = Wfc @ Wd1p ; bcomb = bfc @ Wd1p + bc -----
__global__ void k_wcomb(const float* __restrict__ Wfc, const float* __restrict__ bfc) {
    __shared__ float s[64];
    int b = blockIdx.x;
    int c = threadIdx.x;  // 256
    if (b < 128) {
        if (c < 64) s[c] = Wfc[b * 64 + c];
        __syncthreads();
        float acc = 0.f;
#pragma unroll 8
        for (int j = 0; j < 64; j++) acc = fmaf(s[j], g_wd1p[j * 256 + c], acc);
        g_wcomb[b * 256 + c] = acc;
    } else {
        if (c < 64) s[c] = bfc[c];
        __syncthreads();
        float acc = g_bc[c];
#pragma unroll 8
        for (int j = 0; j < 64; j++) acc = fmaf(s[j], g_wd1p[j * 256 + c], acc);
        g_bcomb[c] = acc;
    }
}

// ---------------- layer-1 input matmul: hs1 = bf16((x @ W1) * dinv) ----------------
__global__ void k_mm_in(const float* __restrict__ x, const float* __restrict__ W,
                        __nv_bfloat16* __restrict__ hs) {
    __shared__ float sW[F_IN * HID];
    int tid = threadIdx.x;
    for (int i = tid; i < F_IN * HID; i += blockDim.x) sW[i] = W[i];
    __syncthreads();
    int t = blockIdx.x * blockDim.x + tid;
    if (t >= N_NODES * 32) return;
    int node = t >> 5, j = (t & 31) * 4;
    float xr[F_IN];
#pragma unroll
    for (int k = 0; k < F_IN; k++) xr[k] = x[node * F_IN + k];
    float4 a = make_float4(0.f, 0.f, 0.f, 0.f);
#pragma unroll
    for (int k = 0; k < F_IN; k++) {
        const float* w = &sW[k * HID + j];
        a.x = fmaf(xr[k], w[0], a.x);
        a.y = fmaf(xr[k], w[1], a.y);
        a.z = fmaf(xr[k], w[2], a.z);
        a.w = fmaf(xr[k], w[3], a.w);
    }
    float dv = g_dinv[node];
    __nv_bfloat162 p0 = __floats2bfloat162_rn(a.x * dv, a.y * dv);
    __nv_bfloat162 p1 = __floats2bfloat162_rn(a.z * dv, a.w * dv);
    uint2 o;
    o.x = *(uint32_t*)&p0;
    o.y = *(uint32_t*)&p1;
    ((uint2*)hs)[t] = o;
}

// ---------------- fused CSR aggregation: out = bf16(relu(dinv*(sum+self)+b)) ------------
__global__ __launch_bounds__(256) void k_agg(const __nv_bfloat16* __restrict__ hs,
                                             const float* __restrict__ bias,
                                             __nv_bfloat16* __restrict__ out) {
    int t = blockIdx.x * blockDim.x + threadIdx.x;
    int node = t >> 5, lane = t & 31;
    if (node >= N_NODES) return;
    const uint2* h2 = (const uint2*)hs;

    float ax, ay, az, aw;
    {
        uint2 v = h2[(size_t)node * 32 + lane];
        float2 f0 = __bfloat1622float2(*(__nv_bfloat162*)&v.x);
        float2 f1 = __bfloat1622float2(*(__nv_bfloat162*)&v.y);
        ax = f0.x; ay = f0.y; az = f1.x; aw = f1.y;
    }
    int e = g_off[node];
    const int end = g_off[node + 1];
    for (; e + 4 <= end; e += 4) {
        int s0 = g_srcn[e], s1 = g_srcn[e + 1], s2 = g_srcn[e + 2], s3 = g_srcn[e + 3];
        uint2 v0 = h2[(size_t)s0 * 32 + lane];
        uint2 v1 = h2[(size_t)s1 * 32 + lane];
        uint2 v2 = h2[(size_t)s2 * 32 + lane];
        uint2 v3 = h2[(size_t)s3 * 32 + lane];
        float2 a0 = __bfloat1622float2(*(__nv_bfloat162*)&v0.x);
        float2 b0 = __bfloat1622float2(*(__nv_bfloat162*)&v0.y);
        float2 a1 = __bfloat1622float2(*(__nv_bfloat162*)&v1.x);
        float2 b1 = __bfloat1622float2(*(__nv_bfloat162*)&v1.y);
        float2 a2 = __bfloat1622float2(*(__nv_bfloat162*)&v2.x);
        float2 b2 = __bfloat1622float2(*(__nv_bfloat162*)&v2.y);
        float2 a3 = __bfloat1622float2(*(__nv_bfloat162*)&v3.x);
        float2 b3 = __bfloat1622float2(*(__nv_bfloat162*)&v3.y);
        ax += a0.x + a1.x + a2.x + a3.x;
        ay += a0.y + a1.y + a2.y + a3.y;
        az += b0.x + b1.x + b2.x + b3.x;
        aw += b0.y + b1.y + b2.y + b3.y;
    }
    for (; e < end; e++) {
        uint2 v = h2[(size_t)g_srcn[e] * 32 + lane];
        float2 f0 = __bfloat1622float2(*(__nv_bfloat162*)&v.x);
        float2 f1 = __bfloat1622float2(*(__nv_bfloat162*)&v.y);
        ax += f0.x; ay += f0.y; az += f1.x; aw += f1.y;
    }
    float dv = g_dinv[node];
    float4 bv = ((const float4*)bias)[lane];
    float r0 = fmaxf(fmaf(ax, dv, bv.x), 0.f);
    float r1 = fmaxf(fmaf(ay, dv, bv.y), 0.f);
    float r2 = fmaxf(fmaf(az, dv, bv.z), 0.f);
    float r3 = fmaxf(fmaf(aw, dv, bv.w), 0.f);
    __nv_bfloat162 p0 = __floats2bfloat162_rn(r0, r1);
    __nv_bfloat162 p1 = __floats2bfloat162_rn(r2, r3);
    uint2 o;
    o.x = *(uint32_t*)&p0;
    o.y = *(uint32_t*)&p1;
    ((uint2*)out)[(size_t)node * 32 + lane] = o;
}

// ---------------- tf32 tensor-core node GEMM: C[M,NT] = A[M,KD] @ B[KD,NT] -------------
// A input is bf16. EPI 0: C = acc * dinv[row]; EPI 1: C = acc + bias[col]. Output bf16.
template <int KD, int NT, int EPI>
__global__ __launch_bounds__(256) void gemm_tf32(const __nv_bfloat16* __restrict__ A,
                                                 const float* __restrict__ B,
                                                 const float* __restrict__ bias,
                                                 __nv_bfloat16* __restrict__ C) {
    constexpr int PITCH = KD + 4;
    extern __shared__ float sm[];
    float* s_a = sm;                 // [128][PITCH]
    float* s_b = sm + 128 * PITCH;   // [NT][PITCH] (B transposed: [n][k])
    const int tid = threadIdx.x;
    const int row0 = blockIdx.x * 128;

    for (int i = tid; i < KD * NT; i += 256) {
        int k = i / NT, n = i % NT;
        s_b[n * PITCH + k] = to_tf32(B[i]);
    }
    for (int i = tid; i < 128 * KD / 4; i += 256) {
        int r = i / (KD / 4), k4 = i % (KD / 4);
        int gr = row0 + r;
        if (gr >= N_NODES) gr = N_NODES - 1;
        uint2 v = *(const uint2*)&A[(size_t)gr * KD + k4 * 4];
        float2 f0 = __bfloat1622float2(*(__nv_bfloat162*)&v.x);
        float2 f1 = __bfloat1622float2(*(__nv_bfloat162*)&v.y);
        float* d = &s_a[r * PITCH + k4 * 4];
        d[0] = f0.x; d[1] = f0.y; d[2] = f1.x; d[3] = f1.y;  // bf16 exact in tf32
    }
    __syncthreads();

    const int lane = tid & 31, warp = tid >> 5;
    const int q0 = warp * 16;
    const int gid = lane >> 2, tig = lane & 3;
    constexpr int NCHUNK = (NT > 128) ? 2 : 1;
    constexpr int NC = NT / NCHUNK;
    constexpr int NTILES = NC / 8;

    const int qa = row0 + q0 + gid, qb = qa + 8;
    float dva = 1.f, dvb = 1.f;
    if (EPI == 0) {
        dva = (qa < N_NODES) ? g_dinv[qa] : 0.f;
        dvb = (qb < N_NODES) ? g_dinv[qb] : 0.f;
    }

    for (int nc = 0; nc < NCHUNK; nc++) {
        float acc[NTILES][4];
#pragma unroll
        for (int t = 0; t < NTILES; t++)
#pragma unroll
            for (int j = 0; j < 4; j++) acc[t][j] = 0.f;

#pragma unroll
        for (int k0 = 0; k0 < KD; k0 += 8) {
            float a0 = s_a[(q0 + gid) * PITCH + k0 + tig];
            float a1 = s_a[(q0 + gid + 8) * PITCH + k0 + tig];
            float a2 = s_a[(q0 + gid) * PITCH + k0 + tig + 4];
            float a3 = s_a[(q0 + gid + 8) * PITCH + k0 + tig + 4];
#pragma unroll
            for (int t = 0; t < NTILES; t++) {
                float b0 = s_b[(nc * NC + t * 8 + gid) * PITCH + k0 + tig];
                float b1 = s_b[(nc * NC + t * 8 + gid) * PITCH + k0 + tig + 4];
                asm volatile(
                    "mma.sync.aligned.m16n8k8.row.col.f32.tf32.tf32.f32 "
                    "{%0,%1,%2,%3}, {%4,%5,%6,%7}, {%8,%9}, {%0,%1,%2,%3};"
                    : "+f"(acc[t][0]), "+f"(acc[t][1]), "+f"(acc[t][2]), "+f"(acc[t][3])
                    : "r"(__float_as_uint(a0)), "r"(__float_as_uint(a1)),
                      "r"(__float_as_uint(a2)), "r"(__float_as_uint(a3)),
                      "r"(__float_as_uint(b0)), "r"(__float_as_uint(b1)));
            }
        }
#pragma unroll
        for (int t = 0; t < NTILES; t++) {
            int c = nc * NC + t * 8 + 2 * tig;
            float r0, r1, r2, r3;
            if (EPI == 0) {
                r0 = acc[t][0] * dva; r1 = acc[t][1] * dva;
                r2 = acc[t][2] * dvb; r3 = acc[t][3] * dvb;
            } else {
                float b0 = bias[c], b1 = bias[c + 1];
                r0 = acc[t][0] + b0; r1 = acc[t][1] + b1;
                r2 = acc[t][2] + b0; r3 = acc[t][3] + b1;
            }
            __nv_bfloat162 pa = __floats2bfloat162_rn(r0, r1);
            __nv_bfloat162 pb = __floats2bfloat162_rn(r2, r3);
            if (qa < N_NODES) *(__nv_bfloat162*)&C[(size_t)qa * NT + c] = pa;
            if (qb < N_NODES) *(__nv_bfloat162*)&C[(size_t)qb * NT + c] = pb;
        }
    }
}

// ---------------- decoder: 256 queries/block (2 tiles), bf16 gather, tf32 TC stage 2 ----
// dyn smem floats: s_d[128][132] | s_w[64][132] | s_c2T[64][132]  = 135168 bytes
__global__ __launch_bounds__(256) void k_decoder(
    const __nv_bfloat16* __restrict__ uv, const int* __restrict__ qe,
    const float* __restrict__ w2t, const float* __restrict__ bd2,
    const float* __restrict__ Wd3, const float* __restrict__ bd3,
    float* __restrict__ out) {
    extern __shared__ float smem[];
    float* s_d   = smem;                  // [128][132]
    float* s_w   = smem + 16896;          // [64][132]
    float* s_c2T = smem + 25344;          // [64][132]
    __shared__ int s_a[128], s_b[128];
    __shared__ float s_b2[EMB], s_w3[EMB];

    const int tid = threadIdx.x;

    for (int i = tid; i < 64 * 128; i += 256) {
        int n = i >> 7, k = i & 127;
        s_w[n * 132 + k] = w2t[i];
    }
    if (tid < EMB) { s_b2[tid] = bd2[tid]; s_w3[tid] = Wd3[tid]; }
    const float b3 = bd3[0];

    for (int t2 = 0; t2 < 2; t2++) {
        const int q0blk = blockIdx.x * 256 + t2 * 128;

        if (tid < 128) {
            int qi = q0blk + tid;
            s_a[tid] = qi < N_QUERY ? qe[qi] : 0;
            s_b[tid] = qi < N_QUERY ? qe[N_QUERY + qi] : 0;
        }
        __syncthreads();

        // stage 1: s_d[q][k] = tf32(relu(U[a_q][k] + V[b_q][k]))
        const uint2* uv2 = (const uint2*)uv;
        for (int i = tid; i < 128 * 32; i += 256) {
            int q = i >> 5, c = i & 31;
            uint2 uu = uv2[(size_t)s_a[q] * 64 + c];
            uint2 vv = uv2[(size_t)s_b[q] * 64 + 32 + c];
            float2 u0 = __bfloat1622float2(*(__nv_bfloat162*)&uu.x);
            float2 u1 = __bfloat1622float2(*(__nv_bfloat162*)&uu.y);
            float2 v0 = __bfloat1622float2(*(__nv_bfloat162*)&vv.x);
            float2 v1 = __bfloat1622float2(*(__nv_bfloat162*)&vv.y);
            float* dst = &s_d[q * 132 + c * 4];
            dst[0] = to_tf32(fmaxf(u0.x + v0.x, 0.f));
            dst[1] = to_tf32(fmaxf(u0.y + v0.y, 0.f));
            dst[2] = to_tf32(fmaxf(u1.x + v1.x, 0.f));
            dst[3] = to_tf32(fmaxf(u1.y + v1.y, 0.f));
        }
        __syncthreads();

        // stage 2: c2T = relu(d @ Wd2 + b2) via tf32 mma; warp = 16-query stripe
        {
            const int lane = tid & 31, warp = tid >> 5;
            const int q0 = warp * 16;
            const int gid = lane >> 2, tig = lane & 3;
            float acc[8][4];
#pragma unroll
            for (int t = 0; t < 8; t++)
#pragma unroll
                for (int j = 0; j < 4; j++) acc[t][j] = 0.f;

#pragma unroll
            for (int k0 = 0; k0 < 128; k0 += 8) {
                float a0 = s_d[(q0 + gid) * 132 + k0 + tig];
                float a1 = s_d[(q0 + gid + 8) * 132 + k0 + tig];
                float a2 = s_d[(q0 + gid) * 132 + k0 + tig + 4];
                float a3 = s_d[(q0 + gid + 8) * 132 + k0 + tig + 4];
#pragma unroll
                for (int t = 0; t < 8; t++) {
                    float b0 = s_w[(t * 8 + gid) * 132 + k0 + tig];
                    float b1 = s_w[(t * 8 + gid) * 132 + k0 + tig + 4];
                    asm volatile(
                        "mma.sync.aligned.m16n8k8.row.col.f32.tf32.tf32.f32 "
                        "{%0,%1,%2,%3}, {%4,%5,%6,%7}, {%8,%9}, {%0,%1,%2,%3};"
                        : "+f"(acc[t][0]), "+f"(acc[t][1]), "+f"(acc[t][2]), "+f"(acc[t][3])
                        : "r"(__float_as_uint(a0)), "r"(__float_as_uint(a1)),
                          "r"(__float_as_uint(a2)), "r"(__float_as_uint(a3)),
                          "r"(__float_as_uint(b0)), "r"(__float_as_uint(b1)));
                }
            }
#pragma unroll
            for (int t = 0; t < 8; t++) {
                int c = t * 8 + 2 * tig;
                float bb0 = s_b2[c], bb1 = s_b2[c + 1];
                int qa = q0 + gid, qb = q0 + gid + 8;
                s_c2T[c * 132 + qa]       = fmaxf(acc[t][0] + bb0, 0.f);
                s_c2T[(c + 1) * 132 + qa] = fmaxf(acc[t][1] + bb1, 0.f);
                s_c2T[c * 132 + qb]       = fmaxf(acc[t][2] + bb0, 0.f);
                s_c2T[(c + 1) * 132 + qb] = fmaxf(acc[t][3] + bb1, 0.f);
            }
        }
        __syncthreads();

        // stage 3: logits + sigmoid
        if (tid < 128) {
            int qi = q0blk + tid;
            if (qi < N_QUERY) {
                float s = b3;
#pragma unroll 8
                for (int c = 0; c < EMB; c++) s = fmaf(s_c2T[c * 132 + tid], s_w3[c], s);
                out[qi] = 1.0f / (1.0f + expf(-s));
            }
        }
        __syncthreads();
    }
}

// ---------------- launch ----------------
extern "C" void kernel_launch(void* const* d_in, const int* in_sizes, int n_in,
                              void* d_out, int out_size) {
    const float* x   = (const float*)d_in[0];
    const int* ei    = (const int*)d_in[1];
    const int* qe    = (const int*)d_in[2];
    const float* W1  = (const float*)d_in[3];
    const float* b1  = (const float*)d_in[4];
    const float* W2  = (const float*)d_in[5];
    const float* b2  = (const float*)d_in[6];
    const float* Wfc = (const float*)d_in[7];
    const float* bfc = (const float*)d_in[8];
    const float* Wd1 = (const float*)d_in[9];
    const float* bd1 = (const float*)d_in[10];
    const float* Wd2 = (const float*)d_in[11];
    const float* bd2 = (const float*)d_in[12];
    const float* Wd3 = (const float*)d_in[13];
    const float* bd3 = (const float*)d_in[14];
    float* out = (float*)d_out;

    float *pW2T, *pWC, *pBC2;
    __nv_bfloat16 *pHS, *pH2, *pUV;
    int* pCnt;
    { void* p; cudaGetSymbolAddress(&p, g_hsb);   pHS = (__nv_bfloat16*)p; }
    { void* p; cudaGetSymbolAddress(&p, g_hb2);   pH2 = (__nv_bfloat16*)p; }
    { void* p; cudaGetSymbolAddress(&p, g_uvb);   pUV = (__nv_bfloat16*)p; }
    { void* p; cudaGetSymbolAddress(&p, g_w2t);   pW2T = (float*)p; }
    { void* p; cudaGetSymbolAddress(&p, g_wcomb); pWC = (float*)p; }
    { void* p; cudaGetSymbolAddress(&p, g_bcomb); pBC2 = (float*)p; }
    { void* p; cudaGetSymbolAddress(&p, g_cnt);   pCnt = (int*)p; }

    const int SM_L2   = (128 * 132 + 128 * 132) * 4;  // 135168
    const int SM_COMB = (128 * 132 + 256 * 132) * 4;  // 202752
    cudaFuncSetAttribute(gemm_tf32<128, 128, 0>, cudaFuncAttributeMaxDynamicSharedMemorySize, SM_L2);
    cudaFuncSetAttribute(gemm_tf32<128, 256, 1>, cudaFuncAttributeMaxDynamicSharedMemorySize, SM_COMB);
    cudaFuncSetAttribute(k_decoder, cudaFuncAttributeMaxDynamicSharedMemorySize, 135168);

    const int NBLK = (N_NODES + 127) / 128;

    // CSR build + weight packing
    cudaMemsetAsync(pCnt, 0, N_NODES * sizeof(int));
    k_cnt<<<(N_EDGES + 255) / 256, 256>>>(ei);
    k_scan<<<1, 1024>>>();
    k_dinv<<<(N_NODES + 255) / 256, 256>>>();
    k_fill<<<(N_EDGES + 255) / 256, 256>>>(ei);
    k_pack<<<64, 256>>>(Wd1, bd1, Wd2);
    k_wcomb<<<129, 256>>>(Wfc, bfc);

    // layer 1: hs1(bf16) -> agg -> h1'(bf16)
    k_mm_in<<<(N_NODES * 32 + 255) / 256, 256>>>(x, W1, pHS);
    k_agg<<<(N_NODES * 32 + 255) / 256, 256>>>(pHS, b1, pH2);

    // layer 2: hs2 = bf16((h1'@W2)*dinv) -> agg -> h2'(bf16)
    gemm_tf32<128, 128, 0><<<NBLK, 256, SM_L2>>>(pH2, W2, nullptr, pHS);
    k_agg<<<(N_NODES * 32 + 255) / 256, 256>>>(pHS, b2, pH2);

    // fused fc+UV: UV = bf16(h2' @ Wcomb + bcomb)
    gemm_tf32<128, 256, 1><<<NBLK, 256, SM_COMB>>>(pH2, pWC, pBC2, pUV);

    // decoder (2 tiles/block)
    k_decoder<<<(N_QUERY + 255) / 256, 256, 135168>>>(pUV, qe, pW2T, bd2, Wd3, bd3, out);
}

// round 10
// speedup vs baseline: 1.4691x; 1.4691x over previous
#include <cuda_runtime.h>
#include <cuda_bf16.h>
#include <math.h>
#include <stdint.h>

#define N_NODES 100000
#define N_EDGES 1600000
#define N_QUERY 500000
#define F_IN 7
#define HID 128
#define EMB 64

// ---------------- scratch (device globals) ----------------
__device__ float g_dinv[N_NODES];
__device__ int   g_cnt[N_NODES];
__device__ int   g_off[N_NODES + 1];
__device__ int   g_cur[N_NODES];
__device__ int   g_srcn[N_EDGES];
__device__ __nv_bfloat16 g_hsb[(size_t)N_NODES * HID];   // bf16 message buffer
__device__ __nv_bfloat16 g_hb2[(size_t)N_NODES * HID];   // bf16 aggregated activations
__device__ __nv_bfloat16 g_uvb[(size_t)N_NODES * 256];   // bf16 [U(128)+b1' | V(128)]
__device__ float g_wd1p[64 * 256];                       // packed [Wd1_top | Wd1_bot] fp32
__device__ float g_bc[256];                              // [bd1 | 0]
__device__ __nv_bfloat16 g_w2tb[64 * 128];               // Wd2^T [n][k] bf16
__device__ __nv_bfloat16 g_wl2t[128 * 128];              // W2^T  [n][k] bf16
__device__ __nv_bfloat16 g_wcombt[256 * 128];            // (Wfc@Wd1p)^T [n][k] bf16
__device__ float g_bcomb[256];                           // bfc @ Wd1p + bc

// ---------------- CSR build ----------------
__global__ void k_cnt(const int* __restrict__ ei) {
    int e = blockIdx.x * blockDim.x + threadIdx.x;
    if (e < N_EDGES) atomicAdd(&g_cnt[ei[N_EDGES + e]], 1);
}

__global__ __launch_bounds__(1024) void k_scan() {
    __shared__ int ssum[1024];
    const int tid = threadIdx.x;
    const int CHUNK = (N_NODES + 1023) / 1024;
    int lo = tid * CHUNK;
    int hi = min(lo + CHUNK, N_NODES);
    int sum = 0;
    for (int i = lo; i < hi; i++) sum += g_cnt[i];
    ssum[tid] = sum;
    __syncthreads();
    for (int off = 1; off < 1024; off <<= 1) {
        int t = (tid >= off) ? ssum[tid - off] : 0;
        __syncthreads();
        if (tid >= off) ssum[tid] += t;
        __syncthreads();
    }
    int run = ssum[tid] - sum;
    for (int i = lo; i < hi; i++) {
        g_off[i] = run;
        g_cur[i] = run;
        run += g_cnt[i];
    }
    if (lo < N_NODES && hi == N_NODES) g_off[N_NODES] = run;
}

__global__ void k_dinv() {
    int i = blockIdx.x * blockDim.x + threadIdx.x;
    if (i < N_NODES) g_dinv[i] = rsqrtf((float)g_cnt[i] + 1.0f);
}

__global__ void k_fill(const int* __restrict__ ei) {
    int e = blockIdx.x * blockDim.x + threadIdx.x;
    if (e >= N_EDGES) return;
    int s = ei[e];
    int d = ei[N_EDGES + e];
    int pos = atomicAdd(&g_cur[d], 1);
    g_srcn[pos] = s;
}

// ---------------- pack weights ----------------
__global__ void k_pack(const float* __restrict__ Wd1, const float* __restrict__ bd1,
                       const float* __restrict__ Wd2, const float* __restrict__ W2) {
    int idx = blockIdx.x * blockDim.x + threadIdx.x;
    if (idx < 64 * 256) {
        int k = idx >> 8, j = idx & 255;
        g_wd1p[idx] = (j < 128) ? Wd1[k * 128 + j] : Wd1[(64 + k) * 128 + (j - 128)];
    }
    if (idx < 256) g_bc[idx] = (idx < 128) ? bd1[idx] : 0.f;
    if (idx < 64 * 128) {
        int n = idx >> 7, k = idx & 127;
        g_w2tb[idx] = __float2bfloat16(Wd2[k * 64 + n]);
    }
    if (idx < 128 * 128) {
        int n = idx >> 7, k = idx & 127;
        g_wl2t[idx] = __float2bfloat16(W2[k * 128 + n]);
    }
}

// ---------------- combine fc into UV weights (transposed bf16 out) ----------------
__global__ void k_wcomb(const float* __restrict__ Wfc, const float* __restrict__ bfc) {
    __shared__ float s[64];
    int b = blockIdx.x;
    int c = threadIdx.x;  // 256
    if (b < 128) {
        if (c < 64) s[c] = Wfc[b * 64 + c];
        __syncthreads();
        float acc = 0.f;
#pragma unroll 8
        for (int j = 0; j < 64; j++) acc = fmaf(s[j], g_wd1p[j * 256 + c], acc);
        g_wcombt[c * 128 + b] = __float2bfloat16(acc);
    } else {
        if (c < 64) s[c] = bfc[c];
        __syncthreads();
        float acc = g_bc[c];
#pragma unroll 8
        for (int j = 0; j < 64; j++) acc = fmaf(s[j], g_wd1p[j * 256 + c], acc);
        g_bcomb[c] = acc;
    }
}

// ---------------- layer-1 input matmul: hs1 = bf16((x @ W1) * dinv) ----------------
__global__ void k_mm_in(const float* __restrict__ x, const float* __restrict__ W,
                        __nv_bfloat16* __restrict__ hs) {
    __shared__ float sW[F_IN * HID];
    int tid = threadIdx.x;
    for (int i = tid; i < F_IN * HID; i += blockDim.x) sW[i] = W[i];
    __syncthreads();
    int t = blockIdx.x * blockDim.x + tid;
    if (t >= N_NODES * 32) return;
    int node = t >> 5, j = (t & 31) * 4;
    float xr[F_IN];
#pragma unroll
    for (int k = 0; k < F_IN; k++) xr[k] = x[node * F_IN + k];
    float4 a = make_float4(0.f, 0.f, 0.f, 0.f);
#pragma unroll
    for (int k = 0; k < F_IN; k++) {
        const float* w = &sW[k * HID + j];
        a.x = fmaf(xr[k], w[0], a.x);
        a.y = fmaf(xr[k], w[1], a.y);
        a.z = fmaf(xr[k], w[2], a.z);
        a.w = fmaf(xr[k], w[3], a.w);
    }
    float dv = g_dinv[node];
    __nv_bfloat162 p0 = __floats2bfloat162_rn(a.x * dv, a.y * dv);
    __nv_bfloat162 p1 = __floats2bfloat162_rn(a.z * dv, a.w * dv);
    uint2 o;
    o.x = *(uint32_t*)&p0;
    o.y = *(uint32_t*)&p1;
    ((uint2*)hs)[t] = o;
}

// ---------------- fused CSR aggregation: out = bf16(relu(dinv*(sum+self)+b)) ------------
__global__ __launch_bounds__(256) void k_agg(const __nv_bfloat16* __restrict__ hs,
                                             const float* __restrict__ bias,
                                             __nv_bfloat16* __restrict__ out) {
    int t = blockIdx.x * blockDim.x + threadIdx.x;
    int node = t >> 5, lane = t & 31;
    if (node >= N_NODES) return;
    const uint2* h2 = (const uint2*)hs;

    float ax, ay, az, aw;
    {
        uint2 v = h2[(size_t)node * 32 + lane];
        float2 f0 = __bfloat1622float2(*(__nv_bfloat162*)&v.x);
        float2 f1 = __bfloat1622float2(*(__nv_bfloat162*)&v.y);
        ax = f0.x; ay = f0.y; az = f1.x; aw = f1.y;
    }
    int e = g_off[node];
    const int end = g_off[node + 1];
    for (; e + 4 <= end; e += 4) {
        int s0 = g_srcn[e], s1 = g_srcn[e + 1], s2 = g_srcn[e + 2], s3 = g_srcn[e + 3];
        uint2 v0 = h2[(size_t)s0 * 32 + lane];
        uint2 v1 = h2[(size_t)s1 * 32 + lane];
        uint2 v2 = h2[(size_t)s2 * 32 + lane];
        uint2 v3 = h2[(size_t)s3 * 32 + lane];
        float2 a0 = __bfloat1622float2(*(__nv_bfloat162*)&v0.x);
        float2 b0 = __bfloat1622float2(*(__nv_bfloat162*)&v0.y);
        float2 a1 = __bfloat1622float2(*(__nv_bfloat162*)&v1.x);
        float2 b1 = __bfloat1622float2(*(__nv_bfloat162*)&v1.y);
        float2 a2 = __bfloat1622float2(*(__nv_bfloat162*)&v2.x);
        float2 b2 = __bfloat1622float2(*(__nv_bfloat162*)&v2.y);
        float2 a3 = __bfloat1622float2(*(__nv_bfloat162*)&v3.x);
        float2 b3 = __bfloat1622float2(*(__nv_bfloat162*)&v3.y);
        ax += a0.x + a1.x + a2.x + a3.x;
        ay += a0.y + a1.y + a2.y + a3.y;
        az += b0.x + b1.x + b2.x + b3.x;
        aw += b0.y + b1.y + b2.y + b3.y;
    }
    for (; e < end; e++) {
        uint2 v = h2[(size_t)g_srcn[e] * 32 + lane];
        float2 f0 = __bfloat1622float2(*(__nv_bfloat162*)&v.x);
        float2 f1 = __bfloat1622float2(*(__nv_bfloat162*)&v.y);
        ax += f0.x; ay += f0.y; az += f1.x; aw += f1.y;
    }
    float dv = g_dinv[node];
    float4 bv = ((const float4*)bias)[lane];
    float r0 = fmaxf(fmaf(ax, dv, bv.x), 0.f);
    float r1 = fmaxf(fmaf(ay, dv, bv.y), 0.f);
    float r2 = fmaxf(fmaf(az, dv, bv.z), 0.f);
    float r3 = fmaxf(fmaf(aw, dv, bv.w), 0.f);
    __nv_bfloat162 p0 = __floats2bfloat162_rn(r0, r1);
    __nv_bfloat162 p1 = __floats2bfloat162_rn(r2, r3);
    uint2 o;
    o.x = *(uint32_t*)&p0;
    o.y = *(uint32_t*)&p1;
    ((uint2*)out)[(size_t)node * 32 + lane] = o;
}

// ---------------- bf16 tensor-core node GEMM: C[M,NT] = A[M,128] @ Bt^T ----------------
// A bf16 [M,128]; Bt bf16 [NT,128] (pre-transposed). m16n8k16 bf16 mma, fp32 accum.
// EPI 0: C = acc * dinv[row]; EPI 1: C = acc + bias[col]. Output bf16.
template <int NT, int EPI>
__global__ __launch_bounds__(256) void gemm_bf16(const __nv_bfloat16* __restrict__ A,
                                                 const __nv_bfloat16* __restrict__ Bt,
                                                 const float* __restrict__ bias,
                                                 __nv_bfloat16* __restrict__ C) {
    constexpr int KD = 128;
    constexpr int KP = KD + 8;   // bf16 pitch: 136 (word pitch 68 -> conflict-free)
    extern __shared__ char smraw[];
    __nv_bfloat16* s_a = (__nv_bfloat16*)smraw;                       // [128][KP]
    __nv_bfloat16* s_b = (__nv_bfloat16*)(smraw + 128 * KP * 2);      // [NT][KP]
    const int tid = threadIdx.x;
    const int row0 = blockIdx.x * 128;

    // B tile: verbatim bf16 copy with pitch
    for (int i = tid; i < NT * (KD / 4); i += 256) {
        int n = i >> 5, k4 = i & 31;
        *(uint2*)&s_b[n * KP + k4 * 4] = ((const uint2*)Bt)[i];
    }
    // A tile: verbatim bf16 copy with pitch
    for (int i = tid; i < 128 * (KD / 4); i += 256) {
        int r = i >> 5, k4 = i & 31;
        int gr = row0 + r;
        if (gr >= N_NODES) gr = N_NODES - 1;
        *(uint2*)&s_a[r * KP + k4 * 4] = *(const uint2*)&A[(size_t)gr * KD + k4 * 4];
    }
    __syncthreads();

    const int lane = tid & 31, warp = tid >> 5;
    const int q0 = warp * 16;
    const int gid = lane >> 2, tig = lane & 3;
    constexpr int NCHUNK = (NT > 128) ? 2 : 1;
    constexpr int NC = NT / NCHUNK;
    constexpr int NTILES = NC / 8;

    const int qa = row0 + q0 + gid, qb = qa + 8;
    float dva = 1.f, dvb = 1.f;
    if (EPI == 0) {
        dva = (qa < N_NODES) ? g_dinv[qa] : 0.f;
        dvb = (qb < N_NODES) ? g_dinv[qb] : 0.f;
    }

    for (int nc = 0; nc < NCHUNK; nc++) {
        float acc[NTILES][4];
#pragma unroll
        for (int t = 0; t < NTILES; t++)
#pragma unroll
            for (int j = 0; j < 4; j++) acc[t][j] = 0.f;

#pragma unroll
        for (int k0 = 0; k0 < KD; k0 += 16) {
            uint32_t a0 = *(const uint32_t*)&s_a[(q0 + gid) * KP + k0 + 2 * tig];
            uint32_t a1 = *(const uint32_t*)&s_a[(q0 + gid + 8) * KP + k0 + 2 * tig];
            uint32_t a2 = *(const uint32_t*)&s_a[(q0 + gid) * KP + k0 + 2 * tig + 8];
            uint32_t a3 = *(const uint32_t*)&s_a[(q0 + gid + 8) * KP + k0 + 2 * tig + 8];
#pragma unroll
            for (int t = 0; t < NTILES; t++) {
                int n = nc * NC + t * 8 + gid;
                uint32_t b0 = *(const uint32_t*)&s_b[n * KP + k0 + 2 * tig];
                uint32_t b1 = *(const uint32_t*)&s_b[n * KP + k0 + 2 * tig + 8];
                asm volatile(
                    "mma.sync.aligned.m16n8k16.row.col.f32.bf16.bf16.f32 "
                    "{%0,%1,%2,%3}, {%4,%5,%6,%7}, {%8,%9}, {%0,%1,%2,%3};"
                    : "+f"(acc[t][0]), "+f"(acc[t][1]), "+f"(acc[t][2]), "+f"(acc[t][3])
                    : "r"(a0), "r"(a1), "r"(a2), "r"(a3), "r"(b0), "r"(b1));
            }
        }
#pragma unroll
        for (int t = 0; t < NTILES; t++) {
            int c = nc * NC + t * 8 + 2 * tig;
            float r0, r1, r2, r3;
            if (EPI == 0) {
                r0 = acc[t][0] * dva; r1 = acc[t][1] * dva;
                r2 = acc[t][2] * dvb; r3 = acc[t][3] * dvb;
            } else {
                float b0 = bias[c], b1 = bias[c + 1];
                r0 = acc[t][0] + b0; r1 = acc[t][1] + b1;
                r2 = acc[t][2] + b0; r3 = acc[t][3] + b1;
            }
            __nv_bfloat162 pa = __floats2bfloat162_rn(r0, r1);
            __nv_bfloat162 pb = __floats2bfloat162_rn(r2, r3);
            if (qa < N_NODES) *(__nv_bfloat162*)&C[(size_t)qa * NT + c] = pa;
            if (qb < N_NODES) *(__nv_bfloat162*)&C[(size_t)qb * NT + c] = pb;
        }
    }
}

// ---------------- decoder: 128 q/block, bf16 gather + bf16 m16n8k16 stage 2 -------------
// dyn smem: s_d bf16[128][136] (34816B) | s_w bf16[64][136] (17408B) | s_c2T f32[64][132]
// total 86016B -> 2 blocks/SM
__global__ __launch_bounds__(256) void k_decoder(
    const __nv_bfloat16* __restrict__ uv, const int* __restrict__ qe,
    const __nv_bfloat16* __restrict__ w2t, const float* __restrict__ bd2,
    const float* __restrict__ Wd3, const float* __restrict__ bd3,
    float* __restrict__ out) {
    extern __shared__ char smraw[];
    __nv_bfloat16* s_d = (__nv_bfloat16*)smraw;              // [128][136]
    __nv_bfloat16* s_w = (__nv_bfloat16*)(smraw + 34816);    // [64][136]
    float* s_c2T = (float*)(smraw + 52224);                  // [64][132]
    __shared__ int s_a[128], s_b[128];
    __shared__ float s_b2[EMB], s_w3[EMB];

    const int tid = threadIdx.x;
    const int q0blk = blockIdx.x * 128;

    for (int i = tid; i < 64 * 32; i += 256) {
        int n = i >> 5, k4 = i & 31;
        *(uint2*)&s_w[n * 136 + k4 * 4] = ((const uint2*)w2t)[i];
    }
    if (tid < EMB) { s_b2[tid] = bd2[tid]; s_w3[tid] = Wd3[tid]; }
    if (tid < 128) {
        int qi = q0blk + tid;
        s_a[tid] = qi < N_QUERY ? qe[qi] : 0;
        s_b[tid] = qi < N_QUERY ? qe[N_QUERY + qi] : 0;
    }
    __syncthreads();

    // stage 1: s_d[q][k] = bf16(relu(U[a_q][k] + V[b_q][k]))
    const uint2* uv2 = (const uint2*)uv;
    for (int i = tid; i < 128 * 32; i += 256) {
        int q = i >> 5, c = i & 31;
        uint2 uu = uv2[(size_t)s_a[q] * 64 + c];
        uint2 vv = uv2[(size_t)s_b[q] * 64 + 32 + c];
        float2 u0 = __bfloat1622float2(*(__nv_bfloat162*)&uu.x);
        float2 u1 = __bfloat1622float2(*(__nv_bfloat162*)&uu.y);
        float2 v0 = __bfloat1622float2(*(__nv_bfloat162*)&vv.x);
        float2 v1 = __bfloat1622float2(*(__nv_bfloat162*)&vv.y);
        __nv_bfloat162 p0 = __floats2bfloat162_rn(fmaxf(u0.x + v0.x, 0.f), fmaxf(u0.y + v0.y, 0.f));
        __nv_bfloat162 p1 = __floats2bfloat162_rn(fmaxf(u1.x + v1.x, 0.f), fmaxf(u1.y + v1.y, 0.f));
        uint2 o;
        o.x = *(uint32_t*)&p0;
        o.y = *(uint32_t*)&p1;
        *(uint2*)&s_d[q * 136 + c * 4] = o;
    }
    __syncthreads();

    // stage 2: c2T = relu(d @ Wd2 + b2) via bf16 m16n8k16; warp = 16-query stripe
    {
        const int lane = tid & 31, warp = tid >> 5;
        const int q0 = warp * 16;
        const int gid = lane >> 2, tig = lane & 3;
        float acc[8][4];
#pragma unroll
        for (int t = 0; t < 8; t++)
#pragma unroll
            for (int j = 0; j < 4; j++) acc[t][j] = 0.f;

#pragma unroll
        for (int k0 = 0; k0 < 128; k0 += 16) {
            uint32_t a0 = *(const uint32_t*)&s_d[(q0 + gid) * 136 + k0 + 2 * tig];
            uint32_t a1 = *(const uint32_t*)&s_d[(q0 + gid + 8) * 136 + k0 + 2 * tig];
            uint32_t a2 = *(const uint32_t*)&s_d[(q0 + gid) * 136 + k0 + 2 * tig + 8];
            uint32_t a3 = *(const uint32_t*)&s_d[(q0 + gid + 8) * 136 + k0 + 2 * tig + 8];
#pragma unroll
            for (int t = 0; t < 8; t++) {
                int n = t * 8 + gid;
                uint32_t b0 = *(const uint32_t*)&s_w[n * 136 + k0 + 2 * tig];
                uint32_t b1 = *(const uint32_t*)&s_w[n * 136 + k0 + 2 * tig + 8];
                asm volatile(
                    "mma.sync.aligned.m16n8k16.row.col.f32.bf16.bf16.f32 "
                    "{%0,%1,%2,%3}, {%4,%5,%6,%7}, {%8,%9}, {%0,%1,%2,%3};"
                    : "+f"(acc[t][0]), "+f"(acc[t][1]), "+f"(acc[t][2]), "+f"(acc[t][3])
                    : "r"(a0), "r"(a1), "r"(a2), "r"(a3), "r"(b0), "r"(b1));
            }
        }
#pragma unroll
        for (int t = 0; t < 8; t++) {
            int c = t * 8 + 2 * tig;
            float bb0 = s_b2[c], bb1 = s_b2[c + 1];
            int qa = q0 + gid, qb = q0 + gid + 8;
            s_c2T[c * 132 + qa]       = fmaxf(acc[t][0] + bb0, 0.f);
            s_c2T[(c + 1) * 132 + qa] = fmaxf(acc[t][1] + bb1, 0.f);
            s_c2T[c * 132 + qb]       = fmaxf(acc[t][2] + bb0, 0.f);
            s_c2T[(c + 1) * 132 + qb] = fmaxf(acc[t][3] + bb1, 0.f);
        }
    }
    __syncthreads();

    // stage 3: logits + sigmoid
    if (tid < 128) {
        int qi = q0blk + tid;
        if (qi < N_QUERY) {
            float s = bd3[0];
#pragma unroll 8
            for (int c = 0; c < EMB; c++) s = fmaf(s_c2T[c * 132 + tid], s_w3[c], s);
            out[qi] = 1.0f / (1.0f + expf(-s));
        }
    }
}

// ---------------- launch ----------------
extern "C" void kernel_launch(void* const* d_in, const int* in_sizes, int n_in,
                              void* d_out, int out_size) {
    const float* x   = (const float*)d_in[0];
    const int* ei    = (const int*)d_in[1];
    const int* qe    = (const int*)d_in[2];
    const float* W1  = (const float*)d_in[3];
    const float* b1  = (const float*)d_in[4];
    const float* W2  = (const float*)d_in[5];
    const float* b2  = (const float*)d_in[6];
    const float* Wfc = (const float*)d_in[7];
    const float* bfc = (const float*)d_in[8];
    const float* Wd1 = (const float*)d_in[9];
    const float* bd1 = (const float*)d_in[10];
    const float* Wd2 = (const float*)d_in[11];
    const float* bd2 = (const float*)d_in[12];
    const float* Wd3 = (const float*)d_in[13];
    const float* bd3 = (const float*)d_in[14];
    float* out = (float*)d_out;

    float* pBC2;
    __nv_bfloat16 *pHS, *pH2, *pUV, *pW2TB, *pWL2T, *pWCT;
    int* pCnt;
    { void* p; cudaGetSymbolAddress(&p, g_hsb);    pHS = (__nv_bfloat16*)p; }
    { void* p; cudaGetSymbolAddress(&p, g_hb2);    pH2 = (__nv_bfloat16*)p; }
    { void* p; cudaGetSymbolAddress(&p, g_uvb);    pUV = (__nv_bfloat16*)p; }
    { void* p; cudaGetSymbolAddress(&p, g_w2tb);   pW2TB = (__nv_bfloat16*)p; }
    { void* p; cudaGetSymbolAddress(&p, g_wl2t);   pWL2T = (__nv_bfloat16*)p; }
    { void* p; cudaGetSymbolAddress(&p, g_wcombt); pWCT = (__nv_bfloat16*)p; }
    { void* p; cudaGetSymbolAddress(&p, g_bcomb);  pBC2 = (float*)p; }
    { void* p; cudaGetSymbolAddress(&p, g_cnt);    pCnt = (int*)p; }

    const int SM_L2   = (128 * 136 + 128 * 136) * 2;  // 69632
    const int SM_COMB = (128 * 136 + 256 * 136) * 2;  // 104448
    const int SM_DEC  = 34816 + 17408 + 64 * 132 * 4; // 86016
    cudaFuncSetAttribute(gemm_bf16<128, 0>, cudaFuncAttributeMaxDynamicSharedMemorySize, SM_L2);
    cudaFuncSetAttribute(gemm_bf16<256, 1>, cudaFuncAttributeMaxDynamicSharedMemorySize, SM_COMB);
    cudaFuncSetAttribute(k_decoder, cudaFuncAttributeMaxDynamicSharedMemorySize, SM_DEC);

    const int NBLK = (N_NODES + 127) / 128;

    // CSR build + weight packing
    cudaMemsetAsync(pCnt, 0, N_NODES * sizeof(int));
    k_cnt<<<(N_EDGES + 255) / 256, 256>>>(ei);
    k_scan<<<1, 1024>>>();
    k_dinv<<<(N_NODES + 255) / 256, 256>>>();
    k_fill<<<(N_EDGES + 255) / 256, 256>>>(ei);
    k_pack<<<64, 256>>>(Wd1, bd1, Wd2, W2);
    k_wcomb<<<129, 256>>>(Wfc, bfc);

    // layer 1: hs1(bf16) -> agg -> h1'(bf16)
    k_mm_in<<<(N_NODES * 32 + 255) / 256, 256>>>(x, W1, pHS);
    k_agg<<<(N_NODES * 32 + 255) / 256, 256>>>(pHS, b1, pH2);

    // layer 2: hs2 = bf16((h1'@W2)*dinv) -> agg -> h2'(bf16)
    gemm_bf16<128, 0><<<NBLK, 256, SM_L2>>>(pH2, pWL2T, nullptr, pHS);
    k_agg<<<(N_NODES * 32 + 255) / 256, 256>>>(pHS, b2, pH2);

    // fused fc+UV: UV = bf16(h2' @ Wcomb + bcomb)
    gemm_bf16<256, 1><<<NBLK, 256, SM_COMB>>>(pH2, pWCT, pBC2, pUV);

    // decoder
    k_decoder<<<(N_QUERY + 127) / 128, 256, SM_DEC>>>(pUV, qe, pW2TB, bd2, Wd3, bd3, out);
}

// round 11
// speedup vs baseline: 1.4740x; 1.0034x over previous
#include <cuda_runtime.h>
#include <cuda_bf16.h>
#include <math.h>
#include <stdint.h>

#define N_NODES 100000
#define N_EDGES 1600000
#define N_QUERY 500000
#define F_IN 7
#define HID 128
#define EMB 64

// ---------------- scratch (device globals) ----------------
__device__ float g_dinv[N_NODES];
__device__ int   g_cnt[N_NODES];
__device__ int   g_off[N_NODES + 1];
__device__ int   g_cur[N_NODES];
__device__ int   g_srcn[N_EDGES];
__device__ __nv_bfloat16 g_hsb[(size_t)N_NODES * HID];   // bf16 message buffer
__device__ __nv_bfloat16 g_hb2[(size_t)N_NODES * HID];   // bf16 aggregated activations
__device__ __nv_bfloat16 g_uvb[(size_t)N_NODES * 256];   // bf16 [U(128)+b1' | V(128)]
__device__ float g_wd1p[64 * 256];                       // packed [Wd1_top | Wd1_bot] fp32
__device__ float g_bc[256];                              // [bd1 | 0]
__device__ __nv_bfloat16 g_w2tb[64 * 128];               // Wd2^T [n][k] bf16
__device__ __nv_bfloat16 g_wl2t[128 * 128];              // W2^T  [n][k] bf16
__device__ __nv_bfloat16 g_wcombt[256 * 128];            // (Wfc@Wd1p)^T [n][k] bf16
__device__ float g_bcomb[256];                           // bfc @ Wd1p + bc

// ---------------- CSR build ----------------
__global__ void k_cnt(const int* __restrict__ ei) {
    int e = blockIdx.x * blockDim.x + threadIdx.x;
    if (e < N_EDGES) atomicAdd(&g_cnt[ei[N_EDGES + e]], 1);
}

// scan + dinv fused
__global__ __launch_bounds__(1024) void k_scan() {
    __shared__ int ssum[1024];
    const int tid = threadIdx.x;
    const int CHUNK = (N_NODES + 1023) / 1024;
    int lo = tid * CHUNK;
    int hi = min(lo + CHUNK, N_NODES);
    int sum = 0;
    for (int i = lo; i < hi; i++) sum += g_cnt[i];
    ssum[tid] = sum;
    __syncthreads();
    for (int off = 1; off < 1024; off <<= 1) {
        int t = (tid >= off) ? ssum[tid - off] : 0;
        __syncthreads();
        if (tid >= off) ssum[tid] += t;
        __syncthreads();
    }
    int run = ssum[tid] - sum;
    for (int i = lo; i < hi; i++) {
        int c = g_cnt[i];
        g_off[i] = run;
        g_cur[i] = run;
        g_dinv[i] = rsqrtf((float)c + 1.0f);
        run += c;
    }
    if (lo < N_NODES && hi == N_NODES) g_off[N_NODES] = run;
}

__global__ void k_fill(const int* __restrict__ ei) {
    int e = blockIdx.x * blockDim.x + threadIdx.x;
    if (e >= N_EDGES) return;
    int s = ei[e];
    int d = ei[N_EDGES + e];
    int pos = atomicAdd(&g_cur[d], 1);
    g_srcn[pos] = s;
}

// ---------------- pack weights ----------------
__global__ void k_pack(const float* __restrict__ Wd1, const float* __restrict__ bd1,
                       const float* __restrict__ Wd2, const float* __restrict__ W2) {
    int idx = blockIdx.x * blockDim.x + threadIdx.x;
    if (idx < 64 * 256) {
        int k = idx >> 8, j = idx & 255;
        g_wd1p[idx] = (j < 128) ? Wd1[k * 128 + j] : Wd1[(64 + k) * 128 + (j - 128)];
    }
    if (idx < 256) g_bc[idx] = (idx < 128) ? bd1[idx] : 0.f;
    if (idx < 64 * 128) {
        int n = idx >> 7, k = idx & 127;
        g_w2tb[idx] = __float2bfloat16(Wd2[k * 64 + n]);
    }
    if (idx < 128 * 128) {
        int n = idx >> 7, k = idx & 127;
        g_wl2t[idx] = __float2bfloat16(W2[k * 128 + n]);
    }
}

// ---------------- combine fc into UV weights (transposed bf16 out) ----------------
__global__ void k_wcomb(const float* __restrict__ Wfc, const float* __restrict__ bfc) {
    __shared__ float s[64];
    int b = blockIdx.x;
    int c = threadIdx.x;  // 256
    if (b < 128) {
        if (c < 64) s[c] = Wfc[b * 64 + c];
        __syncthreads();
        float acc = 0.f;
#pragma unroll 8
        for (int j = 0; j < 64; j++) acc = fmaf(s[j], g_wd1p[j * 256 + c], acc);
        g_wcombt[c * 128 + b] = __float2bfloat16(acc);
    } else {
        if (c < 64) s[c] = bfc[c];
        __syncthreads();
        float acc = g_bc[c];
#pragma unroll 8
        for (int j = 0; j < 64; j++) acc = fmaf(s[j], g_wd1p[j * 256 + c], acc);
        g_bcomb[c] = acc;
    }
}

// ---------------- layer-1 input matmul: hs1 = bf16((x @ W1) * dinv) ----------------
__global__ void k_mm_in(const float* __restrict__ x, const float* __restrict__ W,
                        __nv_bfloat16* __restrict__ hs) {
    __shared__ float sW[F_IN * HID];
    int tid = threadIdx.x;
    for (int i = tid; i < F_IN * HID; i += blockDim.x) sW[i] = W[i];
    __syncthreads();
    int t = blockIdx.x * blockDim.x + tid;
    if (t >= N_NODES * 32) return;
    int node = t >> 5, j = (t & 31) * 4;
    float xr[F_IN];
#pragma unroll
    for (int k = 0; k < F_IN; k++) xr[k] = x[node * F_IN + k];
    float4 a = make_float4(0.f, 0.f, 0.f, 0.f);
#pragma unroll
    for (int k = 0; k < F_IN; k++) {
        const float* w = &sW[k * HID + j];
        a.x = fmaf(xr[k], w[0], a.x);
        a.y = fmaf(xr[k], w[1], a.y);
        a.z = fmaf(xr[k], w[2], a.z);
        a.w = fmaf(xr[k], w[3], a.w);
    }
    float dv = g_dinv[node];
    __nv_bfloat162 p0 = __floats2bfloat162_rn(a.x * dv, a.y * dv);
    __nv_bfloat162 p1 = __floats2bfloat162_rn(a.z * dv, a.w * dv);
    uint2 o;
    o.x = *(uint32_t*)&p0;
    o.y = *(uint32_t*)&p1;
    ((uint2*)hs)[t] = o;
}

// ---------------- fused CSR aggregation: out = bf16(relu(dinv*(sum+self)+b)) ------------
// One node per warp; half-warp per edge (uint4 lane loads), shfl(16) merge at end.
__global__ __launch_bounds__(256) void k_agg(const __nv_bfloat16* __restrict__ hs,
                                             const float* __restrict__ bias,
                                             __nv_bfloat16* __restrict__ out) {
    int t = blockIdx.x * blockDim.x + threadIdx.x;
    int node = t >> 5, lane = t & 31;
    if (node >= N_NODES) return;
    const int half = lane >> 4;     // which edge of the pair
    const int cl = lane & 15;       // 16-byte column chunk (8 bf16)
    const uint4* h4 = (const uint4*)hs;   // 16 uint4 per row

    float a0 = 0.f, a1 = 0.f, a2 = 0.f, a3 = 0.f, a4 = 0.f, a5 = 0.f, a6 = 0.f, a7 = 0.f;
#define ACC_ADD(vv) do { \
        float2 f0 = __bfloat1622float2(*(__nv_bfloat162*)&(vv).x); \
        float2 f1 = __bfloat1622float2(*(__nv_bfloat162*)&(vv).y); \
        float2 f2 = __bfloat1622float2(*(__nv_bfloat162*)&(vv).z); \
        float2 f3 = __bfloat1622float2(*(__nv_bfloat162*)&(vv).w); \
        a0 += f0.x; a1 += f0.y; a2 += f1.x; a3 += f1.y; \
        a4 += f2.x; a5 += f2.y; a6 += f3.x; a7 += f3.y; } while (0)

    if (half == 0) {  // self contribution once
        uint4 v = h4[(size_t)node * 16 + cl];
        ACC_ADD(v);
    }
    int e = g_off[node] + half;
    const int end = g_off[node + 1];
    for (; e + 6 < end; e += 8) {
        int s0 = g_srcn[e], s1 = g_srcn[e + 2], s2 = g_srcn[e + 4], s3 = g_srcn[e + 6];
        uint4 v0 = h4[(size_t)s0 * 16 + cl];
        uint4 v1 = h4[(size_t)s1 * 16 + cl];
        uint4 v2 = h4[(size_t)s2 * 16 + cl];
        uint4 v3 = h4[(size_t)s3 * 16 + cl];
        ACC_ADD(v0); ACC_ADD(v1); ACC_ADD(v2); ACC_ADD(v3);
    }
    for (; e < end; e += 2) {
        uint4 v = h4[(size_t)g_srcn[e] * 16 + cl];
        ACC_ADD(v);
    }
#undef ACC_ADD
    // merge halves
    a0 += __shfl_xor_sync(0xffffffffu, a0, 16);
    a1 += __shfl_xor_sync(0xffffffffu, a1, 16);
    a2 += __shfl_xor_sync(0xffffffffu, a2, 16);
    a3 += __shfl_xor_sync(0xffffffffu, a3, 16);
    a4 += __shfl_xor_sync(0xffffffffu, a4, 16);
    a5 += __shfl_xor_sync(0xffffffffu, a5, 16);
    a6 += __shfl_xor_sync(0xffffffffu, a6, 16);
    a7 += __shfl_xor_sync(0xffffffffu, a7, 16);

    if (half == 0) {
        float dv = g_dinv[node];
        float4 bl = ((const float4*)bias)[cl * 2];
        float4 bh = ((const float4*)bias)[cl * 2 + 1];
        float r0 = fmaxf(fmaf(a0, dv, bl.x), 0.f);
        float r1 = fmaxf(fmaf(a1, dv, bl.y), 0.f);
        float r2 = fmaxf(fmaf(a2, dv, bl.z), 0.f);
        float r3 = fmaxf(fmaf(a3, dv, bl.w), 0.f);
        float r4 = fmaxf(fmaf(a4, dv, bh.x), 0.f);
        float r5 = fmaxf(fmaf(a5, dv, bh.y), 0.f);
        float r6 = fmaxf(fmaf(a6, dv, bh.z), 0.f);
        float r7 = fmaxf(fmaf(a7, dv, bh.w), 0.f);
        __nv_bfloat162 p0 = __floats2bfloat162_rn(r0, r1);
        __nv_bfloat162 p1 = __floats2bfloat162_rn(r2, r3);
        __nv_bfloat162 p2 = __floats2bfloat162_rn(r4, r5);
        __nv_bfloat162 p3 = __floats2bfloat162_rn(r6, r7);
        uint4 o;
        o.x = *(uint32_t*)&p0; o.y = *(uint32_t*)&p1;
        o.z = *(uint32_t*)&p2; o.w = *(uint32_t*)&p3;
        ((uint4*)out)[(size_t)node * 16 + cl] = o;
    }
}

// ---------------- bf16 tensor-core node GEMM: C[M,NT] = A[M,128] @ Bt^T ----------------
template <int NT, int EPI>
__global__ __launch_bounds__(256) void gemm_bf16(const __nv_bfloat16* __restrict__ A,
                                                 const __nv_bfloat16* __restrict__ Bt,
                                                 const float* __restrict__ bias,
                                                 __nv_bfloat16* __restrict__ C) {
    constexpr int KD = 128;
    constexpr int KP = KD + 8;   // bf16 pitch 136
    extern __shared__ char smraw[];
    __nv_bfloat16* s_a = (__nv_bfloat16*)smraw;                       // [128][KP]
    __nv_bfloat16* s_b = (__nv_bfloat16*)(smraw + 128 * KP * 2);      // [NT][KP]
    const int tid = threadIdx.x;
    const int row0 = blockIdx.x * 128;

    for (int i = tid; i < NT * (KD / 4); i += 256) {
        int n = i >> 5, k4 = i & 31;
        *(uint2*)&s_b[n * KP + k4 * 4] = ((const uint2*)Bt)[i];
    }
    for (int i = tid; i < 128 * (KD / 4); i += 256) {
        int r = i >> 5, k4 = i & 31;
        int gr = row0 + r;
        if (gr >= N_NODES) gr = N_NODES - 1;
        *(uint2*)&s_a[r * KP + k4 * 4] = *(const uint2*)&A[(size_t)gr * KD + k4 * 4];
    }
    __syncthreads();

    const int lane = tid & 31, warp = tid >> 5;
    const int q0 = warp * 16;
    const int gid = lane >> 2, tig = lane & 3;
    constexpr int NCHUNK = (NT > 128) ? 2 : 1;
    constexpr int NC = NT / NCHUNK;
    constexpr int NTILES = NC / 8;

    const int qa = row0 + q0 + gid, qb = qa + 8;
    float dva = 1.f, dvb = 1.f;
    if (EPI == 0) {
        dva = (qa < N_NODES) ? g_dinv[qa] : 0.f;
        dvb = (qb < N_NODES) ? g_dinv[qb] : 0.f;
    }

    for (int nc = 0; nc < NCHUNK; nc++) {
        float acc[NTILES][4];
#pragma unroll
        for (int t = 0; t < NTILES; t++)
#pragma unroll
            for (int j = 0; j < 4; j++) acc[t][j] = 0.f;

#pragma unroll
        for (int k0 = 0; k0 < KD; k0 += 16) {
            uint32_t a0 = *(const uint32_t*)&s_a[(q0 + gid) * KP + k0 + 2 * tig];
            uint32_t a1 = *(const uint32_t*)&s_a[(q0 + gid + 8) * KP + k0 + 2 * tig];
            uint32_t a2 = *(const uint32_t*)&s_a[(q0 + gid) * KP + k0 + 2 * tig + 8];
            uint32_t a3 = *(const uint32_t*)&s_a[(q0 + gid + 8) * KP + k0 + 2 * tig + 8];
#pragma unroll
            for (int t = 0; t < NTILES; t++) {
                int n = nc * NC + t * 8 + gid;
                uint32_t b0 = *(const uint32_t*)&s_b[n * KP + k0 + 2 * tig];
                uint32_t b1 = *(const uint32_t*)&s_b[n * KP + k0 + 2 * tig + 8];
                asm volatile(
                    "mma.sync.aligned.m16n8k16.row.col.f32.bf16.bf16.f32 "
                    "{%0,%1,%2,%3}, {%4,%5,%6,%7}, {%8,%9}, {%0,%1,%2,%3};"
                    : "+f"(acc[t][0]), "+f"(acc[t][1]), "+f"(acc[t][2]), "+f"(acc[t][3])
                    : "r"(a0), "r"(a1), "r"(a2), "r"(a3), "r"(b0), "r"(b1));
            }
        }
#pragma unroll
        for (int t = 0; t < NTILES; t++) {
            int c = nc * NC + t * 8 + 2 * tig;
            float r0, r1, r2, r3;
            if (EPI == 0) {
                r0 = acc[t][0] * dva; r1 = acc[t][1] * dva;
                r2 = acc[t][2] * dvb; r3 = acc[t][3] * dvb;
            } else {
                float b0 = bias[c], b1 = bias[c + 1];
                r0 = acc[t][0] + b0; r1 = acc[t][1] + b1;
                r2 = acc[t][2] + b0; r3 = acc[t][3] + b1;
            }
            __nv_bfloat162 pa = __floats2bfloat162_rn(r0, r1);
            __nv_bfloat162 pb = __floats2bfloat162_rn(r2, r3);
            if (qa < N_NODES) *(__nv_bfloat162*)&C[(size_t)qa * NT + c] = pa;
            if (qb < N_NODES) *(__nv_bfloat162*)&C[(size_t)qb * NT + c] = pb;
        }
    }
}

// ---------------- decoder: 128 q/block; bf16 mma stage 2; stage 3 fused via shfl --------
// dyn smem: s_d bf16[128][136] (34816B) | s_w bf16[64][136] (17408B) = 52224B -> 4 blk/SM
__global__ __launch_bounds__(256) void k_decoder(
    const __nv_bfloat16* __restrict__ uv, const int* __restrict__ qe,
    const __nv_bfloat16* __restrict__ w2t, const float* __restrict__ bd2,
    const float* __restrict__ Wd3, const float* __restrict__ bd3,
    float* __restrict__ out) {
    extern __shared__ char smraw[];
    __nv_bfloat16* s_d = (__nv_bfloat16*)smraw;              // [128][136]
    __nv_bfloat16* s_w = (__nv_bfloat16*)(smraw + 34816);    // [64][136]
    __shared__ int s_a[128], s_b[128];
    __shared__ float s_b2[EMB], s_w3[EMB];

    const int tid = threadIdx.x;
    const int q0blk = blockIdx.x * 128;

    for (int i = tid; i < 64 * 32; i += 256) {
        int n = i >> 5, k4 = i & 31;
        *(uint2*)&s_w[n * 136 + k4 * 4] = ((const uint2*)w2t)[i];
    }
    if (tid < EMB) { s_b2[tid] = bd2[tid]; s_w3[tid] = Wd3[tid]; }
    if (tid < 128) {
        int qi = q0blk + tid;
        s_a[tid] = qi < N_QUERY ? qe[qi] : 0;
        s_b[tid] = qi < N_QUERY ? qe[N_QUERY + qi] : 0;
    }
    __syncthreads();

    // stage 1: s_d[q][k] = bf16(relu(U[a_q][k] + V[b_q][k]))
    const uint2* uv2 = (const uint2*)uv;
    for (int i = tid; i < 128 * 32; i += 256) {
        int q = i >> 5, c = i & 31;
        uint2 uu = uv2[(size_t)s_a[q] * 64 + c];
        uint2 vv = uv2[(size_t)s_b[q] * 64 + 32 + c];
        float2 u0 = __bfloat1622float2(*(__nv_bfloat162*)&uu.x);
        float2 u1 = __bfloat1622float2(*(__nv_bfloat162*)&uu.y);
        float2 v0 = __bfloat1622float2(*(__nv_bfloat162*)&vv.x);
        float2 v1 = __bfloat1622float2(*(__nv_bfloat162*)&vv.y);
        __nv_bfloat162 p0 = __floats2bfloat162_rn(fmaxf(u0.x + v0.x, 0.f), fmaxf(u0.y + v0.y, 0.f));
        __nv_bfloat162 p1 = __floats2bfloat162_rn(fmaxf(u1.x + v1.x, 0.f), fmaxf(u1.y + v1.y, 0.f));
        uint2 o;
        o.x = *(uint32_t*)&p0;
        o.y = *(uint32_t*)&p1;
        *(uint2*)&s_d[q * 136 + c * 4] = o;
    }
    __syncthreads();

    // stage 2 + 3: mma, then logits directly from accumulators via shfl reduction
    {
        const int lane = tid & 31, warp = tid >> 5;
        const int q0 = warp * 16;
        const int gid = lane >> 2, tig = lane & 3;
        float acc[8][4];
#pragma unroll
        for (int t = 0; t < 8; t++)
#pragma unroll
            for (int j = 0; j < 4; j++) acc[t][j] = 0.f;

#pragma unroll
        for (int k0 = 0; k0 < 128; k0 += 16) {
            uint32_t a0 = *(const uint32_t*)&s_d[(q0 + gid) * 136 + k0 + 2 * tig];
            uint32_t a1 = *(const uint32_t*)&s_d[(q0 + gid + 8) * 136 + k0 + 2 * tig];
            uint32_t a2 = *(const uint32_t*)&s_d[(q0 + gid) * 136 + k0 + 2 * tig + 8];
            uint32_t a3 = *(const uint32_t*)&s_d[(q0 + gid + 8) * 136 + k0 + 2 * tig + 8];
#pragma unroll
            for (int t = 0; t < 8; t++) {
                int n = t * 8 + gid;
                uint32_t b0 = *(const uint32_t*)&s_w[n * 136 + k0 + 2 * tig];
                uint32_t b1 = *(const uint32_t*)&s_w[n * 136 + k0 + 2 * tig + 8];
                asm volatile(
                    "mma.sync.aligned.m16n8k16.row.col.f32.bf16.bf16.f32 "
                    "{%0,%1,%2,%3}, {%4,%5,%6,%7}, {%8,%9}, {%0,%1,%2,%3};"
                    : "+f"(acc[t][0]), "+f"(acc[t][1]), "+f"(acc[t][2]), "+f"(acc[t][3])
                    : "r"(a0), "r"(a1), "r"(a2), "r"(a3), "r"(b0), "r"(b1));
            }
        }
        // stage 3 fused: each lane covers cols {t*8+2tig, +1}; reduce over tig (shfl 1,2)
        float pa = 0.f, pb = 0.f;
#pragma unroll
        for (int t = 0; t < 8; t++) {
            int c = t * 8 + 2 * tig;
            float bb0 = s_b2[c], bb1 = s_b2[c + 1];
            float w0 = s_w3[c], w1 = s_w3[c + 1];
            pa = fmaf(fmaxf(acc[t][0] + bb0, 0.f), w0, pa);
            pa = fmaf(fmaxf(acc[t][1] + bb1, 0.f), w1, pa);
            pb = fmaf(fmaxf(acc[t][2] + bb0, 0.f), w0, pb);
            pb = fmaf(fmaxf(acc[t][3] + bb1, 0.f), w1, pb);
        }
        pa += __shfl_xor_sync(0xffffffffu, pa, 1);
        pa += __shfl_xor_sync(0xffffffffu, pa, 2);
        pb += __shfl_xor_sync(0xffffffffu, pb, 1);
        pb += __shfl_xor_sync(0xffffffffu, pb, 2);
        if (tig == 0) {
            float b3 = bd3[0];
            int qi_a = q0blk + q0 + gid;
            int qi_b = qi_a + 8;
            if (qi_a < N_QUERY) out[qi_a] = 1.0f / (1.0f + expf(-(pa + b3)));
            if (qi_b < N_QUERY) out[qi_b] = 1.0f / (1.0f + expf(-(pb + b3)));
        }
    }
}

// ---------------- launch ----------------
extern "C" void kernel_launch(void* const* d_in, const int* in_sizes, int n_in,
                              void* d_out, int out_size) {
    const float* x   = (const float*)d_in[0];
    const int* ei    = (const int*)d_in[1];
    const int* qe    = (const int*)d_in[2];
    const float* W1  = (const float*)d_in[3];
    const float* b1  = (const float*)d_in[4];
    const float* W2  = (const float*)d_in[5];
    const float* b2  = (const float*)d_in[6];
    const float* Wfc = (const float*)d_in[7];
    const float* bfc = (const float*)d_in[8];
    const float* Wd1 = (const float*)d_in[9];
    const float* bd1 = (const float*)d_in[10];
    const float* Wd2 = (const float*)d_in[11];
    const float* bd2 = (const float*)d_in[12];
    const float* Wd3 = (const float*)d_in[13];
    const float* bd3 = (const float*)d_in[14];
    float* out = (float*)d_out;

    float* pBC2;
    __nv_bfloat16 *pHS, *pH2, *pUV, *pW2TB, *pWL2T, *pWCT;
    int* pCnt;
    { void* p; cudaGetSymbolAddress(&p, g_hsb);    pHS = (__nv_bfloat16*)p; }
    { void* p; cudaGetSymbolAddress(&p, g_hb2);    pH2 = (__nv_bfloat16*)p; }
    { void* p; cudaGetSymbolAddress(&p, g_uvb);    pUV = (__nv_bfloat16*)p; }
    { void* p; cudaGetSymbolAddress(&p, g_w2tb);   pW2TB = (__nv_bfloat16*)p; }
    { void* p; cudaGetSymbolAddress(&p, g_wl2t);   pWL2T = (__nv_bfloat16*)p; }
    { void* p; cudaGetSymbolAddress(&p, g_wcombt); pWCT = (__nv_bfloat16*)p; }
    { void* p; cudaGetSymbolAddress(&p, g_bcomb);  pBC2 = (float*)p; }
    { void* p; cudaGetSymbolAddress(&p, g_cnt);    pCnt = (int*)p; }

    const int SM_L2   = (128 * 136 + 128 * 136) * 2;  // 69632
    const int SM_COMB = (128 * 136 + 256 * 136) * 2;  // 104448
    const int SM_DEC  = 34816 + 17408;                // 52224 -> 4 blocks/SM
    cudaFuncSetAttribute(gemm_bf16<128, 0>, cudaFuncAttributeMaxDynamicSharedMemorySize, SM_L2);
    cudaFuncSetAttribute(gemm_bf16<256, 1>, cudaFuncAttributeMaxDynamicSharedMemorySize, SM_COMB);
    cudaFuncSetAttribute(k_decoder, cudaFuncAttributeMaxDynamicSharedMemorySize, SM_DEC);

    const int NBLK = (N_NODES + 127) / 128;

    // CSR build + weight packing
    cudaMemsetAsync(pCnt, 0, N_NODES * sizeof(int));
    k_cnt<<<(N_EDGES + 255) / 256, 256>>>(ei);
    k_scan<<<1, 1024>>>();
    k_fill<<<(N_EDGES + 255) / 256, 256>>>(ei);
    k_pack<<<64, 256>>>(Wd1, bd1, Wd2, W2);
    k_wcomb<<<129, 256>>>(Wfc, bfc);

    // layer 1: hs1(bf16) -> agg -> h1'(bf16)
    k_mm_in<<<(N_NODES * 32 + 255) / 256, 256>>>(x, W1, pHS);
    k_agg<<<(N_NODES * 32 + 255) / 256, 256>>>(pHS, b1, pH2);

    // layer 2: hs2 = bf16((h1'@W2)*dinv) -> agg -> h2'(bf16)
    gemm_bf16<128, 0><<<NBLK, 256, SM_L2>>>(pH2, pWL2T, nullptr, pHS);
    k_agg<<<(N_NODES * 32 + 255) / 256, 256>>>(pHS, b2, pH2);

    // fused fc+UV: UV = bf16(h2' @ Wcomb + bcomb)
    gemm_bf16<256, 1><<<NBLK, 256, SM_COMB>>>(pH2, pWCT, pBC2, pUV);

    // decoder
    k_decoder<<<(N_QUERY + 127) / 128, 256, SM_DEC>>>(pUV, qe, pW2TB, bd2, Wd3, bd3, out);
}

// round 12
// speedup vs baseline: 1.5140x; 1.0271x over previous
#include <cuda_runtime.h>
#include <cuda_bf16.h>
#include <math.h>
#include <stdint.h>

#define N_NODES 100000
#define N_EDGES 1600000
#define N_QUERY 500000
#define F_IN 7
#define HID 128
#define EMB 64

// ---------------- scratch (device globals) ----------------
__device__ float g_dinv[N_NODES];
__device__ int   g_cnt[N_NODES];
__device__ int   g_off[N_NODES + 1];
__device__ int   g_cur[N_NODES];
__device__ int   g_srcn[N_EDGES];
__device__ __nv_bfloat16 g_xs8[(size_t)N_NODES * 8];     // bf16 x*dinv padded to 8
__device__ float g_xagg[(size_t)N_NODES * 8];            // 7-dim aggregated input
__device__ __nv_bfloat16 g_hsb[(size_t)N_NODES * HID];   // bf16 message buffer (layer 2)
__device__ __nv_bfloat16 g_hb2[(size_t)N_NODES * HID];   // bf16 aggregated activations
__device__ __nv_bfloat16 g_uvb[(size_t)N_NODES * 256];   // bf16 [U(128)+b1' | V(128)]
__device__ float g_wd1p[64 * 256];                       // packed [Wd1_top | Wd1_bot] fp32
__device__ float g_bc[256];                              // [bd1 | 0]
__device__ __nv_bfloat16 g_w2tb[64 * 128];               // Wd2^T [n][k] bf16
__device__ __nv_bfloat16 g_wl2t[128 * 128];              // W2^T  [n][k] bf16
__device__ __nv_bfloat16 g_wcombt[256 * 128];            // (Wfc@Wd1p)^T [n][k] bf16
__device__ float g_bcomb[256];                           // bfc @ Wd1p + bc

// ---------------- CSR build ----------------
__global__ void k_cnt(const int* __restrict__ ei) {
    int e = blockIdx.x * blockDim.x + threadIdx.x;
    if (e < N_EDGES) atomicAdd(&g_cnt[ei[N_EDGES + e]], 1);
}

// scan + dinv fused
__global__ __launch_bounds__(1024) void k_scan() {
    __shared__ int ssum[1024];
    const int tid = threadIdx.x;
    const int CHUNK = (N_NODES + 1023) / 1024;
    int lo = tid * CHUNK;
    int hi = min(lo + CHUNK, N_NODES);
    int sum = 0;
    for (int i = lo; i < hi; i++) sum += g_cnt[i];
    ssum[tid] = sum;
    __syncthreads();
    for (int off = 1; off < 1024; off <<= 1) {
        int t = (tid >= off) ? ssum[tid - off] : 0;
        __syncthreads();
        if (tid >= off) ssum[tid] += t;
        __syncthreads();
    }
    int run = ssum[tid] - sum;
    for (int i = lo; i < hi; i++) {
        int c = g_cnt[i];
        g_off[i] = run;
        g_cur[i] = run;
        g_dinv[i] = rsqrtf((float)c + 1.0f);
        run += c;
    }
    if (lo < N_NODES && hi == N_NODES) g_off[N_NODES] = run;
}

__global__ void k_fill(const int* __restrict__ ei) {
    int e = blockIdx.x * blockDim.x + threadIdx.x;
    if (e >= N_EDGES) return;
    int s = ei[e];
    int d = ei[N_EDGES + e];
    int pos = atomicAdd(&g_cur[d], 1);
    g_srcn[pos] = s;
}

// ---------------- pack weights ----------------
__global__ void k_pack(const float* __restrict__ Wd1, const float* __restrict__ bd1,
                       const float* __restrict__ Wd2, const float* __restrict__ W2) {
    int idx = blockIdx.x * blockDim.x + threadIdx.x;
    if (idx < 64 * 256) {
        int k = idx >> 8, j = idx & 255;
        g_wd1p[idx] = (j < 128) ? Wd1[k * 128 + j] : Wd1[(64 + k) * 128 + (j - 128)];
    }
    if (idx < 256) g_bc[idx] = (idx < 128) ? bd1[idx] : 0.f;
    if (idx < 64 * 128) {
        int n = idx >> 7, k = idx & 127;
        g_w2tb[idx] = __float2bfloat16(Wd2[k * 64 + n]);
    }
    if (idx < 128 * 128) {
        int n = idx >> 7, k = idx & 127;
        g_wl2t[idx] = __float2bfloat16(W2[k * 128 + n]);
    }
}

// ---------------- combine fc into UV weights (transposed bf16 out) ----------------
__global__ void k_wcomb(const float* __restrict__ Wfc, const float* __restrict__ bfc) {
    __shared__ float s[64];
    int b = blockIdx.x;
    int c = threadIdx.x;  // 256
    if (b < 128) {
        if (c < 64) s[c] = Wfc[b * 64 + c];
        __syncthreads();
        float acc = 0.f;
#pragma unroll 8
        for (int j = 0; j < 64; j++) acc = fmaf(s[j], g_wd1p[j * 256 + c], acc);
        g_wcombt[c * 128 + b] = __float2bfloat16(acc);
    } else {
        if (c < 64) s[c] = bfc[c];
        __syncthreads();
        float acc = g_bc[c];
#pragma unroll 8
        for (int j = 0; j < 64; j++) acc = fmaf(s[j], g_wd1p[j * 256 + c], acc);
        g_bcomb[c] = acc;
    }
}

// ---------------- prep: xs8[n] = bf16(x[n] * dinv[n]) padded to 8 ----------------
__global__ void k_prep(const float* __restrict__ x) {
    int n = blockIdx.x * blockDim.x + threadIdx.x;
    if (n >= N_NODES) return;
    float dv = g_dinv[n];
    float v[8];
#pragma unroll
    for (int k = 0; k < F_IN; k++) v[k] = x[n * F_IN + k] * dv;
    v[7] = 0.f;
    __nv_bfloat162 p0 = __floats2bfloat162_rn(v[0], v[1]);
    __nv_bfloat162 p1 = __floats2bfloat162_rn(v[2], v[3]);
    __nv_bfloat162 p2 = __floats2bfloat162_rn(v[4], v[5]);
    __nv_bfloat162 p3 = __floats2bfloat162_rn(v[6], v[7]);
    uint4 o;
    o.x = *(uint32_t*)&p0; o.y = *(uint32_t*)&p1;
    o.z = *(uint32_t*)&p2; o.w = *(uint32_t*)&p3;
    ((uint4*)g_xs8)[n] = o;
}

// ---------------- layer-1 aggregation in 7-dim input space ----------------
// warp per node; lane per edge (16-B uint4 loads); butterfly reduce 8 floats.
__global__ __launch_bounds__(256) void k_aggx() {
    int t = blockIdx.x * blockDim.x + threadIdx.x;
    int node = t >> 5, lane = t & 31;
    if (node >= N_NODES) return;
    const uint4* xs = (const uint4*)g_xs8;

    float a0 = 0.f, a1 = 0.f, a2 = 0.f, a3 = 0.f, a4 = 0.f, a5 = 0.f, a6 = 0.f, a7 = 0.f;
#define ACC_ADD(vv) do { \
        float2 f0 = __bfloat1622float2(*(__nv_bfloat162*)&(vv).x); \
        float2 f1 = __bfloat1622float2(*(__nv_bfloat162*)&(vv).y); \
        float2 f2 = __bfloat1622float2(*(__nv_bfloat162*)&(vv).z); \
        float2 f3 = __bfloat1622float2(*(__nv_bfloat162*)&(vv).w); \
        a0 += f0.x; a1 += f0.y; a2 += f1.x; a3 += f1.y; \
        a4 += f2.x; a5 += f2.y; a6 += f3.x; a7 += f3.y; } while (0)

    if (lane == 0) {  // self contribution
        uint4 v = xs[node];
        ACC_ADD(v);
    }
    const int end = g_off[node + 1];
    for (int e = g_off[node] + lane; e < end; e += 32) {
        uint4 v = xs[g_srcn[e]];
        ACC_ADD(v);
    }
#undef ACC_ADD
#pragma unroll
    for (int off = 16; off > 0; off >>= 1) {
        a0 += __shfl_xor_sync(0xffffffffu, a0, off);
        a1 += __shfl_xor_sync(0xffffffffu, a1, off);
        a2 += __shfl_xor_sync(0xffffffffu, a2, off);
        a3 += __shfl_xor_sync(0xffffffffu, a3, off);
        a4 += __shfl_xor_sync(0xffffffffu, a4, off);
        a5 += __shfl_xor_sync(0xffffffffu, a5, off);
        a6 += __shfl_xor_sync(0xffffffffu, a6, off);
        a7 += __shfl_xor_sync(0xffffffffu, a7, off);
    }
    if (lane == 0) {
        *(float4*)&g_xagg[(size_t)node * 8]     = make_float4(a0, a1, a2, a3);
        *(float4*)&g_xagg[(size_t)node * 8 + 4] = make_float4(a4, a5, a6, a7);
    }
}

// ---------------- layer-1 GEMM: h1' = bf16(relu(dinv * (xagg @ W1) + b1)) ---------------
// warp per node, lane computes 4 output cols. [100k,7] @ [7,128].
__global__ __launch_bounds__(256) void k_gemm1(const float* __restrict__ W1,
                                               const float* __restrict__ b1,
                                               __nv_bfloat16* __restrict__ out) {
    __shared__ float sW[F_IN * HID];
    const int tid = threadIdx.x;
    for (int i = tid; i < F_IN * HID; i += 256) sW[i] = W1[i];
    __syncthreads();
    int node = blockIdx.x * 8 + (tid >> 5);
    if (node >= N_NODES) return;
    const int lane = tid & 31;
    float v = (lane < 8) ? g_xagg[(size_t)node * 8 + lane] : 0.f;
    float xk[F_IN];
#pragma unroll
    for (int k = 0; k < F_IN; k++) xk[k] = __shfl_sync(0xffffffffu, v, k);
    const int j = lane * 4;
    float4 acc = make_float4(0.f, 0.f, 0.f, 0.f);
#pragma unroll
    for (int k = 0; k < F_IN; k++) {
        const float* w = &sW[k * HID + j];
        acc.x = fmaf(xk[k], w[0], acc.x);
        acc.y = fmaf(xk[k], w[1], acc.y);
        acc.z = fmaf(xk[k], w[2], acc.z);
        acc.w = fmaf(xk[k], w[3], acc.w);
    }
    float dv = g_dinv[node];
    float4 bb = *(const float4*)&b1[j];
    float r0 = fmaxf(fmaf(acc.x, dv, bb.x), 0.f);
    float r1 = fmaxf(fmaf(acc.y, dv, bb.y), 0.f);
    float r2 = fmaxf(fmaf(acc.z, dv, bb.z), 0.f);
    float r3 = fmaxf(fmaf(acc.w, dv, bb.w), 0.f);
    __nv_bfloat162 p0 = __floats2bfloat162_rn(r0, r1);
    __nv_bfloat162 p1 = __floats2bfloat162_rn(r2, r3);
    uint2 o;
    o.x = *(uint32_t*)&p0;
    o.y = *(uint32_t*)&p1;
    *(uint2*)&out[(size_t)node * HID + j] = o;
}

// ---------------- fused CSR aggregation (layer 2): out = bf16(relu(dinv*(sum+self)+b)) --
__global__ __launch_bounds__(256) void k_agg(const __nv_bfloat16* __restrict__ hs,
                                             const float* __restrict__ bias,
                                             __nv_bfloat16* __restrict__ out) {
    int t = blockIdx.x * blockDim.x + threadIdx.x;
    int node = t >> 5, lane = t & 31;
    if (node >= N_NODES) return;
    const int half = lane >> 4;
    const int cl = lane & 15;
    const uint4* h4 = (const uint4*)hs;

    float a0 = 0.f, a1 = 0.f, a2 = 0.f, a3 = 0.f, a4 = 0.f, a5 = 0.f, a6 = 0.f, a7 = 0.f;
#define ACC_ADD(vv) do { \
        float2 f0 = __bfloat1622float2(*(__nv_bfloat162*)&(vv).x); \
        float2 f1 = __bfloat1622float2(*(__nv_bfloat162*)&(vv).y); \
        float2 f2 = __bfloat1622float2(*(__nv_bfloat162*)&(vv).z); \
        float2 f3 = __bfloat1622float2(*(__nv_bfloat162*)&(vv).w); \
        a0 += f0.x; a1 += f0.y; a2 += f1.x; a3 += f1.y; \
        a4 += f2.x; a5 += f2.y; a6 += f3.x; a7 += f3.y; } while (0)

    if (half == 0) {
        uint4 v = h4[(size_t)node * 16 + cl];
        ACC_ADD(v);
    }
    int e = g_off[node] + half;
    const int end = g_off[node + 1];
    for (; e + 6 < end; e += 8) {
        int s0 = g_srcn[e], s1 = g_srcn[e + 2], s2 = g_srcn[e + 4], s3 = g_srcn[e + 6];
        uint4 v0 = h4[(size_t)s0 * 16 + cl];
        uint4 v1 = h4[(size_t)s1 * 16 + cl];
        uint4 v2 = h4[(size_t)s2 * 16 + cl];
        uint4 v3 = h4[(size_t)s3 * 16 + cl];
        ACC_ADD(v0); ACC_ADD(v1); ACC_ADD(v2); ACC_ADD(v3);
    }
    for (; e < end; e += 2) {
        uint4 v = h4[(size_t)g_srcn[e] * 16 + cl];
        ACC_ADD(v);
    }
#undef ACC_ADD
    a0 += __shfl_xor_sync(0xffffffffu, a0, 16);
    a1 += __shfl_xor_sync(0xffffffffu, a1, 16);
    a2 += __shfl_xor_sync(0xffffffffu, a2, 16);
    a3 += __shfl_xor_sync(0xffffffffu, a3, 16);
    a4 += __shfl_xor_sync(0xffffffffu, a4, 16);
    a5 += __shfl_xor_sync(0xffffffffu, a5, 16);
    a6 += __shfl_xor_sync(0xffffffffu, a6, 16);
    a7 += __shfl_xor_sync(0xffffffffu, a7, 16);

    if (half == 0) {
        float dv = g_dinv[node];
        float4 bl = ((const float4*)bias)[cl * 2];
        float4 bh = ((const float4*)bias)[cl * 2 + 1];
        float r0 = fmaxf(fmaf(a0, dv, bl.x), 0.f);
        float r1 = fmaxf(fmaf(a1, dv, bl.y), 0.f);
        float r2 = fmaxf(fmaf(a2, dv, bl.z), 0.f);
        float r3 = fmaxf(fmaf(a3, dv, bl.w), 0.f);
        float r4 = fmaxf(fmaf(a4, dv, bh.x), 0.f);
        float r5 = fmaxf(fmaf(a5, dv, bh.y), 0.f);
        float r6 = fmaxf(fmaf(a6, dv, bh.z), 0.f);
        float r7 = fmaxf(fmaf(a7, dv, bh.w), 0.f);
        __nv_bfloat162 p0 = __floats2bfloat162_rn(r0, r1);
        __nv_bfloat162 p1 = __floats2bfloat162_rn(r2, r3);
        __nv_bfloat162 p2 = __floats2bfloat162_rn(r4, r5);
        __nv_bfloat162 p3 = __floats2bfloat162_rn(r6, r7);
        uint4 o;
        o.x = *(uint32_t*)&p0; o.y = *(uint32_t*)&p1;
        o.z = *(uint32_t*)&p2; o.w = *(uint32_t*)&p3;
        ((uint4*)out)[(size_t)node * 16 + cl] = o;
    }
}

// ---------------- bf16 tensor-core node GEMM: C[M,NT] = A[M,128] @ Bt^T ----------------
template <int NT, int EPI>
__global__ __launch_bounds__(256) void gemm_bf16(const __nv_bfloat16* __restrict__ A,
                                                 const __nv_bfloat16* __restrict__ Bt,
                                                 const float* __restrict__ bias,
                                                 __nv_bfloat16* __restrict__ C) {
    constexpr int KD = 128;
    constexpr int KP = KD + 8;
    extern __shared__ char smraw[];
    __nv_bfloat16* s_a = (__nv_bfloat16*)smraw;
    __nv_bfloat16* s_b = (__nv_bfloat16*)(smraw + 128 * KP * 2);
    const int tid = threadIdx.x;
    const int row0 = blockIdx.x * 128;

    for (int i = tid; i < NT * (KD / 4); i += 256) {
        int n = i >> 5, k4 = i & 31;
        *(uint2*)&s_b[n * KP + k4 * 4] = ((const uint2*)Bt)[i];
    }
    for (int i = tid; i < 128 * (KD / 4); i += 256) {
        int r = i >> 5, k4 = i & 31;
        int gr = row0 + r;
        if (gr >= N_NODES) gr = N_NODES - 1;
        *(uint2*)&s_a[r * KP + k4 * 4] = *(const uint2*)&A[(size_t)gr * KD + k4 * 4];
    }
    __syncthreads();

    const int lane = tid & 31, warp = tid >> 5;
    const int q0 = warp * 16;
    const int gid = lane >> 2, tig = lane & 3;
    constexpr int NCHUNK = (NT > 128) ? 2 : 1;
    constexpr int NC = NT / NCHUNK;
    constexpr int NTILES = NC / 8;

    const int qa = row0 + q0 + gid, qb = qa + 8;
    float dva = 1.f, dvb = 1.f;
    if (EPI == 0) {
        dva = (qa < N_NODES) ? g_dinv[qa] : 0.f;
        dvb = (qb < N_NODES) ? g_dinv[qb] : 0.f;
    }

    for (int nc = 0; nc < NCHUNK; nc++) {
        float acc[NTILES][4];
#pragma unroll
        for (int t = 0; t < NTILES; t++)
#pragma unroll
            for (int j = 0; j < 4; j++) acc[t][j] = 0.f;

#pragma unroll
        for (int k0 = 0; k0 < KD; k0 += 16) {
            uint32_t a0 = *(const uint32_t*)&s_a[(q0 + gid) * KP + k0 + 2 * tig];
            uint32_t a1 = *(const uint32_t*)&s_a[(q0 + gid + 8) * KP + k0 + 2 * tig];
            uint32_t a2 = *(const uint32_t*)&s_a[(q0 + gid) * KP + k0 + 2 * tig + 8];
            uint32_t a3 = *(const uint32_t*)&s_a[(q0 + gid + 8) * KP + k0 + 2 * tig + 8];
#pragma unroll
            for (int t = 0; t < NTILES; t++) {
                int n = nc * NC + t * 8 + gid;
                uint32_t b0 = *(const uint32_t*)&s_b[n * KP + k0 + 2 * tig];
                uint32_t b1 = *(const uint32_t*)&s_b[n * KP + k0 + 2 * tig + 8];
                asm volatile(
                    "mma.sync.aligned.m16n8k16.row.col.f32.bf16.bf16.f32 "
                    "{%0,%1,%2,%3}, {%4,%5,%6,%7}, {%8,%9}, {%0,%1,%2,%3};"
                    : "+f"(acc[t][0]), "+f"(acc[t][1]), "+f"(acc[t][2]), "+f"(acc[t][3])
                    : "r"(a0), "r"(a1), "r"(a2), "r"(a3), "r"(b0), "r"(b1));
            }
        }
#pragma unroll
        for (int t = 0; t < NTILES; t++) {
            int c = nc * NC + t * 8 + 2 * tig;
            float r0, r1, r2, r3;
            if (EPI == 0) {
                r0 = acc[t][0] * dva; r1 = acc[t][1] * dva;
                r2 = acc[t][2] * dvb; r3 = acc[t][3] * dvb;
            } else {
                float b0 = bias[c], b1 = bias[c + 1];
                r0 = acc[t][0] + b0; r1 = acc[t][1] + b1;
                r2 = acc[t][2] + b0; r3 = acc[t][3] + b1;
            }
            __nv_bfloat162 pa = __floats2bfloat162_rn(r0, r1);
            __nv_bfloat162 pb = __floats2bfloat162_rn(r2, r3);
            if (qa < N_NODES) *(__nv_bfloat162*)&C[(size_t)qa * NT + c] = pa;
            if (qb < N_NODES) *(__nv_bfloat162*)&C[(size_t)qb * NT + c] = pb;
        }
    }
}

// ---------------- decoder: 128 q/block; bf16 mma stage 2; stage 3 fused via shfl --------
__global__ __launch_bounds__(256) void k_decoder(
    const __nv_bfloat16* __restrict__ uv, const int* __restrict__ qe,
    const __nv_bfloat16* __restrict__ w2t, const float* __restrict__ bd2,
    const float* __restrict__ Wd3, const float* __restrict__ bd3,
    float* __restrict__ out) {
    extern __shared__ char smraw[];
    __nv_bfloat16* s_d = (__nv_bfloat16*)smraw;              // [128][136]
    __nv_bfloat16* s_w = (__nv_bfloat16*)(smraw + 34816);    // [64][136]
    __shared__ int s_a[128], s_b[128];
    __shared__ float s_b2[EMB], s_w3[EMB];

    const int tid = threadIdx.x;
    const int q0blk = blockIdx.x * 128;

    for (int i = tid; i < 64 * 32; i += 256) {
        int n = i >> 5, k4 = i & 31;
        *(uint2*)&s_w[n * 136 + k4 * 4] = ((const uint2*)w2t)[i];
    }
    if (tid < EMB) { s_b2[tid] = bd2[tid]; s_w3[tid] = Wd3[tid]; }
    if (tid < 128) {
        int qi = q0blk + tid;
        s_a[tid] = qi < N_QUERY ? qe[qi] : 0;
        s_b[tid] = qi < N_QUERY ? qe[N_QUERY + qi] : 0;
    }
    __syncthreads();

    const uint2* uv2 = (const uint2*)uv;
    for (int i = tid; i < 128 * 32; i += 256) {
        int q = i >> 5, c = i & 31;
        uint2 uu = uv2[(size_t)s_a[q] * 64 + c];
        uint2 vv = uv2[(size_t)s_b[q] * 64 + 32 + c];
        float2 u0 = __bfloat1622float2(*(__nv_bfloat162*)&uu.x);
        float2 u1 = __bfloat1622float2(*(__nv_bfloat162*)&uu.y);
        float2 v0 = __bfloat1622float2(*(__nv_bfloat162*)&vv.x);
        float2 v1 = __bfloat1622float2(*(__nv_bfloat162*)&vv.y);
        __nv_bfloat162 p0 = __floats2bfloat162_rn(fmaxf(u0.x + v0.x, 0.f), fmaxf(u0.y + v0.y, 0.f));
        __nv_bfloat162 p1 = __floats2bfloat162_rn(fmaxf(u1.x + v1.x, 0.f), fmaxf(u1.y + v1.y, 0.f));
        uint2 o;
        o.x = *(uint32_t*)&p0;
        o.y = *(uint32_t*)&p1;
        *(uint2*)&s_d[q * 136 + c * 4] = o;
    }
    __syncthreads();

    {
        const int lane = tid & 31, warp = tid >> 5;
        const int q0 = warp * 16;
        const int gid = lane >> 2, tig = lane & 3;
        float acc[8][4];
#pragma unroll
        for (int t = 0; t < 8; t++)
#pragma unroll
            for (int j = 0; j < 4; j++) acc[t][j] = 0.f;

#pragma unroll
        for (int k0 = 0; k0 < 128; k0 += 16) {
            uint32_t a0 = *(const uint32_t*)&s_d[(q0 + gid) * 136 + k0 + 2 * tig];
            uint32_t a1 = *(const uint32_t*)&s_d[(q0 + gid + 8) * 136 + k0 + 2 * tig];
            uint32_t a2 = *(const uint32_t*)&s_d[(q0 + gid) * 136 + k0 + 2 * tig + 8];
            uint32_t a3 = *(const uint32_t*)&s_d[(q0 + gid + 8) * 136 + k0 + 2 * tig + 8];
#pragma unroll
            for (int t = 0; t < 8; t++) {
                int n = t * 8 + gid;
                uint32_t b0 = *(const uint32_t*)&s_w[n * 136 + k0 + 2 * tig];
                uint32_t b1 = *(const uint32_t*)&s_w[n * 136 + k0 + 2 * tig + 8];
                asm volatile(
                    "mma.sync.aligned.m16n8k16.row.col.f32.bf16.bf16.f32 "
                    "{%0,%1,%2,%3}, {%4,%5,%6,%7}, {%8,%9}, {%0,%1,%2,%3};"
                    : "+f"(acc[t][0]), "+f"(acc[t][1]), "+f"(acc[t][2]), "+f"(acc[t][3])
                    : "r"(a0), "r"(a1), "r"(a2), "r"(a3), "r"(b0), "r"(b1));
            }
        }
        float pa = 0.f, pb = 0.f;
#pragma unroll
        for (int t = 0; t < 8; t++) {
            int c = t * 8 + 2 * tig;
            float bb0 = s_b2[c], bb1 = s_b2[c + 1];
            float w0 = s_w3[c], w1 = s_w3[c + 1];
            pa = fmaf(fmaxf(acc[t][0] + bb0, 0.f), w0, pa);
            pa = fmaf(fmaxf(acc[t][1] + bb1, 0.f), w1, pa);
            pb = fmaf(fmaxf(acc[t][2] + bb0, 0.f), w0, pb);
            pb = fmaf(fmaxf(acc[t][3] + bb1, 0.f), w1, pb);
        }
        pa += __shfl_xor_sync(0xffffffffu, pa, 1);
        pa += __shfl_xor_sync(0xffffffffu, pa, 2);
        pb += __shfl_xor_sync(0xffffffffu, pb, 1);
        pb += __shfl_xor_sync(0xffffffffu, pb, 2);
        if (tig == 0) {
            float b3 = bd3[0];
            int qi_a = q0blk + q0 + gid;
            int qi_b = qi_a + 8;
            if (qi_a < N_QUERY) out[qi_a] = 1.0f / (1.0f + expf(-(pa + b3)));
            if (qi_b < N_QUERY) out[qi_b] = 1.0f / (1.0f + expf(-(pb + b3)));
        }
    }
}

// ---------------- launch ----------------
extern "C" void kernel_launch(void* const* d_in, const int* in_sizes, int n_in,
                              void* d_out, int out_size) {
    const float* x   = (const float*)d_in[0];
    const int* ei    = (const int*)d_in[1];
    const int* qe    = (const int*)d_in[2];
    const float* W1  = (const float*)d_in[3];
    const float* b1  = (const float*)d_in[4];
    const float* W2  = (const float*)d_in[5];
    const float* b2  = (const float*)d_in[6];
    const float* Wfc = (const float*)d_in[7];
    const float* bfc = (const float*)d_in[8];
    const float* Wd1 = (const float*)d_in[9];
    const float* bd1 = (const float*)d_in[10];
    const float* Wd2 = (const float*)d_in[11];
    const float* bd2 = (const float*)d_in[12];
    const float* Wd3 = (const float*)d_in[13];
    const float* bd3 = (const float*)d_in[14];
    float* out = (float*)d_out;

    float* pBC2;
    __nv_bfloat16 *pHS, *pH2, *pUV, *pW2TB, *pWL2T, *pWCT;
    int* pCnt;
    { void* p; cudaGetSymbolAddress(&p, g_hsb);    pHS = (__nv_bfloat16*)p; }
    { void* p; cudaGetSymbolAddress(&p, g_hb2);    pH2 = (__nv_bfloat16*)p; }
    { void* p; cudaGetSymbolAddress(&p, g_uvb);    pUV = (__nv_bfloat16*)p; }
    { void* p; cudaGetSymbolAddress(&p, g_w2tb);   pW2TB = (__nv_bfloat16*)p; }
    { void* p; cudaGetSymbolAddress(&p, g_wl2t);   pWL2T = (__nv_bfloat16*)p; }
    { void* p; cudaGetSymbolAddress(&p, g_wcombt); pWCT = (__nv_bfloat16*)p; }
    { void* p; cudaGetSymbolAddress(&p, g_bcomb);  pBC2 = (float*)p; }
    { void* p; cudaGetSymbolAddress(&p, g_cnt);    pCnt = (int*)p; }

    const int SM_L2   = (128 * 136 + 128 * 136) * 2;  // 69632
    const int SM_COMB = (128 * 136 + 256 * 136) * 2;  // 104448
    const int SM_DEC  = 34816 + 17408;                // 52224
    cudaFuncSetAttribute(gemm_bf16<128, 0>, cudaFuncAttributeMaxDynamicSharedMemorySize, SM_L2);
    cudaFuncSetAttribute(gemm_bf16<256, 1>, cudaFuncAttributeMaxDynamicSharedMemorySize, SM_COMB);
    cudaFuncSetAttribute(k_decoder, cudaFuncAttributeMaxDynamicSharedMemorySize, SM_DEC);

    const int NBLK = (N_NODES + 127) / 128;

    // CSR build + weight packing
    cudaMemsetAsync(pCnt, 0, N_NODES * sizeof(int));
    k_cnt<<<(N_EDGES + 255) / 256, 256>>>(ei);
    k_scan<<<1, 1024>>>();
    k_fill<<<(N_EDGES + 255) / 256, 256>>>(ei);
    k_pack<<<64, 256>>>(Wd1, bd1, Wd2, W2);
    k_wcomb<<<129, 256>>>(Wfc, bfc);

    // layer 1 in input space: prep -> 7-dim agg -> tiny GEMM -> h1'(bf16)
    k_prep<<<(N_NODES + 255) / 256, 256>>>(x);
    k_aggx<<<(N_NODES * 32 + 255) / 256, 256>>>();
    k_gemm1<<<(N_NODES + 7) / 8, 256>>>(W1, b1, pH2);

    // layer 2: hs2 = bf16((h1'@W2)*dinv) -> agg -> h2'(bf16)
    gemm_bf16<128, 0><<<NBLK, 256, SM_L2>>>(pH2, pWL2T, nullptr, pHS);
    k_agg<<<(N_NODES * 32 + 255) / 256, 256>>>(pHS, b2, pH2);

    // fused fc+UV: UV = bf16(h2' @ Wcomb + bcomb)
    gemm_bf16<256, 1><<<NBLK, 256, SM_COMB>>>(pH2, pWCT, pBC2, pUV);

    // decoder
    k_decoder<<<(N_QUERY + 127) / 128, 256, SM_DEC>>>(pUV, qe, pW2TB, bd2, Wd3, bd3, out);
}

// round 13
// speedup vs baseline: 2.7217x; 1.7976x over previous
#include <cuda_runtime.h>
#include <cuda_bf16.h>
#include <math.h>
#include <stdint.h>

#define N_NODES 100000
#define N_EDGES 1600000
#define N_QUERY 500000
#define F_IN 7
#define HID 128
#define EMB 64
#define NSCAN_BLK 391

// ---------------- scratch (device globals) ----------------
__device__ float g_dinv[N_NODES];
__device__ int   g_cnt[N_NODES];
__device__ int   g_off[N_NODES + 1];
__device__ int   g_cur[N_NODES];
__device__ int   g_srcn[N_EDGES];
__device__ int   g_bsum[512];
__device__ __nv_bfloat16 g_xs8[(size_t)N_NODES * 8];     // bf16 x*dinv padded to 8
__device__ float g_xagg[(size_t)N_NODES * 8];            // 7-dim aggregated input
__device__ __nv_bfloat16 g_hsb[(size_t)N_NODES * HID];   // bf16 message buffer (layer 2)
__device__ __nv_bfloat16 g_hb2[(size_t)N_NODES * HID];   // bf16 aggregated activations
__device__ __nv_bfloat16 g_uvb[(size_t)N_NODES * 256];   // bf16 [U(128)+b1' | V(128)]
__device__ float g_wd1p[64 * 256];                       // packed [Wd1_top | Wd1_bot] fp32
__device__ float g_bc[256];                              // [bd1 | 0]
__device__ __nv_bfloat16 g_w2tb[64 * 128];               // Wd2^T [n][k] bf16
__device__ __nv_bfloat16 g_wl2t[128 * 128];              // W2^T  [n][k] bf16
__device__ __nv_bfloat16 g_wcombt[256 * 128];            // (Wfc@Wd1p)^T [n][k] bf16
__device__ float g_bcomb[256];                           // bfc @ Wd1p + bc

// ---------------- CSR build ----------------
__global__ void k_cnt(const int* __restrict__ ei) {
    int e = blockIdx.x * blockDim.x + threadIdx.x;
    if (e < N_EDGES) atomicAdd(&g_cnt[ei[N_EDGES + e]], 1);
}

// phase A: per-block sums of 256 counts
__global__ __launch_bounds__(256) void k_scanA() {
    __shared__ int s[256];
    int i = blockIdx.x * 256 + threadIdx.x;
    int c = (i < N_NODES) ? g_cnt[i] : 0;
    s[threadIdx.x] = c;
    __syncthreads();
#pragma unroll
    for (int off = 128; off > 0; off >>= 1) {
        if (threadIdx.x < off) s[threadIdx.x] += s[threadIdx.x + off];
        __syncthreads();
    }
    if (threadIdx.x == 0) g_bsum[blockIdx.x] = s[0];
}

// phase B: exclusive scan of NSCAN_BLK block sums (1 block, 512 threads)
__global__ __launch_bounds__(512) void k_scanB() {
    __shared__ int s[512];
    int tid = threadIdx.x;
    int v = (tid < NSCAN_BLK) ? g_bsum[tid] : 0;
    s[tid] = v;
    __syncthreads();
#pragma unroll
    for (int off = 1; off < 512; off <<= 1) {
        int t = (tid >= off) ? s[tid - off] : 0;
        __syncthreads();
        s[tid] += t;
        __syncthreads();
    }
    if (tid < NSCAN_BLK) g_bsum[tid] = s[tid] - v;  // exclusive
    if (tid == 0) g_off[N_NODES] = N_EDGES;
}

// phase C: per-block exclusive scan + write off/cur/dinv
__global__ __launch_bounds__(256) void k_scanC() {
    __shared__ int s[256];
    int tid = threadIdx.x;
    int i = blockIdx.x * 256 + tid;
    int c = (i < N_NODES) ? g_cnt[i] : 0;
    s[tid] = c;
    __syncthreads();
#pragma unroll
    for (int off = 1; off < 256; off <<= 1) {
        int t = (tid >= off) ? s[tid - off] : 0;
        __syncthreads();
        s[tid] += t;
        __syncthreads();
    }
    if (i < N_NODES) {
        int off = g_bsum[blockIdx.x] + s[tid] - c;  // exclusive prefix
        g_off[i] = off;
        g_cur[i] = off;
        g_dinv[i] = rsqrtf((float)c + 1.0f);
    }
}

__global__ void k_fill(const int* __restrict__ ei) {
    int e = blockIdx.x * blockDim.x + threadIdx.x;
    if (e >= N_EDGES) return;
    int s = ei[e];
    int d = ei[N_EDGES + e];
    int pos = atomicAdd(&g_cur[d], 1);
    g_srcn[pos] = s;
}

// ---------------- pack weights ----------------
__global__ void k_pack(const float* __restrict__ Wd1, const float* __restrict__ bd1,
                       const float* __restrict__ Wd2, const float* __restrict__ W2) {
    int idx = blockIdx.x * blockDim.x + threadIdx.x;
    if (idx < 64 * 256) {
        int k = idx >> 8, j = idx & 255;
        g_wd1p[idx] = (j < 128) ? Wd1[k * 128 + j] : Wd1[(64 + k) * 128 + (j - 128)];
    }
    if (idx < 256) g_bc[idx] = (idx < 128) ? bd1[idx] : 0.f;
    if (idx < 64 * 128) {
        int n = idx >> 7, k = idx & 127;
        g_w2tb[idx] = __float2bfloat16(Wd2[k * 64 + n]);
    }
    if (idx < 128 * 128) {
        int n = idx >> 7, k = idx & 127;
        g_wl2t[idx] = __float2bfloat16(W2[k * 128 + n]);
    }
}

// ---------------- combine fc into UV weights (transposed bf16 out) ----------------
__global__ void k_wcomb(const float* __restrict__ Wfc, const float* __restrict__ bfc) {
    __shared__ float s[64];
    int b = blockIdx.x;
    int c = threadIdx.x;  // 256
    if (b < 128) {
        if (c < 64) s[c] = Wfc[b * 64 + c];
        __syncthreads();
        float acc = 0.f;
#pragma unroll 8
        for (int j = 0; j < 64; j++) acc = fmaf(s[j], g_wd1p[j * 256 + c], acc);
        g_wcombt[c * 128 + b] = __float2bfloat16(acc);
    } else {
        if (c < 64) s[c] = bfc[c];
        __syncthreads();
        float acc = g_bc[c];
#pragma unroll 8
        for (int j = 0; j < 64; j++) acc = fmaf(s[j], g_wd1p[j * 256 + c], acc);
        g_bcomb[c] = acc;
    }
}

// ---------------- prep: xs8[n] = bf16(x[n] * dinv[n]) padded to 8 ----------------
__global__ void k_prep(const float* __restrict__ x) {
    int n = blockIdx.x * blockDim.x + threadIdx.x;
    if (n >= N_NODES) return;
    float dv = g_dinv[n];
    float v[8];
#pragma unroll
    for (int k = 0; k < F_IN; k++) v[k] = x[n * F_IN + k] * dv;
    v[7] = 0.f;
    __nv_bfloat162 p0 = __floats2bfloat162_rn(v[0], v[1]);
    __nv_bfloat162 p1 = __floats2bfloat162_rn(v[2], v[3]);
    __nv_bfloat162 p2 = __floats2bfloat162_rn(v[4], v[5]);
    __nv_bfloat162 p3 = __floats2bfloat162_rn(v[6], v[7]);
    uint4 o;
    o.x = *(uint32_t*)&p0; o.y = *(uint32_t*)&p1;
    o.z = *(uint32_t*)&p2; o.w = *(uint32_t*)&p3;
    ((uint4*)g_xs8)[n] = o;
}

// ---------------- layer-1 aggregation in 7-dim input space ----------------
// 8 threads per node; lane-per-edge (uint4 loads); oct butterfly reduce.
__global__ __launch_bounds__(256) void k_aggx() {
    int t = blockIdx.x * blockDim.x + threadIdx.x;
    int node = t >> 3, sub = t & 7;
    if (node >= N_NODES) return;
    const uint4* xs = (const uint4*)g_xs8;

    float a0 = 0.f, a1 = 0.f, a2 = 0.f, a3 = 0.f, a4 = 0.f, a5 = 0.f, a6 = 0.f, a7 = 0.f;
#define ACC_ADD(vv) do { \
        float2 f0 = __bfloat1622float2(*(__nv_bfloat162*)&(vv).x); \
        float2 f1 = __bfloat1622float2(*(__nv_bfloat162*)&(vv).y); \
        float2 f2 = __bfloat1622float2(*(__nv_bfloat162*)&(vv).z); \
        float2 f3 = __bfloat1622float2(*(__nv_bfloat162*)&(vv).w); \
        a0 += f0.x; a1 += f0.y; a2 += f1.x; a3 += f1.y; \
        a4 += f2.x; a5 += f2.y; a6 += f3.x; a7 += f3.y; } while (0)

    if (sub == 0) {  // self contribution
        uint4 v = xs[node];
        ACC_ADD(v);
    }
    const int end = g_off[node + 1];
    for (int e = g_off[node] + sub; e < end; e += 8) {
        uint4 v = xs[g_srcn[e]];
        ACC_ADD(v);
    }
#undef ACC_ADD
#pragma unroll
    for (int off = 4; off > 0; off >>= 1) {
        a0 += __shfl_xor_sync(0xffffffffu, a0, off);
        a1 += __shfl_xor_sync(0xffffffffu, a1, off);
        a2 += __shfl_xor_sync(0xffffffffu, a2, off);
        a3 += __shfl_xor_sync(0xffffffffu, a3, off);
        a4 += __shfl_xor_sync(0xffffffffu, a4, off);
        a5 += __shfl_xor_sync(0xffffffffu, a5, off);
        a6 += __shfl_xor_sync(0xffffffffu, a6, off);
        a7 += __shfl_xor_sync(0xffffffffu, a7, off);
    }
    if (sub == 0) {
        *(float4*)&g_xagg[(size_t)node * 8]     = make_float4(a0, a1, a2, a3);
        *(float4*)&g_xagg[(size_t)node * 8 + 4] = make_float4(a4, a5, a6, a7);
    }
}

// ---------------- layer-1 GEMM: h1' = bf16(relu(dinv * (xagg @ W1) + b1)) ---------------
__global__ __launch_bounds__(256) void k_gemm1(const float* __restrict__ W1,
                                               const float* __restrict__ b1,
                                               __nv_bfloat16* __restrict__ out) {
    __shared__ float sW[F_IN * HID];
    const int tid = threadIdx.x;
    for (int i = tid; i < F_IN * HID; i += 256) sW[i] = W1[i];
    __syncthreads();
    int node = blockIdx.x * 8 + (tid >> 5);
    if (node >= N_NODES) return;
    const int lane = tid & 31;
    float v = (lane < 8) ? g_xagg[(size_t)node * 8 + lane] : 0.f;
    float xk[F_IN];
#pragma unroll
    for (int k = 0; k < F_IN; k++) xk[k] = __shfl_sync(0xffffffffu, v, k);
    const int j = lane * 4;
    float4 acc = make_float4(0.f, 0.f, 0.f, 0.f);
#pragma unroll
    for (int k = 0; k < F_IN; k++) {
        const float* w = &sW[k * HID + j];
        acc.x = fmaf(xk[k], w[0], acc.x);
        acc.y = fmaf(xk[k], w[1], acc.y);
        acc.z = fmaf(xk[k], w[2], acc.z);
        acc.w = fmaf(xk[k], w[3], acc.w);
    }
    float dv = g_dinv[node];
    float4 bb = *(const float4*)&b1[j];
    float r0 = fmaxf(fmaf(acc.x, dv, bb.x), 0.f);
    float r1 = fmaxf(fmaf(acc.y, dv, bb.y), 0.f);
    float r2 = fmaxf(fmaf(acc.z, dv, bb.z), 0.f);
    float r3 = fmaxf(fmaf(acc.w, dv, bb.w), 0.f);
    __nv_bfloat162 p0 = __floats2bfloat162_rn(r0, r1);
    __nv_bfloat162 p1 = __floats2bfloat162_rn(r2, r3);
    uint2 o;
    o.x = *(uint32_t*)&p0;
    o.y = *(uint32_t*)&p1;
    *(uint2*)&out[(size_t)node * HID + j] = o;
}

// ---------------- fused CSR aggregation (layer 2): out = bf16(relu(dinv*(sum+self)+b)) --
__global__ __launch_bounds__(256) void k_agg(const __nv_bfloat16* __restrict__ hs,
                                             const float* __restrict__ bias,
                                             __nv_bfloat16* __restrict__ out) {
    int t = blockIdx.x * blockDim.x + threadIdx.x;
    int node = t >> 5, lane = t & 31;
    if (node >= N_NODES) return;
    const int half = lane >> 4;
    const int cl = lane & 15;
    const uint4* h4 = (const uint4*)hs;

    float a0 = 0.f, a1 = 0.f, a2 = 0.f, a3 = 0.f, a4 = 0.f, a5 = 0.f, a6 = 0.f, a7 = 0.f;
#define ACC_ADD(vv) do { \
        float2 f0 = __bfloat1622float2(*(__nv_bfloat162*)&(vv).x); \
        float2 f1 = __bfloat1622float2(*(__nv_bfloat162*)&(vv).y); \
        float2 f2 = __bfloat1622float2(*(__nv_bfloat162*)&(vv).z); \
        float2 f3 = __bfloat1622float2(*(__nv_bfloat162*)&(vv).w); \
        a0 += f0.x; a1 += f0.y; a2 += f1.x; a3 += f1.y; \
        a4 += f2.x; a5 += f2.y; a6 += f3.x; a7 += f3.y; } while (0)

    if (half == 0) {
        uint4 v = h4[(size_t)node * 16 + cl];
        ACC_ADD(v);
    }
    int e = g_off[node] + half;
    const int end = g_off[node + 1];
    for (; e + 6 < end; e += 8) {
        int s0 = g_srcn[e], s1 = g_srcn[e + 2], s2 = g_srcn[e + 4], s3 = g_srcn[e + 6];
        uint4 v0 = h4[(size_t)s0 * 16 + cl];
        uint4 v1 = h4[(size_t)s1 * 16 + cl];
        uint4 v2 = h4[(size_t)s2 * 16 + cl];
        uint4 v3 = h4[(size_t)s3 * 16 + cl];
        ACC_ADD(v0); ACC_ADD(v1); ACC_ADD(v2); ACC_ADD(v3);
    }
    for (; e < end; e += 2) {
        uint4 v = h4[(size_t)g_srcn[e] * 16 + cl];
        ACC_ADD(v);
    }
#undef ACC_ADD
    a0 += __shfl_xor_sync(0xffffffffu, a0, 16);
    a1 += __shfl_xor_sync(0xffffffffu, a1, 16);
    a2 += __shfl_xor_sync(0xffffffffu, a2, 16);
    a3 += __shfl_xor_sync(0xffffffffu, a3, 16);
    a4 += __shfl_xor_sync(0xffffffffu, a4, 16);
    a5 += __shfl_xor_sync(0xffffffffu, a5, 16);
    a6 += __shfl_xor_sync(0xffffffffu, a6, 16);
    a7 += __shfl_xor_sync(0xffffffffu, a7, 16);

    if (half == 0) {
        float dv = g_dinv[node];
        float4 bl = ((const float4*)bias)[cl * 2];
        float4 bh = ((const float4*)bias)[cl * 2 + 1];
        float r0 = fmaxf(fmaf(a0, dv, bl.x), 0.f);
        float r1 = fmaxf(fmaf(a1, dv, bl.y), 0.f);
        float r2 = fmaxf(fmaf(a2, dv, bl.z), 0.f);
        float r3 = fmaxf(fmaf(a3, dv, bl.w), 0.f);
        float r4 = fmaxf(fmaf(a4, dv, bh.x), 0.f);
        float r5 = fmaxf(fmaf(a5, dv, bh.y), 0.f);
        float r6 = fmaxf(fmaf(a6, dv, bh.z), 0.f);
        float r7 = fmaxf(fmaf(a7, dv, bh.w), 0.f);
        __nv_bfloat162 p0 = __floats2bfloat162_rn(r0, r1);
        __nv_bfloat162 p1 = __floats2bfloat162_rn(r2, r3);
        __nv_bfloat162 p2 = __floats2bfloat162_rn(r4, r5);
        __nv_bfloat162 p3 = __floats2bfloat162_rn(r6, r7);
        uint4 o;
        o.x = *(uint32_t*)&p0; o.y = *(uint32_t*)&p1;
        o.z = *(uint32_t*)&p2; o.w = *(uint32_t*)&p3;
        ((uint4*)out)[(size_t)node * 16 + cl] = o;
    }
}

// ---------------- bf16 tensor-core node GEMM: C[M,NT] = A[M,128] @ Bt^T ----------------
// Chunked B buffer (128 cols at a time) -> 69632 B smem -> 2 blocks/SM for all NT.
template <int NT, int EPI>
__global__ __launch_bounds__(256) void gemm_bf16(const __nv_bfloat16* __restrict__ A,
                                                 const __nv_bfloat16* __restrict__ Bt,
                                                 const float* __restrict__ bias,
                                                 __nv_bfloat16* __restrict__ C) {
    constexpr int KD = 128;
    constexpr int KP = KD + 8;
    extern __shared__ char smraw[];
    __nv_bfloat16* s_a = (__nv_bfloat16*)smraw;                   // [128][KP]
    __nv_bfloat16* s_b = (__nv_bfloat16*)(smraw + 128 * KP * 2);  // [128][KP]
    const int tid = threadIdx.x;
    const int row0 = blockIdx.x * 128;

    for (int i = tid; i < 128 * (KD / 4); i += 256) {
        int r = i >> 5, k4 = i & 31;
        int gr = row0 + r;
        if (gr >= N_NODES) gr = N_NODES - 1;
        *(uint2*)&s_a[r * KP + k4 * 4] = *(const uint2*)&A[(size_t)gr * KD + k4 * 4];
    }

    const int lane = tid & 31, warp = tid >> 5;
    const int q0 = warp * 16;
    const int gid = lane >> 2, tig = lane & 3;
    constexpr int NCHUNK = NT / 128;
    constexpr int NTILES = 16;  // 128 cols / 8

    const int qa = row0 + q0 + gid, qb = qa + 8;
    float dva = 1.f, dvb = 1.f;
    if (EPI == 0) {
        dva = (qa < N_NODES) ? g_dinv[qa] : 0.f;
        dvb = (qb < N_NODES) ? g_dinv[qb] : 0.f;
    }

#pragma unroll
    for (int nc = 0; nc < NCHUNK; nc++) {
        // load B chunk [128 rows of Bt starting at nc*128]
        for (int i = tid; i < 128 * (KD / 4); i += 256) {
            int n = i >> 5, k4 = i & 31;
            *(uint2*)&s_b[n * KP + k4 * 4] =
                *(const uint2*)&Bt[((size_t)(nc * 128 + n)) * KD + k4 * 4];
        }
        __syncthreads();

        float acc[NTILES][4];
#pragma unroll
        for (int t = 0; t < NTILES; t++)
#pragma unroll
            for (int j = 0; j < 4; j++) acc[t][j] = 0.f;

#pragma unroll
        for (int k0 = 0; k0 < KD; k0 += 16) {
            uint32_t a0 = *(const uint32_t*)&s_a[(q0 + gid) * KP + k0 + 2 * tig];
            uint32_t a1 = *(const uint32_t*)&s_a[(q0 + gid + 8) * KP + k0 + 2 * tig];
            uint32_t a2 = *(const uint32_t*)&s_a[(q0 + gid) * KP + k0 + 2 * tig + 8];
            uint32_t a3 = *(const uint32_t*)&s_a[(q0 + gid + 8) * KP + k0 + 2 * tig + 8];
#pragma unroll
            for (int t = 0; t < NTILES; t++) {
                int n = t * 8 + gid;
                uint32_t b0 = *(const uint32_t*)&s_b[n * KP + k0 + 2 * tig];
                uint32_t b1 = *(const uint32_t*)&s_b[n * KP + k0 + 2 * tig + 8];
                asm volatile(
                    "mma.sync.aligned.m16n8k16.row.col.f32.bf16.bf16.f32 "
                    "{%0,%1,%2,%3}, {%4,%5,%6,%7}, {%8,%9}, {%0,%1,%2,%3};"
                    : "+f"(acc[t][0]), "+f"(acc[t][1]), "+f"(acc[t][2]), "+f"(acc[t][3])
                    : "r"(a0), "r"(a1), "r"(a2), "r"(a3), "r"(b0), "r"(b1));
            }
        }
#pragma unroll
        for (int t = 0; t < NTILES; t++) {
            int c = nc * 128 + t * 8 + 2 * tig;
            float r0, r1, r2, r3;
            if (EPI == 0) {
                r0 = acc[t][0] * dva; r1 = acc[t][1] * dva;
                r2 = acc[t][2] * dvb; r3 = acc[t][3] * dvb;
            } else {
                float b0 = bias[c], b1 = bias[c + 1];
                r0 = acc[t][0] + b0; r1 = acc[t][1] + b1;
                r2 = acc[t][2] + b0; r3 = acc[t][3] + b1;
            }
            __nv_bfloat162 pa = __floats2bfloat162_rn(r0, r1);
            __nv_bfloat162 pb = __floats2bfloat162_rn(r2, r3);
            if (qa < N_NODES) *(__nv_bfloat162*)&C[(size_t)qa * NT + c] = pa;
            if (qb < N_NODES) *(__nv_bfloat162*)&C[(size_t)qb * NT + c] = pb;
        }
        if (nc + 1 < NCHUNK) __syncthreads();
    }
}

// ---------------- decoder: 128 q/block; bf16 mma stage 2; stage 3 fused via shfl --------
__global__ __launch_bounds__(256) void k_decoder(
    const __nv_bfloat16* __restrict__ uv, const int* __restrict__ qe,
    const __nv_bfloat16* __restrict__ w2t, const float* __restrict__ bd2,
    const float* __restrict__ Wd3, const float* __restrict__ bd3,
    float* __restrict__ out) {
    extern __shared__ char smraw[];
    __nv_bfloat16* s_d = (__nv_bfloat16*)smraw;              // [128][136]
    __nv_bfloat16* s_w = (__nv_bfloat16*)(smraw + 34816);    // [64][136]
    __shared__ int s_a[128], s_b[128];
    __shared__ float s_b2[EMB], s_w3[EMB];

    const int tid = threadIdx.x;
    const int q0blk = blockIdx.x * 128;

    for (int i = tid; i < 64 * 32; i += 256) {
        int n = i >> 5, k4 = i & 31;
        *(uint2*)&s_w[n * 136 + k4 * 4] = ((const uint2*)w2t)[i];
    }
    if (tid < EMB) { s_b2[tid] = bd2[tid]; s_w3[tid] = Wd3[tid]; }
    if (tid < 128) {
        int qi = q0blk + tid;
        s_a[tid] = qi < N_QUERY ? qe[qi] : 0;
        s_b[tid] = qi < N_QUERY ? qe[N_QUERY + qi] : 0;
    }
    __syncthreads();

    const uint2* uv2 = (const uint2*)uv;
    for (int i = tid; i < 128 * 32; i += 256) {
        int q = i >> 5, c = i & 31;
        uint2 uu = uv2[(size_t)s_a[q] * 64 + c];
        uint2 vv = uv2[(size_t)s_b[q] * 64 + 32 + c];
        float2 u0 = __bfloat1622float2(*(__nv_bfloat162*)&uu.x);
        float2 u1 = __bfloat1622float2(*(__nv_bfloat162*)&uu.y);
        float2 v0 = __bfloat1622float2(*(__nv_bfloat162*)&vv.x);
        float2 v1 = __bfloat1622float2(*(__nv_bfloat162*)&vv.y);
        __nv_bfloat162 p0 = __floats2bfloat162_rn(fmaxf(u0.x + v0.x, 0.f), fmaxf(u0.y + v0.y, 0.f));
        __nv_bfloat162 p1 = __floats2bfloat162_rn(fmaxf(u1.x + v1.x, 0.f), fmaxf(u1.y + v1.y, 0.f));
        uint2 o;
        o.x = *(uint32_t*)&p0;
        o.y = *(uint32_t*)&p1;
        *(uint2*)&s_d[q * 136 + c * 4] = o;
    }
    __syncthreads();

    {
        const int lane = tid & 31, warp = tid >> 5;
        const int q0 = warp * 16;
        const int gid = lane >> 2, tig = lane & 3;
        float acc[8][4];
#pragma unroll
        for (int t = 0; t < 8; t++)
#pragma unroll
            for (int j = 0; j < 4; j++) acc[t][j] = 0.f;

#pragma unroll
        for (int k0 = 0; k0 < 128; k0 += 16) {
            uint32_t a0 = *(const uint32_t*)&s_d[(q0 + gid) * 136 + k0 + 2 * tig];
            uint32_t a1 = *(const uint32_t*)&s_d[(q0 + gid + 8) * 136 + k0 + 2 * tig];
            uint32_t a2 = *(const uint32_t*)&s_d[(q0 + gid) * 136 + k0 + 2 * tig + 8];
            uint32_t a3 = *(const uint32_t*)&s_d[(q0 + gid + 8) * 136 + k0 + 2 * tig + 8];
#pragma unroll
            for (int t = 0; t < 8; t++) {
                int n = t * 8 + gid;
                uint32_t b0 = *(const uint32_t*)&s_w[n * 136 + k0 + 2 * tig];
                uint32_t b1 = *(const uint32_t*)&s_w[n * 136 + k0 + 2 * tig + 8];
                asm volatile(
                    "mma.sync.aligned.m16n8k16.row.col.f32.bf16.bf16.f32 "
                    "{%0,%1,%2,%3}, {%4,%5,%6,%7}, {%8,%9}, {%0,%1,%2,%3};"
                    : "+f"(acc[t][0]), "+f"(acc[t][1]), "+f"(acc[t][2]), "+f"(acc[t][3])
                    : "r"(a0), "r"(a1), "r"(a2), "r"(a3), "r"(b0), "r"(b1));
            }
        }
        float pa = 0.f, pb = 0.f;
#pragma unroll
        for (int t = 0; t < 8; t++) {
            int c = t * 8 + 2 * tig;
            float bb0 = s_b2[c], bb1 = s_b2[c + 1];
            float w0 = s_w3[c], w1 = s_w3[c + 1];
            pa = fmaf(fmaxf(acc[t][0] + bb0, 0.f), w0, pa);
            pa = fmaf(fmaxf(acc[t][1] + bb1, 0.f), w1, pa);
            pb = fmaf(fmaxf(acc[t][2] + bb0, 0.f), w0, pb);
            pb = fmaf(fmaxf(acc[t][3] + bb1, 0.f), w1, pb);
        }
        pa += __shfl_xor_sync(0xffffffffu, pa, 1);
        pa += __shfl_xor_sync(0xffffffffu, pa, 2);
        pb += __shfl_xor_sync(0xffffffffu, pb, 1);
        pb += __shfl_xor_sync(0xffffffffu, pb, 2);
        if (tig == 0) {
            float b3 = bd3[0];
            int qi_a = q0blk + q0 + gid;
            int qi_b = qi_a + 8;
            if (qi_a < N_QUERY) out[qi_a] = 1.0f / (1.0f + expf(-(pa + b3)));
            if (qi_b < N_QUERY) out[qi_b] = 1.0f / (1.0f + expf(-(pb + b3)));
        }
    }
}

// ---------------- launch ----------------
extern "C" void kernel_launch(void* const* d_in, const int* in_sizes, int n_in,
                              void* d_out, int out_size) {
    const float* x   = (const float*)d_in[0];
    const int* ei    = (const int*)d_in[1];
    const int* qe    = (const int*)d_in[2];
    const float* W1  = (const float*)d_in[3];
    const float* b1  = (const float*)d_in[4];
    const float* W2  = (const float*)d_in[5];
    const float* b2  = (const float*)d_in[6];
    const float* Wfc = (const float*)d_in[7];
    const float* bfc = (const float*)d_in[8];
    const float* Wd1 = (const float*)d_in[9];
    const float* bd1 = (const float*)d_in[10];
    const float* Wd2 = (const float*)d_in[11];
    const float* bd2 = (const float*)d_in[12];
    const float* Wd3 = (const float*)d_in[13];
    const float* bd3 = (const float*)d_in[14];
    float* out = (float*)d_out;

    float* pBC2;
    __nv_bfloat16 *pHS, *pH2, *pUV, *pW2TB, *pWL2T, *pWCT;
    int* pCnt;
    { void* p; cudaGetSymbolAddress(&p, g_hsb);    pHS = (__nv_bfloat16*)p; }
    { void* p; cudaGetSymbolAddress(&p, g_hb2);    pH2 = (__nv_bfloat16*)p; }
    { void* p; cudaGetSymbolAddress(&p, g_uvb);    pUV = (__nv_bfloat16*)p; }
    { void* p; cudaGetSymbolAddress(&p, g_w2tb);   pW2TB = (__nv_bfloat16*)p; }
    { void* p; cudaGetSymbolAddress(&p, g_wl2t);   pWL2T = (__nv_bfloat16*)p; }
    { void* p; cudaGetSymbolAddress(&p, g_wcombt); pWCT = (__nv_bfloat16*)p; }
    { void* p; cudaGetSymbolAddress(&p, g_bcomb);  pBC2 = (float*)p; }
    { void* p; cudaGetSymbolAddress(&p, g_cnt);    pCnt = (int*)p; }

    const int SM_GEMM = 2 * 128 * 136 * 2;  // 69632 -> 2 blocks/SM
    const int SM_DEC  = 34816 + 17408;      // 52224
    cudaFuncSetAttribute(gemm_bf16<128, 0>, cudaFuncAttributeMaxDynamicSharedMemorySize, SM_GEMM);
    cudaFuncSetAttribute(gemm_bf16<256, 1>, cudaFuncAttributeMaxDynamicSharedMemorySize, SM_GEMM);
    cudaFuncSetAttribute(k_decoder, cudaFuncAttributeMaxDynamicSharedMemorySize, SM_DEC);

    const int NBLK = (N_NODES + 127) / 128;

    // CSR build (parallel scan) + weight packing
    cudaMemsetAsync(pCnt, 0, N_NODES * sizeof(int));
    k_cnt<<<(N_EDGES + 255) / 256, 256>>>(ei);
    k_scanA<<<NSCAN_BLK, 256>>>();
    k_scanB<<<1, 512>>>();
    k_scanC<<<NSCAN_BLK, 256>>>();
    k_fill<<<(N_EDGES + 255) / 256, 256>>>(ei);
    k_pack<<<64, 256>>>(Wd1, bd1, Wd2, W2);
    k_wcomb<<<129, 256>>>(Wfc, bfc);

    // layer 1 in input space: prep -> 7-dim agg -> tiny GEMM -> h1'(bf16)
    k_prep<<<(N_NODES + 255) / 256, 256>>>(x);
    k_aggx<<<(N_NODES * 8 + 255) / 256, 256>>>();
    k_gemm1<<<(N_NODES + 7) / 8, 256>>>(W1, b1, pH2);

    // layer 2: hs2 = bf16((h1'@W2)*dinv) -> agg -> h2'(bf16)
    gemm_bf16<128, 0><<<NBLK, 256, SM_GEMM>>>(pH2, pWL2T, nullptr, pHS);
    k_agg<<<(N_NODES * 32 + 255) / 256, 256>>>(pHS, b2, pH2);

    // fused fc+UV: UV = bf16(h2' @ Wcomb + bcomb)
    gemm_bf16<256, 1><<<NBLK, 256, SM_GEMM>>>(pH2, pWCT, pBC2, pUV);

    // decoder
    k_decoder<<<(N_QUERY + 127) / 128, 256, SM_DEC>>>(pUV, qe, pW2TB, bd2, Wd3, bd3, out);
}

// round 14
// speedup vs baseline: 2.8150x; 1.0343x over previous
#include <cuda_runtime.h>
#include <cuda_bf16.h>
#include <math.h>
#include <stdint.h>

#define N_NODES 100000
#define N_EDGES 1600000
#define N_QUERY 500000
#define F_IN 7
#define HID 128
#define EMB 64
#define NSCAN_BLK 391

// ---------------- scratch (device globals) ----------------
__device__ float g_dinv[N_NODES];
__device__ int   g_cnt[N_NODES];
__device__ int   g_off[N_NODES + 1];
__device__ int   g_cur[N_NODES];
__device__ int   g_srcn[N_EDGES];
__device__ int   g_bsum[512];
__device__ __nv_bfloat16 g_xs8[(size_t)N_NODES * 8];     // bf16 x*dinv padded to 8
__device__ __nv_bfloat16 g_hsb[(size_t)N_NODES * HID];   // bf16 message buffer (layer 2)
__device__ __nv_bfloat16 g_hb2[(size_t)N_NODES * HID];   // bf16 aggregated activations
__device__ __nv_bfloat16 g_uvb[(size_t)N_NODES * 256];   // bf16 [U(128)+b1' | V(128)]
__device__ __nv_bfloat16 g_w2tb[64 * 128];               // Wd2^T [n][k] bf16
__device__ __nv_bfloat16 g_wl2t[128 * 128];              // W2^T  [n][k] bf16
__device__ __nv_bfloat16 g_wcombt[256 * 128];            // (Wfc@Wd1p)^T [n][k] bf16
__device__ float g_bcomb[256];                           // bfc @ Wd1p + [bd1|0]

// ---------------- CSR build ----------------
__global__ void k_cnt(const int* __restrict__ ei) {
    int e = blockIdx.x * blockDim.x + threadIdx.x;
    if (e < N_EDGES) atomicAdd(&g_cnt[ei[N_EDGES + e]], 1);
}

// phase A: per-block sums of 256 counts
__global__ __launch_bounds__(256) void k_scanA() {
    __shared__ int s[256];
    int i = blockIdx.x * 256 + threadIdx.x;
    int c = (i < N_NODES) ? g_cnt[i] : 0;
    s[threadIdx.x] = c;
    __syncthreads();
#pragma unroll
    for (int off = 128; off > 0; off >>= 1) {
        if (threadIdx.x < off) s[threadIdx.x] += s[threadIdx.x + off];
        __syncthreads();
    }
    if (threadIdx.x == 0) g_bsum[blockIdx.x] = s[0];
}

// phase B: exclusive scan of NSCAN_BLK block sums (1 block, 512 threads)
__global__ __launch_bounds__(512) void k_scanB() {
    __shared__ int s[512];
    int tid = threadIdx.x;
    int v = (tid < NSCAN_BLK) ? g_bsum[tid] : 0;
    s[tid] = v;
    __syncthreads();
#pragma unroll
    for (int off = 1; off < 512; off <<= 1) {
        int t = (tid >= off) ? s[tid - off] : 0;
        __syncthreads();
        s[tid] += t;
        __syncthreads();
    }
    if (tid < NSCAN_BLK) g_bsum[tid] = s[tid] - v;  // exclusive
    if (tid == 0) g_off[N_NODES] = N_EDGES;
}

// phase C: per-block exclusive scan + write off/cur/dinv + fused x-prep (xs8)
__global__ __launch_bounds__(256) void k_scanC(const float* __restrict__ x) {
    __shared__ int s[256];
    int tid = threadIdx.x;
    int i = blockIdx.x * 256 + tid;
    int c = (i < N_NODES) ? g_cnt[i] : 0;
    s[tid] = c;
    __syncthreads();
#pragma unroll
    for (int off = 1; off < 256; off <<= 1) {
        int t = (tid >= off) ? s[tid - off] : 0;
        __syncthreads();
        s[tid] += t;
        __syncthreads();
    }
    if (i < N_NODES) {
        int off = g_bsum[blockIdx.x] + s[tid] - c;  // exclusive prefix
        g_off[i] = off;
        g_cur[i] = off;
        float dv = rsqrtf((float)c + 1.0f);
        g_dinv[i] = dv;
        // fused prep: xs8[i] = bf16(x[i] * dinv) padded to 8
        float v[8];
#pragma unroll
        for (int k = 0; k < F_IN; k++) v[k] = x[i * F_IN + k] * dv;
        v[7] = 0.f;
        __nv_bfloat162 p0 = __floats2bfloat162_rn(v[0], v[1]);
        __nv_bfloat162 p1 = __floats2bfloat162_rn(v[2], v[3]);
        __nv_bfloat162 p2 = __floats2bfloat162_rn(v[4], v[5]);
        __nv_bfloat162 p3 = __floats2bfloat162_rn(v[6], v[7]);
        uint4 o;
        o.x = *(uint32_t*)&p0; o.y = *(uint32_t*)&p1;
        o.z = *(uint32_t*)&p2; o.w = *(uint32_t*)&p3;
        ((uint4*)g_xs8)[i] = o;
    }
}

__global__ void k_fill(const int* __restrict__ ei) {
    int e = blockIdx.x * blockDim.x + threadIdx.x;
    if (e >= N_EDGES) return;
    int s = ei[e];
    int d = ei[N_EDGES + e];
    int pos = atomicAdd(&g_cur[d], 1);
    g_srcn[pos] = s;
}

// ---------------- pack weights (transposed bf16) ----------------
__global__ void k_pack(const float* __restrict__ Wd2, const float* __restrict__ W2) {
    int idx = blockIdx.x * blockDim.x + threadIdx.x;
    if (idx < 64 * 128) {
        int n = idx >> 7, k = idx & 127;
        g_w2tb[idx] = __float2bfloat16(Wd2[k * 64 + n]);
    }
    if (idx < 128 * 128) {
        int n = idx >> 7, k = idx & 127;
        g_wl2t[idx] = __float2bfloat16(W2[k * 128 + n]);
    }
}

// ---------------- combined fc+Wd1 weights: Wcomb^T = (Wfc @ Wd1p)^T, bcomb --------------
// Wd1p[j][c] = (c<128) ? Wd1[j][c] : Wd1[64+j][c-128]
__global__ void k_wcomb(const float* __restrict__ Wfc, const float* __restrict__ bfc,
                        const float* __restrict__ Wd1, const float* __restrict__ bd1) {
    __shared__ float s[64];
    int b = blockIdx.x;
    int c = threadIdx.x;  // 256
    const float* wcol = (c < 128) ? &Wd1[c] : &Wd1[64 * 128 + (c - 128)];
    if (b < 128) {
        if (c < 64) s[c] = Wfc[b * 64 + c];
        __syncthreads();
        float acc = 0.f;
#pragma unroll 8
        for (int j = 0; j < 64; j++) acc = fmaf(s[j], wcol[j * 128], acc);
        g_wcombt[c * 128 + b] = __float2bfloat16(acc);
    } else {
        if (c < 64) s[c] = bfc[c];
        __syncthreads();
        float acc = (c < 128) ? bd1[c] : 0.f;
#pragma unroll 8
        for (int j = 0; j < 64; j++) acc = fmaf(s[j], wcol[j * 128], acc);
        g_bcomb[c] = acc;
    }
}

// ---------------- fused layer 1: 7-dim agg + tiny GEMM -> h1'(bf16) ----------------
// Warp = 4 nodes. 8-lane groups aggregate (butterfly -> all lanes hold sums),
// then whole warp emits 128 cols per node via shfl broadcast.
__global__ __launch_bounds__(256) void k_l1(const float* __restrict__ W1,
                                            const float* __restrict__ b1,
                                            __nv_bfloat16* __restrict__ out) {
    __shared__ float sW[F_IN * HID];
    const int tid = threadIdx.x;
    for (int i = tid; i < F_IN * HID; i += 256) sW[i] = W1[i];
    __syncthreads();

    const int lane = tid & 31;
    const int gwarp = (blockIdx.x * 256 + tid) >> 5;
    const int sub = lane & 7, grp = lane >> 3;
    const int node = gwarp * 4 + grp;   // exact: 3125 blocks * 32 = 100000
    const uint4* xs = (const uint4*)g_xs8;

    float a0 = 0.f, a1 = 0.f, a2 = 0.f, a3 = 0.f, a4 = 0.f, a5 = 0.f, a6 = 0.f, a7 = 0.f;
#define ACC_ADD(vv) do { \
        float2 f0 = __bfloat1622float2(*(__nv_bfloat162*)&(vv).x); \
        float2 f1 = __bfloat1622float2(*(__nv_bfloat162*)&(vv).y); \
        float2 f2 = __bfloat1622float2(*(__nv_bfloat162*)&(vv).z); \
        float2 f3 = __bfloat1622float2(*(__nv_bfloat162*)&(vv).w); \
        a0 += f0.x; a1 += f0.y; a2 += f1.x; a3 += f1.y; \
        a4 += f2.x; a5 += f2.y; a6 += f3.x; a7 += f3.y; } while (0)
    if (node < N_NODES) {
        if (sub == 0) {
            uint4 v = xs[node];
            ACC_ADD(v);
        }
        const int end = g_off[node + 1];
        for (int e = g_off[node] + sub; e < end; e += 8) {
            uint4 v = xs[g_srcn[e]];
            ACC_ADD(v);
        }
    }
#undef ACC_ADD
#pragma unroll
    for (int off = 4; off > 0; off >>= 1) {
        a0 += __shfl_xor_sync(0xffffffffu, a0, off);
        a1 += __shfl_xor_sync(0xffffffffu, a1, off);
        a2 += __shfl_xor_sync(0xffffffffu, a2, off);
        a3 += __shfl_xor_sync(0xffffffffu, a3, off);
        a4 += __shfl_xor_sync(0xffffffffu, a4, off);
        a5 += __shfl_xor_sync(0xffffffffu, a5, off);
        a6 += __shfl_xor_sync(0xffffffffu, a6, off);
        a7 += __shfl_xor_sync(0xffffffffu, a7, off);
    }

    // GEMM per node: broadcast 7 values from lane w*8; 32 lanes x 4 cols
    const int j = lane * 4;
    const float4 bb = *(const float4*)&b1[j];
#pragma unroll
    for (int w = 0; w < 4; w++) {
        int n2 = gwarp * 4 + w;
        if (n2 >= N_NODES) break;
        int src = w * 8;
        float xk0 = __shfl_sync(0xffffffffu, a0, src);
        float xk1 = __shfl_sync(0xffffffffu, a1, src);
        float xk2 = __shfl_sync(0xffffffffu, a2, src);
        float xk3 = __shfl_sync(0xffffffffu, a3, src);
        float xk4 = __shfl_sync(0xffffffffu, a4, src);
        float xk5 = __shfl_sync(0xffffffffu, a5, src);
        float xk6 = __shfl_sync(0xffffffffu, a6, src);
        const float* w0 = &sW[0 * HID + j];
        float4 acc;
        acc.x = xk0 * w0[0]; acc.y = xk0 * w0[1]; acc.z = xk0 * w0[2]; acc.w = xk0 * w0[3];
        const float* wp;
        wp = &sW[1 * HID + j];
        acc.x = fmaf(xk1, wp[0], acc.x); acc.y = fmaf(xk1, wp[1], acc.y);
        acc.z = fmaf(xk1, wp[2], acc.z); acc.w = fmaf(xk1, wp[3], acc.w);
        wp = &sW[2 * HID + j];
        acc.x = fmaf(xk2, wp[0], acc.x); acc.y = fmaf(xk2, wp[1], acc.y);
        acc.z = fmaf(xk2, wp[2], acc.z); acc.w = fmaf(xk2, wp[3], acc.w);
        wp = &sW[3 * HID + j];
        acc.x = fmaf(xk3, wp[0], acc.x); acc.y = fmaf(xk3, wp[1], acc.y);
        acc.z = fmaf(xk3, wp[2], acc.z); acc.w = fmaf(xk3, wp[3], acc.w);
        wp = &sW[4 * HID + j];
        acc.x = fmaf(xk4, wp[0], acc.x); acc.y = fmaf(xk4, wp[1], acc.y);
        acc.z = fmaf(xk4, wp[2], acc.z); acc.w = fmaf(xk4, wp[3], acc.w);
        wp = &sW[5 * HID + j];
        acc.x = fmaf(xk5, wp[0], acc.x); acc.y = fmaf(xk5, wp[1], acc.y);
        acc.z = fmaf(xk5, wp[2], acc.z); acc.w = fmaf(xk5, wp[3], acc.w);
        wp = &sW[6 * HID + j];
        acc.x = fmaf(xk6, wp[0], acc.x); acc.y = fmaf(xk6, wp[1], acc.y);
        acc.z = fmaf(xk6, wp[2], acc.z); acc.w = fmaf(xk6, wp[3], acc.w);
        float dv = g_dinv[n2];
        float r0 = fmaxf(fmaf(acc.x, dv, bb.x), 0.f);
        float r1 = fmaxf(fmaf(acc.y, dv, bb.y), 0.f);
        float r2 = fmaxf(fmaf(acc.z, dv, bb.z), 0.f);
        float r3 = fmaxf(fmaf(acc.w, dv, bb.w), 0.f);
        __nv_bfloat162 p0 = __floats2bfloat162_rn(r0, r1);
        __nv_bfloat162 p1 = __floats2bfloat162_rn(r2, r3);
        uint2 o;
        o.x = *(uint32_t*)&p0;
        o.y = *(uint32_t*)&p1;
        *(uint2*)&out[(size_t)n2 * HID + j] = o;
    }
}

// ---------------- fused CSR aggregation (layer 2): out = bf16(relu(dinv*(sum+self)+b)) --
__global__ __launch_bounds__(256) void k_agg(const __nv_bfloat16* __restrict__ hs,
                                             const float* __restrict__ bias,
                                             __nv_bfloat16* __restrict__ out) {
    int t = blockIdx.x * blockDim.x + threadIdx.x;
    int node = t >> 5, lane = t & 31;
    if (node >= N_NODES) return;
    const int half = lane >> 4;
    const int cl = lane & 15;
    const uint4* h4 = (const uint4*)hs;

    float a0 = 0.f, a1 = 0.f, a2 = 0.f, a3 = 0.f, a4 = 0.f, a5 = 0.f, a6 = 0.f, a7 = 0.f;
#define ACC_ADD(vv) do { \
        float2 f0 = __bfloat1622float2(*(__nv_bfloat162*)&(vv).x); \
        float2 f1 = __bfloat1622float2(*(__nv_bfloat162*)&(vv).y); \
        float2 f2 = __bfloat1622float2(*(__nv_bfloat162*)&(vv).z); \
        float2 f3 = __bfloat1622float2(*(__nv_bfloat162*)&(vv).w); \
        a0 += f0.x; a1 += f0.y; a2 += f1.x; a3 += f1.y; \
        a4 += f2.x; a5 += f2.y; a6 += f3.x; a7 += f3.y; } while (0)

    if (half == 0) {
        uint4 v = h4[(size_t)node * 16 + cl];
        ACC_ADD(v);
    }
    int e = g_off[node] + half;
    const int end = g_off[node + 1];
    for (; e + 6 < end; e += 8) {
        int s0 = g_srcn[e], s1 = g_srcn[e + 2], s2 = g_srcn[e + 4], s3 = g_srcn[e + 6];
        uint4 v0 = h4[(size_t)s0 * 16 + cl];
        uint4 v1 = h4[(size_t)s1 * 16 + cl];
        uint4 v2 = h4[(size_t)s2 * 16 + cl];
        uint4 v3 = h4[(size_t)s3 * 16 + cl];
        ACC_ADD(v0); ACC_ADD(v1); ACC_ADD(v2); ACC_ADD(v3);
    }
    for (; e < end; e += 2) {
        uint4 v = h4[(size_t)g_srcn[e] * 16 + cl];
        ACC_ADD(v);
    }
#undef ACC_ADD
    a0 += __shfl_xor_sync(0xffffffffu, a0, 16);
    a1 += __shfl_xor_sync(0xffffffffu, a1, 16);
    a2 += __shfl_xor_sync(0xffffffffu, a2, 16);
    a3 += __shfl_xor_sync(0xffffffffu, a3, 16);
    a4 += __shfl_xor_sync(0xffffffffu, a4, 16);
    a5 += __shfl_xor_sync(0xffffffffu, a5, 16);
    a6 += __shfl_xor_sync(0xffffffffu, a6, 16);
    a7 += __shfl_xor_sync(0xffffffffu, a7, 16);

    if (half == 0) {
        float dv = g_dinv[node];
        float4 bl = ((const float4*)bias)[cl * 2];
        float4 bh = ((const float4*)bias)[cl * 2 + 1];
        float r0 = fmaxf(fmaf(a0, dv, bl.x), 0.f);
        float r1 = fmaxf(fmaf(a1, dv, bl.y), 0.f);
        float r2 = fmaxf(fmaf(a2, dv, bl.z), 0.f);
        float r3 = fmaxf(fmaf(a3, dv, bl.w), 0.f);
        float r4 = fmaxf(fmaf(a4, dv, bh.x), 0.f);
        float r5 = fmaxf(fmaf(a5, dv, bh.y), 0.f);
        float r6 = fmaxf(fmaf(a6, dv, bh.z), 0.f);
        float r7 = fmaxf(fmaf(a7, dv, bh.w), 0.f);
        __nv_bfloat162 p0 = __floats2bfloat162_rn(r0, r1);
        __nv_bfloat162 p1 = __floats2bfloat162_rn(r2, r3);
        __nv_bfloat162 p2 = __floats2bfloat162_rn(r4, r5);
        __nv_bfloat162 p3 = __floats2bfloat162_rn(r6, r7);
        uint4 o;
        o.x = *(uint32_t*)&p0; o.y = *(uint32_t*)&p1;
        o.z = *(uint32_t*)&p2; o.w = *(uint32_t*)&p3;
        ((uint4*)out)[(size_t)node * 16 + cl] = o;
    }
}

// ---------------- bf16 tensor-core node GEMM: C[M,NT] = A[M,128] @ Bt^T ----------------
// Chunked B buffer (128 cols at a time) -> 69632 B smem -> 2 blocks/SM for all NT.
template <int NT, int EPI>
__global__ __launch_bounds__(256) void gemm_bf16(const __nv_bfloat16* __restrict__ A,
                                                 const __nv_bfloat16* __restrict__ Bt,
                                                 const float* __restrict__ bias,
                                                 __nv_bfloat16* __restrict__ C) {
    constexpr int KD = 128;
    constexpr int KP = KD + 8;
    extern __shared__ char smraw[];
    __nv_bfloat16* s_a = (__nv_bfloat16*)smraw;                   // [128][KP]
    __nv_bfloat16* s_b = (__nv_bfloat16*)(smraw + 128 * KP * 2);  // [128][KP]
    const int tid = threadIdx.x;
    const int row0 = blockIdx.x * 128;

    for (int i = tid; i < 128 * (KD / 4); i += 256) {
        int r = i >> 5, k4 = i & 31;
        int gr = row0 + r;
        if (gr >= N_NODES) gr = N_NODES - 1;
        *(uint2*)&s_a[r * KP + k4 * 4] = *(const uint2*)&A[(size_t)gr * KD + k4 * 4];
    }

    const int lane = tid & 31, warp = tid >> 5;
    const int q0 = warp * 16;
    const int gid = lane >> 2, tig = lane & 3;
    constexpr int NCHUNK = NT / 128;
    constexpr int NTILES = 16;

    const int qa = row0 + q0 + gid, qb = qa + 8;
    float dva = 1.f, dvb = 1.f;
    if (EPI == 0) {
        dva = (qa < N_NODES) ? g_dinv[qa] : 0.f;
        dvb = (qb < N_NODES) ? g_dinv[qb] : 0.f;
    }

#pragma unroll
    for (int nc = 0; nc < NCHUNK; nc++) {
        for (int i = tid; i < 128 * (KD / 4); i += 256) {
            int n = i >> 5, k4 = i & 31;
            *(uint2*)&s_b[n * KP + k4 * 4] =
                *(const uint2*)&Bt[((size_t)(nc * 128 + n)) * KD + k4 * 4];
        }
        __syncthreads();

        float acc[NTILES][4];
#pragma unroll
        for (int t = 0; t < NTILES; t++)
#pragma unroll
            for (int j = 0; j < 4; j++) acc[t][j] = 0.f;

#pragma unroll
        for (int k0 = 0; k0 < KD; k0 += 16) {
            uint32_t a0 = *(const uint32_t*)&s_a[(q0 + gid) * KP + k0 + 2 * tig];
            uint32_t a1 = *(const uint32_t*)&s_a[(q0 + gid + 8) * KP + k0 + 2 * tig];
            uint32_t a2 = *(const uint32_t*)&s_a[(q0 + gid) * KP + k0 + 2 * tig + 8];
            uint32_t a3 = *(const uint32_t*)&s_a[(q0 + gid + 8) * KP + k0 + 2 * tig + 8];
#pragma unroll
            for (int t = 0; t < NTILES; t++) {
                int n = t * 8 + gid;
                uint32_t b0 = *(const uint32_t*)&s_b[n * KP + k0 + 2 * tig];
                uint32_t b1 = *(const uint32_t*)&s_b[n * KP + k0 + 2 * tig + 8];
                asm volatile(
                    "mma.sync.aligned.m16n8k16.row.col.f32.bf16.bf16.f32 "
                    "{%0,%1,%2,%3}, {%4,%5,%6,%7}, {%8,%9}, {%0,%1,%2,%3};"
                    : "+f"(acc[t][0]), "+f"(acc[t][1]), "+f"(acc[t][2]), "+f"(acc[t][3])
                    : "r"(a0), "r"(a1), "r"(a2), "r"(a3), "r"(b0), "r"(b1));
            }
        }
#pragma unroll
        for (int t = 0; t < NTILES; t++) {
            int c = nc * 128 + t * 8 + 2 * tig;
            float r0, r1, r2, r3;
            if (EPI == 0) {
                r0 = acc[t][0] * dva; r1 = acc[t][1] * dva;
                r2 = acc[t][2] * dvb; r3 = acc[t][3] * dvb;
            } else {
                float b0 = bias[c], b1 = bias[c + 1];
                r0 = acc[t][0] + b0; r1 = acc[t][1] + b1;
                r2 = acc[t][2] + b0; r3 = acc[t][3] + b1;
            }
            __nv_bfloat162 pa = __floats2bfloat162_rn(r0, r1);
            __nv_bfloat162 pb = __floats2bfloat162_rn(r2, r3);
            if (qa < N_NODES) *(__nv_bfloat162*)&C[(size_t)qa * NT + c] = pa;
            if (qb < N_NODES) *(__nv_bfloat162*)&C[(size_t)qb * NT + c] = pb;
        }
        if (nc + 1 < NCHUNK) __syncthreads();
    }
}

// ---------------- decoder: 128 q/block; bf16 mma stage 2; stage 3 fused via shfl --------
__global__ __launch_bounds__(256) void k_decoder(
    const __nv_bfloat16* __restrict__ uv, const int* __restrict__ qe,
    const __nv_bfloat16* __restrict__ w2t, const float* __restrict__ bd2,
    const float* __restrict__ Wd3, const float* __restrict__ bd3,
    float* __restrict__ out) {
    extern __shared__ char smraw[];
    __nv_bfloat16* s_d = (__nv_bfloat16*)smraw;              // [128][136]
    __nv_bfloat16* s_w = (__nv_bfloat16*)(smraw + 34816);    // [64][136]
    __shared__ int s_a[128], s_b[128];
    __shared__ float s_b2[EMB], s_w3[EMB];

    const int tid = threadIdx.x;
    const int q0blk = blockIdx.x * 128;

    for (int i = tid; i < 64 * 32; i += 256) {
        int n = i >> 5, k4 = i & 31;
        *(uint2*)&s_w[n * 136 + k4 * 4] = ((const uint2*)w2t)[i];
    }
    if (tid < EMB) { s_b2[tid] = bd2[tid]; s_w3[tid] = Wd3[tid]; }
    if (tid < 128) {
        int qi = q0blk + tid;
        s_a[tid] = qi < N_QUERY ? qe[qi] : 0;
        s_b[tid] = qi < N_QUERY ? qe[N_QUERY + qi] : 0;
    }
    __syncthreads();

    const uint2* uv2 = (const uint2*)uv;
    for (int i = tid; i < 128 * 32; i += 256) {
        int q = i >> 5, c = i & 31;
        uint2 uu = uv2[(size_t)s_a[q] * 64 + c];
        uint2 vv = uv2[(size_t)s_b[q] * 64 + 32 + c];
        float2 u0 = __bfloat1622float2(*(__nv_bfloat162*)&uu.x);
        float2 u1 = __bfloat1622float2(*(__nv_bfloat162*)&uu.y);
        float2 v0 = __bfloat1622float2(*(__nv_bfloat162*)&vv.x);
        float2 v1 = __bfloat1622float2(*(__nv_bfloat162*)&vv.y);
        __nv_bfloat162 p0 = __floats2bfloat162_rn(fmaxf(u0.x + v0.x, 0.f), fmaxf(u0.y + v0.y, 0.f));
        __nv_bfloat162 p1 = __floats2bfloat162_rn(fmaxf(u1.x + v1.x, 0.f), fmaxf(u1.y + v1.y, 0.f));
        uint2 o;
        o.x = *(uint32_t*)&p0;
        o.y = *(uint32_t*)&p1;
        *(uint2*)&s_d[q * 136 + c * 4] = o;
    }
    __syncthreads();

    {
        const int lane = tid & 31, warp = tid >> 5;
        const int q0 = warp * 16;
        const int gid = lane >> 2, tig = lane & 3;
        float acc[8][4];
#pragma unroll
        for (int t = 0; t < 8; t++)
#pragma unroll
            for (int j = 0; j < 4; j++) acc[t][j] = 0.f;

#pragma unroll
        for (int k0 = 0; k0 < 128; k0 += 16) {
            uint32_t a0 = *(const uint32_t*)&s_d[(q0 + gid) * 136 + k0 + 2 * tig];
            uint32_t a1 = *(const uint32_t*)&s_d[(q0 + gid + 8) * 136 + k0 + 2 * tig];
            uint32_t a2 = *(const uint32_t*)&s_d[(q0 + gid) * 136 + k0 + 2 * tig + 8];
            uint32_t a3 = *(const uint32_t*)&s_d[(q0 + gid + 8) * 136 + k0 + 2 * tig + 8];
#pragma unroll
            for (int t = 0; t < 8; t++) {
                int n = t * 8 + gid;
                uint32_t b0 = *(const uint32_t*)&s_w[n * 136 + k0 + 2 * tig];
                uint32_t b1 = *(const uint32_t*)&s_w[n * 136 + k0 + 2 * tig + 8];
                asm volatile(
                    "mma.sync.aligned.m16n8k16.row.col.f32.bf16.bf16.f32 "
                    "{%0,%1,%2,%3}, {%4,%5,%6,%7}, {%8,%9}, {%0,%1,%2,%3};"
                    : "+f"(acc[t][0]), "+f"(acc[t][1]), "+f"(acc[t][2]), "+f"(acc[t][3])
                    : "r"(a0), "r"(a1), "r"(a2), "r"(a3), "r"(b0), "r"(b1));
            }
        }
        float pa = 0.f, pb = 0.f;
#pragma unroll
        for (int t = 0; t < 8; t++) {
            int c = t * 8 + 2 * tig;
            float bb0 = s_b2[c], bb1 = s_b2[c + 1];
            float w0 = s_w3[c], w1 = s_w3[c + 1];
            pa = fmaf(fmaxf(acc[t][0] + bb0, 0.f), w0, pa);
            pa = fmaf(fmaxf(acc[t][1] + bb1, 0.f), w1, pa);
            pb = fmaf(fmaxf(acc[t][2] + bb0, 0.f), w0, pb);
            pb = fmaf(fmaxf(acc[t][3] + bb1, 0.f), w1, pb);
        }
        pa += __shfl_xor_sync(0xffffffffu, pa, 1);
        pa += __shfl_xor_sync(0xffffffffu, pa, 2);
        pb += __shfl_xor_sync(0xffffffffu, pb, 1);
        pb += __shfl_xor_sync(0xffffffffu, pb, 2);
        if (tig == 0) {
            float b3 = bd3[0];
            int qi_a = q0blk + q0 + gid;
            int qi_b = qi_a + 8;
            if (qi_a < N_QUERY) out[qi_a] = 1.0f / (1.0f + expf(-(pa + b3)));
            if (qi_b < N_QUERY) out[qi_b] = 1.0f / (1.0f + expf(-(pb + b3)));
        }
    }
}

// ---------------- launch ----------------
extern "C" void kernel_launch(void* const* d_in, const int* in_sizes, int n_in,
                              void* d_out, int out_size) {
    const float* x   = (const float*)d_in[0];
    const int* ei    = (const int*)d_in[1];
    const int* qe    = (const int*)d_in[2];
    const float* W1  = (const float*)d_in[3];
    const float* b1  = (const float*)d_in[4];
    const float* W2  = (const float*)d_in[5];
    const float* b2  = (const float*)d_in[6];
    const float* Wfc = (const float*)d_in[7];
    const float* bfc = (const float*)d_in[8];
    const float* Wd1 = (const float*)d_in[9];
    const float* bd1 = (const float*)d_in[10];
    const float* Wd2 = (const float*)d_in[11];
    const float* bd2 = (const float*)d_in[12];
    const float* Wd3 = (const float*)d_in[13];
    const float* bd3 = (const float*)d_in[14];
    float* out = (float*)d_out;

    float* pBC2;
    __nv_bfloat16 *pHS, *pH2, *pUV, *pW2TB, *pWL2T, *pWCT;
    int* pCnt;
    { void* p; cudaGetSymbolAddress(&p, g_hsb);    pHS = (__nv_bfloat16*)p; }
    { void* p; cudaGetSymbolAddress(&p, g_hb2);    pH2 = (__nv_bfloat16*)p; }
    { void* p; cudaGetSymbolAddress(&p, g_uvb);    pUV = (__nv_bfloat16*)p; }
    { void* p; cudaGetSymbolAddress(&p, g_w2tb);   pW2TB = (__nv_bfloat16*)p; }
    { void* p; cudaGetSymbolAddress(&p, g_wl2t);   pWL2T = (__nv_bfloat16*)p; }
    { void* p; cudaGetSymbolAddress(&p, g_wcombt); pWCT = (__nv_bfloat16*)p; }
    { void* p; cudaGetSymbolAddress(&p, g_bcomb);  pBC2 = (float*)p; }
    { void* p; cudaGetSymbolAddress(&p, g_cnt);    pCnt = (int*)p; }

    const int SM_GEMM = 2 * 128 * 136 * 2;  // 69632 -> 2 blocks/SM
    const int SM_DEC  = 34816 + 17408;      // 52224
    cudaFuncSetAttribute(gemm_bf16<128, 0>, cudaFuncAttributeMaxDynamicSharedMemorySize, SM_GEMM);
    cudaFuncSetAttribute(gemm_bf16<256, 1>, cudaFuncAttributeMaxDynamicSharedMemorySize, SM_GEMM);
    cudaFuncSetAttribute(k_decoder, cudaFuncAttributeMaxDynamicSharedMemorySize, SM_DEC);

    const int NBLK = (N_NODES + 127) / 128;

    // CSR build (parallel scan; scanC fused with x-prep) + weight packing
    cudaMemsetAsync(pCnt, 0, N_NODES * sizeof(int));
    k_cnt<<<(N_EDGES + 255) / 256, 256>>>(ei);
    k_scanA<<<NSCAN_BLK, 256>>>();
    k_scanB<<<1, 512>>>();
    k_scanC<<<NSCAN_BLK, 256>>>(x);
    k_fill<<<(N_EDGES + 255) / 256, 256>>>(ei);
    k_pack<<<64, 256>>>(Wd2, W2);
    k_wcomb<<<129, 256>>>(Wfc, bfc, Wd1, bd1);

    // layer 1 fused (7-dim agg + tiny GEMM) -> h1'(bf16)
    k_l1<<<(N_NODES / 32), 256>>>(W1, b1, pH2);

    // layer 2: hs2 = bf16((h1'@W2)*dinv) -> agg -> h2'(bf16)
    gemm_bf16<128, 0><<<NBLK, 256, SM_GEMM>>>(pH2, pWL2T, nullptr, pHS);
    k_agg<<<(N_NODES * 32 + 255) / 256, 256>>>(pHS, b2, pH2);

    // fused fc+UV: UV = bf16(h2' @ Wcomb + bcomb)
    gemm_bf16<256, 1><<<NBLK, 256, SM_GEMM>>>(pH2, pWCT, pBC2, pUV);

    // decoder
    k_decoder<<<(N_QUERY + 127) / 128, 256, SM_DEC>>>(pUV, qe, pW2TB, bd2, Wd3, bd3, out);
}

// round 15
// speedup vs baseline: 3.0709x; 1.0909x over previous
#include <cuda_runtime.h>
#include <cuda_bf16.h>
#include <math.h>
#include <stdint.h>

#define N_NODES 100000
#define N_EDGES 1600000
#define N_QUERY 500000
#define F_IN 7
#define HID 128
#define EMB 64
#define NSCAN_BLK 391

// ---------------- scratch (device globals) ----------------
__device__ float g_dinv[N_NODES];
__device__ int   g_cnt[N_NODES];
__device__ int   g_off[N_NODES + 1];
__device__ int   g_cur[N_NODES];
__device__ int   g_srcn[N_EDGES];
__device__ int   g_bsum[512];
__device__ __nv_bfloat16 g_xs8[(size_t)N_NODES * 8];     // bf16 x*dinv padded to 8
__device__ __nv_bfloat16 g_h1s[(size_t)N_NODES * HID];   // bf16 h1'*dinv (messages)
__device__ __nv_bfloat16 g_m[(size_t)N_NODES * HID];     // bf16 aggregated m
__device__ __nv_bfloat16 g_uvb[(size_t)N_NODES * 256];   // bf16 [U(128)+b1' | V(128)]
__device__ __nv_bfloat16 g_w2tb[64 * 128];               // Wd2^T [n][k] bf16
__device__ __nv_bfloat16 g_wl2t[128 * 128];              // W2^T  [n][k] bf16
__device__ __nv_bfloat16 g_wcombt[256 * 128];            // (Wfc@Wd1p)^T [n][k] bf16
__device__ float g_bcomb[256];                           // bfc @ Wd1p + [bd1|0]

// ---------------- CSR build ----------------
__global__ void k_cnt(const int* __restrict__ ei) {
    int t = blockIdx.x * blockDim.x + threadIdx.x;
    if (t >= N_EDGES / 4) return;
    int4 d = ((const int4*)(ei + N_EDGES))[t];
    atomicAdd(&g_cnt[d.x], 1);
    atomicAdd(&g_cnt[d.y], 1);
    atomicAdd(&g_cnt[d.z], 1);
    atomicAdd(&g_cnt[d.w], 1);
}

// phase A: per-block sums of 256 counts
__global__ __launch_bounds__(256) void k_scanA() {
    __shared__ int s[256];
    int i = blockIdx.x * 256 + threadIdx.x;
    int c = (i < N_NODES) ? g_cnt[i] : 0;
    s[threadIdx.x] = c;
    __syncthreads();
#pragma unroll
    for (int off = 128; off > 0; off >>= 1) {
        if (threadIdx.x < off) s[threadIdx.x] += s[threadIdx.x + off];
        __syncthreads();
    }
    if (threadIdx.x == 0) g_bsum[blockIdx.x] = s[0];
}

// phase B: exclusive scan of NSCAN_BLK block sums
__global__ __launch_bounds__(512) void k_scanB() {
    __shared__ int s[512];
    int tid = threadIdx.x;
    int v = (tid < NSCAN_BLK) ? g_bsum[tid] : 0;
    s[tid] = v;
    __syncthreads();
#pragma unroll
    for (int off = 1; off < 512; off <<= 1) {
        int t = (tid >= off) ? s[tid - off] : 0;
        __syncthreads();
        s[tid] += t;
        __syncthreads();
    }
    if (tid < NSCAN_BLK) g_bsum[tid] = s[tid] - v;
    if (tid == 0) g_off[N_NODES] = N_EDGES;
}

// phase C: per-block exclusive scan + off/cur/dinv + fused x-prep
__global__ __launch_bounds__(256) void k_scanC(const float* __restrict__ x) {
    __shared__ int s[256];
    int tid = threadIdx.x;
    int i = blockIdx.x * 256 + tid;
    int c = (i < N_NODES) ? g_cnt[i] : 0;
    s[tid] = c;
    __syncthreads();
#pragma unroll
    for (int off = 1; off < 256; off <<= 1) {
        int t = (tid >= off) ? s[tid - off] : 0;
        __syncthreads();
        s[tid] += t;
        __syncthreads();
    }
    if (i < N_NODES) {
        int off = g_bsum[blockIdx.x] + s[tid] - c;
        g_off[i] = off;
        g_cur[i] = off;
        float dv = rsqrtf((float)c + 1.0f);
        g_dinv[i] = dv;
        float v[8];
#pragma unroll
        for (int k = 0; k < F_IN; k++) v[k] = x[i * F_IN + k] * dv;
        v[7] = 0.f;
        __nv_bfloat162 p0 = __floats2bfloat162_rn(v[0], v[1]);
        __nv_bfloat162 p1 = __floats2bfloat162_rn(v[2], v[3]);
        __nv_bfloat162 p2 = __floats2bfloat162_rn(v[4], v[5]);
        __nv_bfloat162 p3 = __floats2bfloat162_rn(v[6], v[7]);
        uint4 o;
        o.x = *(uint32_t*)&p0; o.y = *(uint32_t*)&p1;
        o.z = *(uint32_t*)&p2; o.w = *(uint32_t*)&p3;
        ((uint4*)g_xs8)[i] = o;
    }
}

__global__ void k_fill(const int* __restrict__ ei) {
    int e = blockIdx.x * blockDim.x + threadIdx.x;
    if (e >= N_EDGES) return;
    int s = ei[e];
    int d = ei[N_EDGES + e];
    int pos = atomicAdd(&g_cur[d], 1);
    g_srcn[pos] = s;
}

// ---------------- all weight prep in one grid ----------------
// blocks 0..127: wcomb row; block 128: bcomb; blocks 129..192: bf16 transposes
__global__ void k_weights(const float* __restrict__ Wfc, const float* __restrict__ bfc,
                          const float* __restrict__ Wd1, const float* __restrict__ bd1,
                          const float* __restrict__ Wd2, const float* __restrict__ W2) {
    __shared__ float s[64];
    int b = blockIdx.x;
    int c = threadIdx.x;  // 256
    if (b < 128) {
        const float* wcol = (c < 128) ? &Wd1[c] : &Wd1[64 * 128 + (c - 128)];
        if (c < 64) s[c] = Wfc[b * 64 + c];
        __syncthreads();
        float acc = 0.f;
#pragma unroll 8
        for (int j = 0; j < 64; j++) acc = fmaf(s[j], wcol[j * 128], acc);
        g_wcombt[c * 128 + b] = __float2bfloat16(acc);
    } else if (b == 128) {
        const float* wcol = (c < 128) ? &Wd1[c] : &Wd1[64 * 128 + (c - 128)];
        if (c < 64) s[c] = bfc[c];
        __syncthreads();
        float acc = (c < 128) ? bd1[c] : 0.f;
#pragma unroll 8
        for (int j = 0; j < 64; j++) acc = fmaf(s[j], wcol[j * 128], acc);
        g_bcomb[c] = acc;
    } else {
        int idx = (b - 129) * 256 + c;
        if (idx < 128 * 128) {
            int n = idx >> 7, k = idx & 127;
            g_wl2t[idx] = __float2bfloat16(W2[k * 128 + n]);
        }
        if (idx < 64 * 128) {
            int n = idx >> 7, k = idx & 127;
            g_w2tb[idx] = __float2bfloat16(Wd2[k * 64 + n]);
        }
    }
}

// ---------------- fused layer 1: 7-dim agg + tiny GEMM -> h1s = h1'*dinv (bf16) ---------
__global__ __launch_bounds__(256) void k_l1(const float* __restrict__ W1,
                                            const float* __restrict__ b1,
                                            __nv_bfloat16* __restrict__ out) {
    __shared__ float sW[F_IN * HID];
    const int tid = threadIdx.x;
    for (int i = tid; i < F_IN * HID; i += 256) sW[i] = W1[i];
    __syncthreads();

    const int lane = tid & 31;
    const int gwarp = (blockIdx.x * 256 + tid) >> 5;
    const int sub = lane & 7, grp = lane >> 3;
    const int node = gwarp * 4 + grp;
    const uint4* xs = (const uint4*)g_xs8;

    float a0 = 0.f, a1 = 0.f, a2 = 0.f, a3 = 0.f, a4 = 0.f, a5 = 0.f, a6 = 0.f, a7 = 0.f;
#define ACC_ADD(vv) do { \
        float2 f0 = __bfloat1622float2(*(__nv_bfloat162*)&(vv).x); \
        float2 f1 = __bfloat1622float2(*(__nv_bfloat162*)&(vv).y); \
        float2 f2 = __bfloat1622float2(*(__nv_bfloat162*)&(vv).z); \
        float2 f3 = __bfloat1622float2(*(__nv_bfloat162*)&(vv).w); \
        a0 += f0.x; a1 += f0.y; a2 += f1.x; a3 += f1.y; \
        a4 += f2.x; a5 += f2.y; a6 += f3.x; a7 += f3.y; } while (0)
    if (node < N_NODES) {
        if (sub == 0) {
            uint4 v = xs[node];
            ACC_ADD(v);
        }
        const int end = g_off[node + 1];
        for (int e = g_off[node] + sub; e < end; e += 8) {
            uint4 v = xs[g_srcn[e]];
            ACC_ADD(v);
        }
    }
#undef ACC_ADD
#pragma unroll
    for (int off = 4; off > 0; off >>= 1) {
        a0 += __shfl_xor_sync(0xffffffffu, a0, off);
        a1 += __shfl_xor_sync(0xffffffffu, a1, off);
        a2 += __shfl_xor_sync(0xffffffffu, a2, off);
        a3 += __shfl_xor_sync(0xffffffffu, a3, off);
        a4 += __shfl_xor_sync(0xffffffffu, a4, off);
        a5 += __shfl_xor_sync(0xffffffffu, a5, off);
        a6 += __shfl_xor_sync(0xffffffffu, a6, off);
        a7 += __shfl_xor_sync(0xffffffffu, a7, off);
    }

    const int j = lane * 4;
    const float4 bb = *(const float4*)&b1[j];
#pragma unroll
    for (int w = 0; w < 4; w++) {
        int n2 = gwarp * 4 + w;
        if (n2 >= N_NODES) break;
        int src = w * 8;
        float xk0 = __shfl_sync(0xffffffffu, a0, src);
        float xk1 = __shfl_sync(0xffffffffu, a1, src);
        float xk2 = __shfl_sync(0xffffffffu, a2, src);
        float xk3 = __shfl_sync(0xffffffffu, a3, src);
        float xk4 = __shfl_sync(0xffffffffu, a4, src);
        float xk5 = __shfl_sync(0xffffffffu, a5, src);
        float xk6 = __shfl_sync(0xffffffffu, a6, src);
        const float* wp = &sW[j];
        float4 acc;
        acc.x = xk0 * wp[0]; acc.y = xk0 * wp[1]; acc.z = xk0 * wp[2]; acc.w = xk0 * wp[3];
        wp = &sW[1 * HID + j];
        acc.x = fmaf(xk1, wp[0], acc.x); acc.y = fmaf(xk1, wp[1], acc.y);
        acc.z = fmaf(xk1, wp[2], acc.z); acc.w = fmaf(xk1, wp[3], acc.w);
        wp = &sW[2 * HID + j];
        acc.x = fmaf(xk2, wp[0], acc.x); acc.y = fmaf(xk2, wp[1], acc.y);
        acc.z = fmaf(xk2, wp[2], acc.z); acc.w = fmaf(xk2, wp[3], acc.w);
        wp = &sW[3 * HID + j];
        acc.x = fmaf(xk3, wp[0], acc.x); acc.y = fmaf(xk3, wp[1], acc.y);
        acc.z = fmaf(xk3, wp[2], acc.z); acc.w = fmaf(xk3, wp[3], acc.w);
        wp = &sW[4 * HID + j];
        acc.x = fmaf(xk4, wp[0], acc.x); acc.y = fmaf(xk4, wp[1], acc.y);
        acc.z = fmaf(xk4, wp[2], acc.z); acc.w = fmaf(xk4, wp[3], acc.w);
        wp = &sW[5 * HID + j];
        acc.x = fmaf(xk5, wp[0], acc.x); acc.y = fmaf(xk5, wp[1], acc.y);
        acc.z = fmaf(xk5, wp[2], acc.z); acc.w = fmaf(xk5, wp[3], acc.w);
        wp = &sW[6 * HID + j];
        acc.x = fmaf(xk6, wp[0], acc.x); acc.y = fmaf(xk6, wp[1], acc.y);
        acc.z = fmaf(xk6, wp[2], acc.z); acc.w = fmaf(xk6, wp[3], acc.w);
        float dv = g_dinv[n2];
        // h1s = relu(dinv*acc + b1) * dinv
        float r0 = fmaxf(fmaf(acc.x, dv, bb.x), 0.f) * dv;
        float r1 = fmaxf(fmaf(acc.y, dv, bb.y), 0.f) * dv;
        float r2 = fmaxf(fmaf(acc.z, dv, bb.z), 0.f) * dv;
        float r3 = fmaxf(fmaf(acc.w, dv, bb.w), 0.f) * dv;
        __nv_bfloat162 p0 = __floats2bfloat162_rn(r0, r1);
        __nv_bfloat162 p1 = __floats2bfloat162_rn(r2, r3);
        uint2 o;
        o.x = *(uint32_t*)&p0;
        o.y = *(uint32_t*)&p1;
        *(uint2*)&out[(size_t)n2 * HID + j] = o;
    }
}

// ---------------- CSR aggregation (layer 2): m = bf16(dinv_d * (sum h1s + self)) --------
__global__ __launch_bounds__(256) void k_agg(const __nv_bfloat16* __restrict__ hs,
                                             __nv_bfloat16* __restrict__ out) {
    int t = blockIdx.x * blockDim.x + threadIdx.x;
    int node = t >> 5, lane = t & 31;
    if (node >= N_NODES) return;
    const int half = lane >> 4;
    const int cl = lane & 15;
    const uint4* h4 = (const uint4*)hs;

    float a0 = 0.f, a1 = 0.f, a2 = 0.f, a3 = 0.f, a4 = 0.f, a5 = 0.f, a6 = 0.f, a7 = 0.f;
#define ACC_ADD(vv) do { \
        float2 f0 = __bfloat1622float2(*(__nv_bfloat162*)&(vv).x); \
        float2 f1 = __bfloat1622float2(*(__nv_bfloat162*)&(vv).y); \
        float2 f2 = __bfloat1622float2(*(__nv_bfloat162*)&(vv).z); \
        float2 f3 = __bfloat1622float2(*(__nv_bfloat162*)&(vv).w); \
        a0 += f0.x; a1 += f0.y; a2 += f1.x; a3 += f1.y; \
        a4 += f2.x; a5 += f2.y; a6 += f3.x; a7 += f3.y; } while (0)

    if (half == 0) {
        uint4 v = h4[(size_t)node * 16 + cl];
        ACC_ADD(v);
    }
    int e = g_off[node] + half;
    const int end = g_off[node + 1];
    for (; e + 6 < end; e += 8) {
        int s0 = g_srcn[e], s1 = g_srcn[e + 2], s2 = g_srcn[e + 4], s3 = g_srcn[e + 6];
        uint4 v0 = h4[(size_t)s0 * 16 + cl];
        uint4 v1 = h4[(size_t)s1 * 16 + cl];
        uint4 v2 = h4[(size_t)s2 * 16 + cl];
        uint4 v3 = h4[(size_t)s3 * 16 + cl];
        ACC_ADD(v0); ACC_ADD(v1); ACC_ADD(v2); ACC_ADD(v3);
    }
    for (; e < end; e += 2) {
        uint4 v = h4[(size_t)g_srcn[e] * 16 + cl];
        ACC_ADD(v);
    }
#undef ACC_ADD
    a0 += __shfl_xor_sync(0xffffffffu, a0, 16);
    a1 += __shfl_xor_sync(0xffffffffu, a1, 16);
    a2 += __shfl_xor_sync(0xffffffffu, a2, 16);
    a3 += __shfl_xor_sync(0xffffffffu, a3, 16);
    a4 += __shfl_xor_sync(0xffffffffu, a4, 16);
    a5 += __shfl_xor_sync(0xffffffffu, a5, 16);
    a6 += __shfl_xor_sync(0xffffffffu, a6, 16);
    a7 += __shfl_xor_sync(0xffffffffu, a7, 16);

    if (half == 0) {
        float dv = g_dinv[node];
        __nv_bfloat162 p0 = __floats2bfloat162_rn(a0 * dv, a1 * dv);
        __nv_bfloat162 p1 = __floats2bfloat162_rn(a2 * dv, a3 * dv);
        __nv_bfloat162 p2 = __floats2bfloat162_rn(a4 * dv, a5 * dv);
        __nv_bfloat162 p3 = __floats2bfloat162_rn(a6 * dv, a7 * dv);
        uint4 o;
        o.x = *(uint32_t*)&p0; o.y = *(uint32_t*)&p1;
        o.z = *(uint32_t*)&p2; o.w = *(uint32_t*)&p3;
        ((uint4*)out)[(size_t)node * 16 + cl] = o;
    }
}

// ---------------- fused double GEMM: h2' = relu(m@W2+b2); UV = h2'@Wcomb+bcomb ----------
// smem: s_a[128][136] | s_b[128][136] | s_h[128][136]  (bf16) = 104448 B
__global__ __launch_bounds__(256) void k_gemm2(const __nv_bfloat16* __restrict__ M,
                                               const __nv_bfloat16* __restrict__ W2t,
                                               const float* __restrict__ b2,
                                               const __nv_bfloat16* __restrict__ WCt,
                                               const float* __restrict__ bcomb,
                                               __nv_bfloat16* __restrict__ UV) {
    constexpr int KD = 128;
    constexpr int KP = KD + 8;
    extern __shared__ char smraw[];
    __nv_bfloat16* s_a = (__nv_bfloat16*)smraw;                       // m tile
    __nv_bfloat16* s_b = (__nv_bfloat16*)(smraw + 128 * KP * 2);      // weight chunk
    __nv_bfloat16* s_h = (__nv_bfloat16*)(smraw + 2 * 128 * KP * 2);  // h2' tile
    const int tid = threadIdx.x;
    const int row0 = blockIdx.x * 128;

    for (int i = tid; i < 128 * (KD / 4); i += 256) {
        int r = i >> 5, k4 = i & 31;
        int gr = row0 + r;
        if (gr >= N_NODES) gr = N_NODES - 1;
        *(uint2*)&s_a[r * KP + k4 * 4] = *(const uint2*)&M[(size_t)gr * KD + k4 * 4];
    }
    for (int i = tid; i < 128 * (KD / 4); i += 256) {
        int n = i >> 5, k4 = i & 31;
        *(uint2*)&s_b[n * KP + k4 * 4] = ((const uint2*)W2t)[i];
    }
    __syncthreads();

    const int lane = tid & 31, warp = tid >> 5;
    const int q0 = warp * 16;
    const int gid = lane >> 2, tig = lane & 3;
    const int qa = row0 + q0 + gid, qb = qa + 8;

    // stage 1: h2' = relu(m@W2 + b2)
    {
        float acc[16][4];
#pragma unroll
        for (int t = 0; t < 16; t++)
#pragma unroll
            for (int j = 0; j < 4; j++) acc[t][j] = 0.f;
#pragma unroll
        for (int k0 = 0; k0 < KD; k0 += 16) {
            uint32_t a0 = *(const uint32_t*)&s_a[(q0 + gid) * KP + k0 + 2 * tig];
            uint32_t a1 = *(const uint32_t*)&s_a[(q0 + gid + 8) * KP + k0 + 2 * tig];
            uint32_t a2 = *(const uint32_t*)&s_a[(q0 + gid) * KP + k0 + 2 * tig + 8];
            uint32_t a3 = *(const uint32_t*)&s_a[(q0 + gid + 8) * KP + k0 + 2 * tig + 8];
#pragma unroll
            for (int t = 0; t < 16; t++) {
                int n = t * 8 + gid;
                uint32_t b0 = *(const uint32_t*)&s_b[n * KP + k0 + 2 * tig];
                uint32_t b1 = *(const uint32_t*)&s_b[n * KP + k0 + 2 * tig + 8];
                asm volatile(
                    "mma.sync.aligned.m16n8k16.row.col.f32.bf16.bf16.f32 "
                    "{%0,%1,%2,%3}, {%4,%5,%6,%7}, {%8,%9}, {%0,%1,%2,%3};"
                    : "+f"(acc[t][0]), "+f"(acc[t][1]), "+f"(acc[t][2]), "+f"(acc[t][3])
                    : "r"(a0), "r"(a1), "r"(a2), "r"(a3), "r"(b0), "r"(b1));
            }
        }
#pragma unroll
        for (int t = 0; t < 16; t++) {
            int c = t * 8 + 2 * tig;
            float bb0 = b2[c], bb1 = b2[c + 1];
            __nv_bfloat162 pa = __floats2bfloat162_rn(fmaxf(acc[t][0] + bb0, 0.f),
                                                      fmaxf(acc[t][1] + bb1, 0.f));
            __nv_bfloat162 pb = __floats2bfloat162_rn(fmaxf(acc[t][2] + bb0, 0.f),
                                                      fmaxf(acc[t][3] + bb1, 0.f));
            *(__nv_bfloat162*)&s_h[(q0 + gid) * KP + c]     = pa;
            *(__nv_bfloat162*)&s_h[(q0 + gid + 8) * KP + c] = pb;
        }
    }
    __syncthreads();

    // stage 2: UV = h2' @ Wcomb + bcomb, 2 chunks of 128 cols
#pragma unroll
    for (int nc = 0; nc < 2; nc++) {
        for (int i = tid; i < 128 * (KD / 4); i += 256) {
            int n = i >> 5, k4 = i & 31;
            *(uint2*)&s_b[n * KP + k4 * 4] =
                *(const uint2*)&WCt[((size_t)(nc * 128 + n)) * KD + k4 * 4];
        }
        __syncthreads();

        float acc[16][4];
#pragma unroll
        for (int t = 0; t < 16; t++)
#pragma unroll
            for (int j = 0; j < 4; j++) acc[t][j] = 0.f;
#pragma unroll
        for (int k0 = 0; k0 < KD; k0 += 16) {
            uint32_t a0 = *(const uint32_t*)&s_h[(q0 + gid) * KP + k0 + 2 * tig];
            uint32_t a1 = *(const uint32_t*)&s_h[(q0 + gid + 8) * KP + k0 + 2 * tig];
            uint32_t a2 = *(const uint32_t*)&s_h[(q0 + gid) * KP + k0 + 2 * tig + 8];
            uint32_t a3 = *(const uint32_t*)&s_h[(q0 + gid + 8) * KP + k0 + 2 * tig + 8];
#pragma unroll
            for (int t = 0; t < 16; t++) {
                int n = t * 8 + gid;
                uint32_t b0 = *(const uint32_t*)&s_b[n * KP + k0 + 2 * tig];
                uint32_t b1 = *(const uint32_t*)&s_b[n * KP + k0 + 2 * tig + 8];
                asm volatile(
                    "mma.sync.aligned.m16n8k16.row.col.f32.bf16.bf16.f32 "
                    "{%0,%1,%2,%3}, {%4,%5,%6,%7}, {%8,%9}, {%0,%1,%2,%3};"
                    : "+f"(acc[t][0]), "+f"(acc[t][1]), "+f"(acc[t][2]), "+f"(acc[t][3])
                    : "r"(a0), "r"(a1), "r"(a2), "r"(a3), "r"(b0), "r"(b1));
            }
        }
#pragma unroll
        for (int t = 0; t < 16; t++) {
            int c = nc * 128 + t * 8 + 2 * tig;
            float bb0 = bcomb[c], bb1 = bcomb[c + 1];
            __nv_bfloat162 pa = __floats2bfloat162_rn(acc[t][0] + bb0, acc[t][1] + bb1);
            __nv_bfloat162 pb = __floats2bfloat162_rn(acc[t][2] + bb0, acc[t][3] + bb1);
            if (qa < N_NODES) *(__nv_bfloat162*)&UV[(size_t)qa * 256 + c] = pa;
            if (qb < N_NODES) *(__nv_bfloat162*)&UV[(size_t)qb * 256 + c] = pb;
        }
        if (nc == 0) __syncthreads();
    }
}

// ---------------- decoder: 128 q/block; uint4 gather; bf16 mma; fused stage 3 -----------
__global__ __launch_bounds__(256) void k_decoder(
    const __nv_bfloat16* __restrict__ uv, const int* __restrict__ qe,
    const __nv_bfloat16* __restrict__ w2t, const float* __restrict__ bd2,
    const float* __restrict__ Wd3, const float* __restrict__ bd3,
    float* __restrict__ out) {
    extern __shared__ char smraw[];
    __nv_bfloat16* s_d = (__nv_bfloat16*)smraw;              // [128][136]
    __nv_bfloat16* s_w = (__nv_bfloat16*)(smraw + 34816);    // [64][136]
    __shared__ int s_a[128], s_b[128];
    __shared__ float s_b2[EMB], s_w3[EMB];

    const int tid = threadIdx.x;
    const int q0blk = blockIdx.x * 128;

    for (int i = tid; i < 64 * 32; i += 256) {
        int n = i >> 5, k4 = i & 31;
        *(uint2*)&s_w[n * 136 + k4 * 4] = ((const uint2*)w2t)[i];
    }
    if (tid < EMB) { s_b2[tid] = bd2[tid]; s_w3[tid] = Wd3[tid]; }
    if (tid < 128) {
        int qi = q0blk + tid;
        s_a[tid] = qi < N_QUERY ? qe[qi] : 0;
        s_b[tid] = qi < N_QUERY ? qe[N_QUERY + qi] : 0;
    }
    __syncthreads();

    // stage 1: uint4 gather (16B per lane-load)
    const uint4* uv4 = (const uint4*)uv;   // 32 uint4 per 256-entry row
    for (int i = tid; i < 128 * 16; i += 256) {
        int q = i >> 4, c = i & 15;
        uint4 uu = uv4[(size_t)s_a[q] * 32 + c];
        uint4 vv = uv4[(size_t)s_b[q] * 32 + 16 + c];
        float2 u0 = __bfloat1622float2(*(__nv_bfloat162*)&uu.x);
        float2 u1 = __bfloat1622float2(*(__nv_bfloat162*)&uu.y);
        float2 u2 = __bfloat1622float2(*(__nv_bfloat162*)&uu.z);
        float2 u3 = __bfloat1622float2(*(__nv_bfloat162*)&uu.w);
        float2 v0 = __bfloat1622float2(*(__nv_bfloat162*)&vv.x);
        float2 v1 = __bfloat1622float2(*(__nv_bfloat162*)&vv.y);
        float2 v2 = __bfloat1622float2(*(__nv_bfloat162*)&vv.z);
        float2 v3 = __bfloat1622float2(*(__nv_bfloat162*)&vv.w);
        __nv_bfloat162 p0 = __floats2bfloat162_rn(fmaxf(u0.x + v0.x, 0.f), fmaxf(u0.y + v0.y, 0.f));
        __nv_bfloat162 p1 = __floats2bfloat162_rn(fmaxf(u1.x + v1.x, 0.f), fmaxf(u1.y + v1.y, 0.f));
        __nv_bfloat162 p2 = __floats2bfloat162_rn(fmaxf(u2.x + v2.x, 0.f), fmaxf(u2.y + v2.y, 0.f));
        __nv_bfloat162 p3 = __floats2bfloat162_rn(fmaxf(u3.x + v3.x, 0.f), fmaxf(u3.y + v3.y, 0.f));
        uint4 o;
        o.x = *(uint32_t*)&p0; o.y = *(uint32_t*)&p1;
        o.z = *(uint32_t*)&p2; o.w = *(uint32_t*)&p3;
        *(uint4*)&s_d[q * 136 + c * 8] = o;
    }
    __syncthreads();

    {
        const int lane = tid & 31, warp = tid >> 5;
        const int q0 = warp * 16;
        const int gid = lane >> 2, tig = lane & 3;
        float acc[8][4];
#pragma unroll
        for (int t = 0; t < 8; t++)
#pragma unroll
            for (int j = 0; j < 4; j++) acc[t][j] = 0.f;

#pragma unroll
        for (int k0 = 0; k0 < 128; k0 += 16) {
            uint32_t a0 = *(const uint32_t*)&s_d[(q0 + gid) * 136 + k0 + 2 * tig];
            uint32_t a1 = *(const uint32_t*)&s_d[(q0 + gid + 8) * 136 + k0 + 2 * tig];
            uint32_t a2 = *(const uint32_t*)&s_d[(q0 + gid) * 136 + k0 + 2 * tig + 8];
            uint32_t a3 = *(const uint32_t*)&s_d[(q0 + gid + 8) * 136 + k0 + 2 * tig + 8];
#pragma unroll
            for (int t = 0; t < 8; t++) {
                int n = t * 8 + gid;
                uint32_t b0 = *(const uint32_t*)&s_w[n * 136 + k0 + 2 * tig];
                uint32_t b1 = *(const uint32_t*)&s_w[n * 136 + k0 + 2 * tig + 8];
                asm volatile(
                    "mma.sync.aligned.m16n8k16.row.col.f32.bf16.bf16.f32 "
                    "{%0,%1,%2,%3}, {%4,%5,%6,%7}, {%8,%9}, {%0,%1,%2,%3};"
                    : "+f"(acc[t][0]), "+f"(acc[t][1]), "+f"(acc[t][2]), "+f"(acc[t][3])
                    : "r"(a0), "r"(a1), "r"(a2), "r"(a3), "r"(b0), "r"(b1));
            }
        }
        float pa = 0.f, pb = 0.f;
#pragma unroll
        for (int t = 0; t < 8; t++) {
            int c = t * 8 + 2 * tig;
            float bb0 = s_b2[c], bb1 = s_b2[c + 1];
            float w0 = s_w3[c], w1 = s_w3[c + 1];
            pa = fmaf(fmaxf(acc[t][0] + bb0, 0.f), w0, pa);
            pa = fmaf(fmaxf(acc[t][1] + bb1, 0.f), w1, pa);
            pb = fmaf(fmaxf(acc[t][2] + bb0, 0.f), w0, pb);
            pb = fmaf(fmaxf(acc[t][3] + bb1, 0.f), w1, pb);
        }
        pa += __shfl_xor_sync(0xffffffffu, pa, 1);
        pa += __shfl_xor_sync(0xffffffffu, pa, 2);
        pb += __shfl_xor_sync(0xffffffffu, pb, 1);
        pb += __shfl_xor_sync(0xffffffffu, pb, 2);
        if (tig == 0) {
            float b3 = bd3[0];
            int qi_a = q0blk + q0 + gid;
            int qi_b = qi_a + 8;
            if (qi_a < N_QUERY) out[qi_a] = 1.0f / (1.0f + expf(-(pa + b3)));
            if (qi_b < N_QUERY) out[qi_b] = 1.0f / (1.0f + expf(-(pb + b3)));
        }
    }
}

// ---------------- launch ----------------
extern "C" void kernel_launch(void* const* d_in, const int* in_sizes, int n_in,
                              void* d_out, int out_size) {
    const float* x   = (const float*)d_in[0];
    const int* ei    = (const int*)d_in[1];
    const int* qe    = (const int*)d_in[2];
    const float* W1  = (const float*)d_in[3];
    const float* b1  = (const float*)d_in[4];
    const float* W2  = (const float*)d_in[5];
    const float* b2  = (const float*)d_in[6];
    const float* Wfc = (const float*)d_in[7];
    const float* bfc = (const float*)d_in[8];
    const float* Wd1 = (const float*)d_in[9];
    const float* bd1 = (const float*)d_in[10];
    const float* Wd2 = (const float*)d_in[11];
    const float* bd2 = (const float*)d_in[12];
    const float* Wd3 = (const float*)d_in[13];
    const float* bd3 = (const float*)d_in[14];
    float* out = (float*)d_out;

    float* pBC2;
    __nv_bfloat16 *pH1S, *pM, *pUV, *pW2TB, *pWL2T, *pWCT;
    int* pCnt;
    { void* p; cudaGetSymbolAddress(&p, g_h1s);    pH1S = (__nv_bfloat16*)p; }
    { void* p; cudaGetSymbolAddress(&p, g_m);      pM = (__nv_bfloat16*)p; }
    { void* p; cudaGetSymbolAddress(&p, g_uvb);    pUV = (__nv_bfloat16*)p; }
    { void* p; cudaGetSymbolAddress(&p, g_w2tb);   pW2TB = (__nv_bfloat16*)p; }
    { void* p; cudaGetSymbolAddress(&p, g_wl2t);   pWL2T = (__nv_bfloat16*)p; }
    { void* p; cudaGetSymbolAddress(&p, g_wcombt); pWCT = (__nv_bfloat16*)p; }
    { void* p; cudaGetSymbolAddress(&p, g_bcomb);  pBC2 = (float*)p; }
    { void* p; cudaGetSymbolAddress(&p, g_cnt);    pCnt = (int*)p; }

    const int SM_G2  = 3 * 128 * 136 * 2;  // 104448
    const int SM_DEC = 34816 + 17408;      // 52224
    cudaFuncSetAttribute(k_gemm2, cudaFuncAttributeMaxDynamicSharedMemorySize, SM_G2);
    cudaFuncSetAttribute(k_decoder, cudaFuncAttributeMaxDynamicSharedMemorySize, SM_DEC);

    const int NBLK = (N_NODES + 127) / 128;

    // CSR build + weight prep
    cudaMemsetAsync(pCnt, 0, N_NODES * sizeof(int));
    k_cnt<<<(N_EDGES / 4 + 255) / 256, 256>>>(ei);
    k_scanA<<<NSCAN_BLK, 256>>>();
    k_scanB<<<1, 512>>>();
    k_scanC<<<NSCAN_BLK, 256>>>(x);
    k_fill<<<(N_EDGES + 255) / 256, 256>>>(ei);
    k_weights<<<193, 256>>>(Wfc, bfc, Wd1, bd1, Wd2, W2);

    // layer 1 fused -> h1s (bf16, message form)
    k_l1<<<(N_NODES / 32), 256>>>(W1, b1, pH1S);

    // layer-2 aggregation (commuted before W2): m = dinv_d * (sum h1s + self)
    k_agg<<<(N_NODES * 32 + 255) / 256, 256>>>(pH1S, pM);

    // fused double GEMM: h2' = relu(m@W2+b2); UV = h2'@Wcomb+bcomb
    k_gemm2<<<NBLK, 256, SM_G2>>>(pM, pWL2T, b2, pWCT, pBC2, pUV);

    // decoder
    k_decoder<<<(N_QUERY + 127) / 128, 256, SM_DEC>>>(pUV, qe, pW2TB, bd2, Wd3, bd3, out);
}